// round 1
// baseline (speedup 1.0000x reference)
#include <cuda_runtime.h>
#include <math.h>

// ---------------- shapes ----------------
#define BB 2
#define CC 128
#define LL 32
#define HH 32
#define WW 32
#define WF 17          // W/2+1
#define BNN 64         // B*L
#define NP 1024        // H*W
#define NPC 256        // pooled pixels (16*16)
#define MH 12
#define MW 12

#define TWO_PI_32 0.19634954084936207f   // 2*pi/32
#define INV32 0.03125f
#define INV_SQRT32 0.17677669529663687f

// ---------------- device scratch (no runtime allocation allowed) ----------------
__device__ float2 g_xf[BB*CC*LL*HH*WF];      // rfft + scan states (in-place)
__device__ float2 g_A [BB*LL*CC*WF];
__device__ float  g_xt [BNN*NP*CC];          // channels-last residual stream
__device__ float  g_xn [BNN*NP*CC];
__device__ float  g_qkv[BNN*NP*384];
__device__ float  g_ao [BNN*NP*CC];
__device__ float  g_y2n[BNN*NP*CC];
__device__ float  g_gp [BNN*NPC*CC];
__device__ float  g_gg [BNN*NPC*CC];
__device__ float  g_l  [BNN*NP*CC];
__device__ float  g_gate[BNN*NP];
__device__ float  g_y3 [BNN*CC*NP];          // channels-first for spectral part
__device__ float2 g_Xw [BNN*CC*HH*MW];
__device__ float  g_zin [BNN*144*256];
__device__ float  g_zout[BNN*144*256];
__device__ float2 g_tH [BNN*CC*HH*MW];
__device__ float2 g_st1[BNN*4];
__device__ float2 g_st2[BNN*4];

// ---------------- stage 1: A precompute ----------------
__global__ void k_precompA(const float* __restrict__ dt, const float* __restrict__ nu,
                           const float* __restrict__ th) {
    int i = blockIdx.x * blockDim.x + threadIdx.x;
    if (i >= BB*LL*CC*WF) return;
    int k = i % WF;
    int c = (i / WF) % CC;
    int l = (i / (WF*CC)) % LL;
    int b =  i / (WF*CC*LL);
    float d  = dt[b*LL + l];
    float e  = expf(-nu[c*WF + k] * d);
    float si, co;
    sincosf(th[c*WF + k] * d, &si, &co);
    g_A[i] = make_float2(e*co, e*si);
}

// ---------------- stage 1: rfft along W (direct DFT, W=32) ----------------
__global__ void k_rfft(const float* __restrict__ x) {
    __shared__ float tc[32], ts[32];
    if (threadIdx.x < 32) {
        float a = TWO_PI_32 * (float)threadIdx.x;
        tc[threadIdx.x] = cosf(a);
        ts[threadIdx.x] = sinf(a);
    }
    __syncthreads();
    int row = blockIdx.x * blockDim.x + threadIdx.x;   // (b,c,l,h)
    if (row >= BB*CC*LL*HH) return;
    const float* xp = x + (size_t)row * WW;
    float xr[WW];
#pragma unroll
    for (int w = 0; w < WW; w++) xr[w] = xp[w];
    float2* out = g_xf + (size_t)row * WF;
    for (int k = 0; k < WF; k++) {
        float re = 0.f, im = 0.f;
#pragma unroll
        for (int w = 0; w < WW; w++) {
            int t = (w*k) & 31;
            re += xr[w]*tc[t];
            im -= xr[w]*ts[t];
        }
        out[k] = make_float2(re, im);
    }
}

// ---------------- stage 1: complex scan over L (in-place) ----------------
__global__ void k_scan() {
    int i = blockIdx.x * blockDim.x + threadIdx.x;     // (b,c,h,k)
    if (i >= BB*CC*HH*WF) return;
    int k = i % WF;
    int h = (i / WF) % HH;
    int c = (i / (WF*HH)) % CC;
    int b =  i / (WF*HH*CC);
    size_t xfb = ((((size_t)b*CC + c)*LL)*HH + h)*WF + k;
    const size_t xstr = (size_t)HH*WF;
    size_t ab = ((size_t)b*LL*CC + c)*WF + k;
    const size_t astr = (size_t)CC*WF;
    float2 s = make_float2(0.f, 0.f);
    for (int l = 0; l < LL; l++) {
        float2 a = g_A[ab + (size_t)l*astr];
        float2 u = g_xf[xfb + (size_t)l*xstr];
        float re = a.x*s.x - a.y*s.y + u.x;
        float im = a.x*s.y + a.y*s.x + u.y;
        s = make_float2(re, im);
        g_xf[xfb + (size_t)l*xstr] = s;
    }
}

// ---------------- stage 1: irfft -> xt channels-last (BN,N,C) ----------------
__global__ void k_irfft() {
    __shared__ float tc[32], ts[32];
    if (threadIdx.x < 32) {
        float a = TWO_PI_32 * (float)threadIdx.x;
        tc[threadIdx.x] = cosf(a);
        ts[threadIdx.x] = sinf(a);
    }
    __syncthreads();
    int i = blockIdx.x * blockDim.x + threadIdx.x;     // (b,l,h,c) c fastest
    if (i >= BB*LL*HH*CC) return;
    int c = i & 127;
    int h = (i >> 7) & 31;
    int l = (i >> 12) & 31;
    int b =  i >> 17;
    const float2* st = g_xf + ((((size_t)b*CC + c)*LL + l)*HH + h)*WF;
    float2 S[WF];
#pragma unroll
    for (int k = 0; k < WF; k++) S[k] = st[k];
    int bn = b*LL + l;
    float* out = g_xt + ((size_t)bn*NP + h*WW)*CC + c;
    for (int w = 0; w < WW; w++) {
        float v = S[0].x + ((w & 1) ? -S[16].x : S[16].x);
#pragma unroll
        for (int k = 1; k < 16; k++) {
            int t = (w*k) & 31;
            v += 2.f*(S[k].x*tc[t] - S[k].y*ts[t]);
        }
        out[(size_t)w*CC] = v * INV32;
    }
}

// ---------------- LayerNorm over C (warp per row) ----------------
__global__ void k_ln(const float* __restrict__ g, const float* __restrict__ b) {
    int lane = threadIdx.x & 31, wid = threadIdx.x >> 5;
    int r = blockIdx.x*8 + wid;
    float4 v = ((const float4*)(g_xt + (size_t)r*CC))[lane];
    float s = v.x + v.y + v.z + v.w;
#pragma unroll
    for (int o = 16; o; o >>= 1) s += __shfl_xor_sync(0xffffffffu, s, o);
    float mu = s * (1.f/128.f);
    float dx = v.x-mu, dy = v.y-mu, dz = v.z-mu, dw = v.w-mu;
    float q = dx*dx + dy*dy + dz*dz + dw*dw;
#pragma unroll
    for (int o = 16; o; o >>= 1) q += __shfl_xor_sync(0xffffffffu, q, o);
    float rstd = rsqrtf(q*(1.f/128.f) + 1e-5f);
    float4 g4 = ((const float4*)g)[lane];
    float4 b4 = ((const float4*)b)[lane];
    float4 o4;
    o4.x = dx*rstd*g4.x + b4.x;
    o4.y = dy*rstd*g4.y + b4.y;
    o4.z = dz*rstd*g4.z + b4.z;
    o4.w = dw*rstd*g4.w + b4.w;
    ((float4*)(g_xn + (size_t)r*CC))[lane] = o4;
}

// ---------------- generic GEMM: C[M,N] (=/+=) A[M,K] * B[N,K]^T (+bias) ----------------
// M,N multiples of 64; K multiple of 16. 256 threads; 64x64 tile, 4x4 per thread.
__global__ void k_gemm(const float* __restrict__ A, const float* __restrict__ B,
                       const float* __restrict__ bias, float* __restrict__ C,
                       int M, int N, int K, int accum) {
    __shared__ float As[16][72];
    __shared__ float Bs[16][72];
    int bm = blockIdx.y << 6, bn = blockIdx.x << 6;
    int tid = threadIdx.x;
    int tx = tid & 15, ty = tid >> 4;
    int lm = tid >> 2, lk = (tid & 3) << 2;
    float acc[4][4];
#pragma unroll
    for (int i = 0; i < 4; i++)
#pragma unroll
        for (int j = 0; j < 4; j++) acc[i][j] = 0.f;

    for (int k0 = 0; k0 < K; k0 += 16) {
        float4 a4 = *(const float4*)(A + (size_t)(bm+lm)*K + k0 + lk);
        float4 b4 = *(const float4*)(B + (size_t)(bn+lm)*K + k0 + lk);
        As[lk+0][lm] = a4.x; As[lk+1][lm] = a4.y; As[lk+2][lm] = a4.z; As[lk+3][lm] = a4.w;
        Bs[lk+0][lm] = b4.x; Bs[lk+1][lm] = b4.y; Bs[lk+2][lm] = b4.z; Bs[lk+3][lm] = b4.w;
        __syncthreads();
#pragma unroll
        for (int k = 0; k < 16; k++) {
            float4 av = *(const float4*)&As[k][ty << 2];
            float4 bv = *(const float4*)&Bs[k][tx << 2];
            acc[0][0] += av.x*bv.x; acc[0][1] += av.x*bv.y; acc[0][2] += av.x*bv.z; acc[0][3] += av.x*bv.w;
            acc[1][0] += av.y*bv.x; acc[1][1] += av.y*bv.y; acc[1][2] += av.y*bv.z; acc[1][3] += av.y*bv.w;
            acc[2][0] += av.z*bv.x; acc[2][1] += av.z*bv.y; acc[2][2] += av.z*bv.z; acc[2][3] += av.z*bv.w;
            acc[3][0] += av.w*bv.x; acc[3][1] += av.w*bv.y; acc[3][2] += av.w*bv.z; acc[3][3] += av.w*bv.w;
        }
        __syncthreads();
    }
#pragma unroll
    for (int i = 0; i < 4; i++) {
        int row = bm + (ty << 2) + i;
#pragma unroll
        for (int j = 0; j < 4; j++) {
            int col = bn + (tx << 2) + j;
            float v = acc[i][j];
            if (bias) v += bias[col];
            size_t ci = (size_t)row*N + col;
            if (accum) v += C[ci];
            C[ci] = v;
        }
    }
}

// ---------------- attention: online softmax, thread-per-query ----------------
__global__ void k_attn() {
    __shared__ float Ks[128][16];
    __shared__ float Vs[128][16];
    int blk = blockIdx.x;                  // 64*8*4
    int qt = blk & 3, head = (blk >> 2) & 7, bn = blk >> 5;
    int q = qt*256 + threadIdx.x;
    const float* qp = g_qkv + ((size_t)(bn*NP + q))*384 + head*16;
    float qv[16];
#pragma unroll
    for (int d4 = 0; d4 < 4; d4++) {
        float4 t = *(const float4*)(qp + d4*4);
        qv[d4*4+0] = t.x; qv[d4*4+1] = t.y; qv[d4*4+2] = t.z; qv[d4*4+3] = t.w;
    }
    float m = -1e30f, l = 0.f;
    float acc[16];
#pragma unroll
    for (int d = 0; d < 16; d++) acc[d] = 0.f;

    for (int c0 = 0; c0 < NP; c0 += 128) {
        __syncthreads();
#pragma unroll
        for (int i = 0; i < 2; i++) {
            int f = threadIdx.x*2 + i;           // 512 float4 slots
            int key = f >> 2, d4 = (f & 3) << 2;
            size_t base = ((size_t)(bn*NP + c0 + key))*384 + head*16 + d4;
            float4 kv = *(const float4*)(g_qkv + base + 128);
            float4 vv = *(const float4*)(g_qkv + base + 256);
            Ks[key][d4+0] = kv.x; Ks[key][d4+1] = kv.y; Ks[key][d4+2] = kv.z; Ks[key][d4+3] = kv.w;
            Vs[key][d4+0] = vv.x; Vs[key][d4+1] = vv.y; Vs[key][d4+2] = vv.z; Vs[key][d4+3] = vv.w;
        }
        __syncthreads();
        for (int kk = 0; kk < 128; kk++) {
            float s = 0.f;
#pragma unroll
            for (int d = 0; d < 16; d++) s += qv[d]*Ks[kk][d];
            s *= 0.25f;                          // hd^-0.5
            float nm = fmaxf(m, s);
            float p  = __expf(s - nm);
            float sc = __expf(m - nm);
            l = l*sc + p;
#pragma unroll
            for (int d = 0; d < 16; d++) acc[d] = acc[d]*sc + p*Vs[kk][d];
            m = nm;
        }
    }
    float inv = 1.f / l;
    float* op = g_ao + ((size_t)(bn*NP + q))*CC + head*16;
#pragma unroll
    for (int d4 = 0; d4 < 4; d4++) {
        float4 t;
        t.x = acc[d4*4+0]*inv; t.y = acc[d4*4+1]*inv;
        t.z = acc[d4*4+2]*inv; t.w = acc[d4*4+3]*inv;
        *(float4*)(op + d4*4) = t;
    }
}

// ---------------- GroupNorm stats (optionally gated input) ----------------
__global__ void k_gnstats(const float* __restrict__ X, const float* __restrict__ gate,
                          float2* __restrict__ stats) {
    __shared__ float sh[256], sh2[256];
    int bn = blockIdx.x >> 2, g = blockIdx.x & 3;
    float s = 0.f, q = 0.f;
    const float* base = X + (size_t)bn*NP*CC + g*32;
    for (int e = threadIdx.x; e < 32768; e += 256) {
        int n = e >> 5, cc = e & 31;
        float v = base[(size_t)n*CC + cc];
        if (gate) v *= gate[bn*NP + n];
        s += v; q += v*v;
    }
    sh[threadIdx.x] = s; sh2[threadIdx.x] = q;
    __syncthreads();
    for (int o = 128; o; o >>= 1) {
        if (threadIdx.x < o) { sh[threadIdx.x] += sh[threadIdx.x+o]; sh2[threadIdx.x] += sh2[threadIdx.x+o]; }
        __syncthreads();
    }
    if (threadIdx.x == 0) {
        float mu = sh[0] * (1.f/32768.f);
        float var = sh2[0] * (1.f/32768.f) - mu*mu;
        stats[blockIdx.x] = make_float2(mu, rsqrtf(var + 1e-5f));
    }
}

__global__ void k_gnapply(const float* __restrict__ g, const float* __restrict__ b) {
    int i = blockIdx.x * blockDim.x + threadIdx.x;
    if (i >= BNN*NP*CC) return;
    int c = i & 127;
    int bn = i >> 17;
    float2 st = g_st1[bn*4 + (c >> 5)];
    g_y2n[i] = (g_xt[i] - st.x)*st.y*g[c] + b[c];
}

__global__ void k_pool() {
    int i = blockIdx.x * blockDim.x + threadIdx.x;     // (bn,pc,c)
    if (i >= BNN*NPC*CC) return;
    int c = i & 127;
    int pc = (i >> 7) & 255;
    int bn = i >> 15;
    int hp = pc >> 4, wp = pc & 15;
    size_t base = ((size_t)bn*NP + hp*64 + wp*2)*CC + c;
    g_gp[i] = 0.25f*(g_y2n[base] + g_y2n[base + CC] + g_y2n[base + 32*CC] + g_y2n[base + 33*CC]);
}

__global__ void k_gate(const float* __restrict__ w_psi, const float* __restrict__ b_psi) {
    int lane = threadIdx.x & 31, wid = threadIdx.x >> 5;
    int p = blockIdx.x*8 + wid;                        // 65536 pixels
    int bn = p >> 10, n = p & 1023;
    int h = n >> 5, w = n & 31;
    int pc = (h >> 1)*16 + (w >> 1);
    float4 gv = ((const float4*)(g_gg + ((size_t)bn*NPC + pc)*CC))[lane];
    float4 lv = ((const float4*)(g_l  + (size_t)p*CC))[lane];
    float4 wp = ((const float4*)w_psi)[lane];
    float s = fmaxf(gv.x+lv.x, 0.f)*wp.x + fmaxf(gv.y+lv.y, 0.f)*wp.y
            + fmaxf(gv.z+lv.z, 0.f)*wp.z + fmaxf(gv.w+lv.w, 0.f)*wp.w;
#pragma unroll
    for (int o = 16; o; o >>= 1) s += __shfl_xor_sync(0xffffffffu, s, o);
    if (lane == 0) g_gate[p] = 1.f/(1.f + expf(-(s + b_psi[0])));
}

// apply 2nd groupnorm on gated values, write channels-first y3
__global__ void k_y3(const float* __restrict__ g, const float* __restrict__ b) {
    int i = blockIdx.x * blockDim.x + threadIdx.x;     // (bn,c,n), n fastest
    if (i >= BNN*CC*NP) return;
    int n = i & 1023;
    int c = (i >> 10) & 127;
    int bn = i >> 17;
    float v = g_y2n[((size_t)bn*NP + n)*CC + c] * g_gate[bn*NP + n];
    float2 st = g_st2[bn*4 + (c >> 5)];
    g_y3[i] = (v - st.x)*st.y*g[c] + b[c];
}

// ---------------- spectral: partial rfft along W (modes 0..11) ----------------
__global__ void k_sa() {
    __shared__ float tc[32], ts[32];
    if (threadIdx.x < 32) {
        float a = TWO_PI_32 * (float)threadIdx.x;
        tc[threadIdx.x] = cosf(a);
        ts[threadIdx.x] = sinf(a);
    }
    __syncthreads();
    int row = blockIdx.x * blockDim.x + threadIdx.x;   // (bn,c,h)
    if (row >= BNN*CC*HH) return;
    const float* yp = g_y3 + (size_t)row * WW;
    float xr[WW];
#pragma unroll
    for (int w = 0; w < WW; w++) xr[w] = yp[w];
    float2* out = g_Xw + (size_t)row * MW;
    for (int kw = 0; kw < MW; kw++) {
        float re = 0.f, im = 0.f;
#pragma unroll
        for (int w = 0; w < WW; w++) {
            int t = (w*kw) & 31;
            re += xr[w]*tc[t];
            im -= xr[w]*ts[t];
        }
        out[kw] = make_float2(re, im);
    }
}

// partial DFT along H (modes 0..11), write z rows (re|im) for mix GEMM, with ortho 1/32
__global__ void k_sb() {
    __shared__ float2 Xs[HH*MW];
    __shared__ float tc[32], ts[32];
    if (threadIdx.x < 32) {
        float a = TWO_PI_32 * (float)threadIdx.x;
        tc[threadIdx.x] = cosf(a);
        ts[threadIdx.x] = sinf(a);
    }
    int bc = blockIdx.x;                               // (bn,c)
    int bn = bc >> 7, c = bc & 127;
    const float2* src = g_Xw + (size_t)bc * HH * MW;
    for (int e = threadIdx.x; e < HH*MW; e += 192) Xs[e] = src[e];
    __syncthreads();
    if (threadIdx.x < 144) {
        int kh = threadIdx.x / 12, kw = threadIdx.x % 12;
        float re = 0.f, im = 0.f;
#pragma unroll
        for (int h = 0; h < HH; h++) {
            int t = (kh*h) & 31;
            float2 v = Xs[h*MW + kw];
            re += v.x*tc[t] + v.y*ts[t];
            im += v.y*tc[t] - v.x*ts[t];
        }
        size_t rowz = (size_t)(bn*144 + threadIdx.x) * 256;
        g_zin[rowz + c]       = re * INV32;
        g_zin[rowz + 128 + c] = im * INV32;
    }
}

// inverse DFT along H of delta modes
__global__ void k_sd() {
    __shared__ float2 D[144];
    __shared__ float tc[32], ts[32];
    if (threadIdx.x < 32) {
        float a = TWO_PI_32 * (float)threadIdx.x;
        tc[threadIdx.x] = cosf(a);
        ts[threadIdx.x] = sinf(a);
    }
    int bc = blockIdx.x;                               // (bn,c)
    int bn = bc >> 7, c = bc & 127;
    if (threadIdx.x < 144) {
        size_t rowz = (size_t)(bn*144 + threadIdx.x) * 256;
        D[threadIdx.x] = make_float2(g_zout[rowz + c]       - g_zin[rowz + c],
                                     g_zout[rowz + 128 + c] - g_zin[rowz + 128 + c]);
    }
    __syncthreads();
    int h = threadIdx.x / 12, kw = threadIdx.x % 12;   // 384 threads = 32*12
    float re = 0.f, im = 0.f;
#pragma unroll
    for (int kh = 0; kh < MH; kh++) {
        int t = (kh*h) & 31;
        float2 d = D[kh*12 + kw];
        re += d.x*tc[t] - d.y*ts[t];
        im += d.x*ts[t] + d.y*tc[t];
    }
    g_tH[(size_t)bc*HH*MW + threadIdx.x] = make_float2(re*INV_SQRT32, im*INV_SQRT32);
}

// final c2r along W of delta + out = 2*y3 + ys, with output transpose
__global__ void k_se(float* __restrict__ out) {
    __shared__ float tc[32], ts[32];
    if (threadIdx.x < 32) {
        float a = TWO_PI_32 * (float)threadIdx.x;
        tc[threadIdx.x] = cosf(a);
        ts[threadIdx.x] = sinf(a);
    }
    __syncthreads();
    int row = blockIdx.x * blockDim.x + threadIdx.x;   // (bn,c,h)
    if (row >= BNN*CC*HH) return;
    int h = row & 31;
    int c = (row >> 5) & 127;
    int bn = row >> 12;
    (void)h;
    float2 T[MW];
    const float2* tp = g_tH + (size_t)row * MW;
#pragma unroll
    for (int kw = 0; kw < MW; kw++) T[kw] = tp[kw];
    const float* yp = g_y3 + (size_t)row * WW;
    int b = bn >> 5, l = bn & 31;
    float* op = out + (((((size_t)b*CC + c)*LL + l)*HH + h)) * WW;
    for (int w = 0; w < WW; w++) {
        float ys = T[0].x;
#pragma unroll
        for (int kw = 1; kw < MW; kw++) {
            int t = (kw*w) & 31;
            ys += 2.f*(T[kw].x*tc[t] - T[kw].y*ts[t]);
        }
        op[w] = 2.f*yp[w] + ys*INV_SQRT32;
    }
}

// ---------------- launch ----------------
static float* symaddr_f(const void* sym) { void* p = 0; cudaGetSymbolAddress(&p, sym); return (float*)p; }

extern "C" void kernel_launch(void* const* d_in, const int* in_sizes, int n_in,
                              void* d_out, int out_size) {
    const float* x      = (const float*)d_in[0];
    const float* dt     = (const float*)d_in[1];
    const float* nu     = (const float*)d_in[2];
    const float* theta  = (const float*)d_in[3];
    const float* ln_g   = (const float*)d_in[4];
    const float* ln_b   = (const float*)d_in[5];
    const float* w_qkv  = (const float*)d_in[6];
    const float* w_proj = (const float*)d_in[7];
    const float* b_proj = (const float*)d_in[8];
    const float* gn_g   = (const float*)d_in[9];
    const float* gn_b   = (const float*)d_in[10];
    const float* w_g    = (const float*)d_in[11];
    const float* w_l    = (const float*)d_in[12];
    const float* w_psi  = (const float*)d_in[13];
    const float* b_psi  = (const float*)d_in[14];
    const float* gate_g = (const float*)d_in[15];
    const float* gate_b = (const float*)d_in[16];
    const float* mix_w  = (const float*)d_in[17];
    const float* mix_b  = (const float*)d_in[18];
    float* out = (float*)d_out;

    float* p_xt  = symaddr_f(g_xt);
    float* p_xn  = symaddr_f(g_xn);
    float* p_qkv = symaddr_f(g_qkv);
    float* p_ao  = symaddr_f(g_ao);
    float* p_y2n = symaddr_f(g_y2n);
    float* p_gp  = symaddr_f(g_gp);
    float* p_gg  = symaddr_f(g_gg);
    float* p_l   = symaddr_f(g_l);
    float* p_zin = symaddr_f(g_zin);
    float* p_zout= symaddr_f(g_zout);
    float2* p_st1 = (float2*)symaddr_f(g_st1);
    float2* p_st2 = (float2*)symaddr_f(g_st2);
    float* p_gate = symaddr_f(g_gate);

    // stage 1
    k_precompA<<<(BB*LL*CC*WF + 255)/256, 256>>>(dt, nu, theta);
    k_rfft<<<(BB*CC*LL*HH + 127)/128, 128>>>(x);
    k_scan<<<(BB*CC*HH*WF + 255)/256, 256>>>();
    k_irfft<<<(BB*LL*HH*CC)/256, 256>>>();
    // stage 2: LN + attention + proj residual
    k_ln<<<(BNN*NP)/8, 256>>>(ln_g, ln_b);
    k_gemm<<<dim3(384/64, (BNN*NP)/64), 256>>>(p_xn, w_qkv, (const float*)0, p_qkv, BNN*NP, 384, CC, 0);
    k_attn<<<BNN*8*4, 256>>>();
    k_gemm<<<dim3(CC/64, (BNN*NP)/64), 256>>>(p_ao, w_proj, b_proj, p_xt, BNN*NP, CC, CC, 1);
    // stage 3: GN1, gating, GN2
    k_gnstats<<<BNN*4, 256>>>(p_xt, (const float*)0, p_st1);
    k_gnapply<<<(BNN*NP*CC)/256, 256>>>(gn_g, gn_b);
    k_pool<<<(BNN*NPC*CC)/256, 256>>>();
    k_gemm<<<dim3(CC/64, (BNN*NPC)/64), 256>>>(p_gp, w_g, (const float*)0, p_gg, BNN*NPC, CC, CC, 0);
    k_gemm<<<dim3(CC/64, (BNN*NP)/64), 256>>>(p_y2n, w_l, (const float*)0, p_l, BNN*NP, CC, CC, 0);
    k_gate<<<(BNN*NP)/8, 256>>>(w_psi, b_psi);
    k_gnstats<<<BNN*4, 256>>>(p_y2n, p_gate, p_st2);
    k_y3<<<(BNN*CC*NP)/256, 256>>>(gate_g, gate_b);
    // stage 4: spectral delta
    k_sa<<<(BNN*CC*HH)/256, 256>>>();
    k_sb<<<BNN*CC, 192>>>();
    k_gemm<<<dim3(256/64, (BNN*144)/64), 256>>>(p_zin, mix_w, mix_b, p_zout, BNN*144, 256, 256, 0);
    k_sd<<<BNN*CC, 384>>>();
    k_se<<<(BNN*CC*HH)/256, 256>>>(out);
}

// round 4
// speedup vs baseline: 2.1857x; 2.1857x over previous
#include <cuda_runtime.h>
#include <cuda_fp16.h>
#include <math.h>

// ---------------- shapes ----------------
#define BB 2
#define CC 128
#define LL 32
#define HH 32
#define WW 32
#define WF 17          // W/2+1
#define BNN 64         // B*L
#define NP 1024        // H*W
#define NPC 256        // pooled pixels (16*16)
#define MH 12
#define MW 12

#define TWO_PI_32 0.19634954084936207f   // 2*pi/32
#define INV32 0.03125f
#define INV_SQRT32 0.17677669529663687f

// ---------------- device scratch ----------------
__device__ float2 g_xf[BB*CC*LL*HH*WF];
__device__ float2 g_A [BB*LL*CC*WF];
__device__ float  g_xt [BNN*NP*CC];
__device__ float  g_xn [BNN*NP*CC];
__device__ float  g_qkv[BNN*NP*384];
__device__ float  g_ao [BNN*NP*CC];
__device__ float  g_y2n[BNN*NP*CC];
__device__ float  g_gp [BNN*NPC*CC];
__device__ float  g_gg [BNN*NPC*CC];
__device__ float  g_l  [BNN*NP*CC];
__device__ float  g_gate[BNN*NP];
__device__ float  g_y3 [BNN*CC*NP];
__device__ float2 g_Xw [BNN*CC*HH*MW];
__device__ float  g_zin [BNN*144*256];
__device__ float  g_zout[BNN*144*256];
__device__ float2 g_tH [BNN*CC*HH*MW];
__device__ float2 g_st1[BNN*4];
__device__ float2 g_st2[BNN*4];

// ---------------- mma helpers ----------------
__device__ __forceinline__ unsigned f2tf32(float f) {
    unsigned r; asm("cvt.rna.tf32.f32 %0, %1;" : "=r"(r) : "f"(f)); return r;
}
__device__ __forceinline__ void mma_tf32(float* c, const unsigned* a, const unsigned* b) {
    asm("mma.sync.aligned.m16n8k8.row.col.f32.tf32.tf32.f32 "
        "{%0,%1,%2,%3}, {%4,%5,%6,%7}, {%8,%9}, {%0,%1,%2,%3};"
        : "+f"(c[0]), "+f"(c[1]), "+f"(c[2]), "+f"(c[3])
        : "r"(a[0]), "r"(a[1]), "r"(a[2]), "r"(a[3]), "r"(b[0]), "r"(b[1]));
}
__device__ __forceinline__ void mma_f16(float* c, const unsigned* a, const unsigned* b) {
    asm("mma.sync.aligned.m16n8k16.row.col.f32.f16.f16.f32 "
        "{%0,%1,%2,%3}, {%4,%5,%6,%7}, {%8,%9}, {%0,%1,%2,%3};"
        : "+f"(c[0]), "+f"(c[1]), "+f"(c[2]), "+f"(c[3])
        : "r"(a[0]), "r"(a[1]), "r"(a[2]), "r"(a[3]), "r"(b[0]), "r"(b[1]));
}
__device__ __forceinline__ unsigned packh2(float a, float b) {
    __half2 h = __floats2half2_rn(a, b);
    return *(unsigned*)&h;
}
__device__ __forceinline__ float expc(float x) {      // clamped exp, never -inf input
    return __expf(fmaxf(x, -80.f));
}

// ---------------- stage 1: A precompute ----------------
__global__ void k_precompA(const float* __restrict__ dt, const float* __restrict__ nu,
                           const float* __restrict__ th) {
    int i = blockIdx.x * blockDim.x + threadIdx.x;
    if (i >= BB*LL*CC*WF) return;
    int k = i % WF;
    int c = (i / WF) % CC;
    int l = (i / (WF*CC)) % LL;
    int b =  i / (WF*CC*LL);
    float d  = dt[b*LL + l];
    float e  = expf(-nu[c*WF + k] * d);
    float si, co;
    sincosf(th[c*WF + k] * d, &si, &co);
    g_A[i] = make_float2(e*co, e*si);
}

// ---------------- stage 1: rfft along W ----------------
__global__ void k_rfft(const float* __restrict__ x) {
    __shared__ float tc[32], ts[32];
    if (threadIdx.x < 32) {
        float a = TWO_PI_32 * (float)threadIdx.x;
        tc[threadIdx.x] = cosf(a);
        ts[threadIdx.x] = sinf(a);
    }
    __syncthreads();
    int row = blockIdx.x * blockDim.x + threadIdx.x;   // (b,c,l,h)
    if (row >= BB*CC*LL*HH) return;
    const float* xp = x + (size_t)row * WW;
    float xr[WW];
#pragma unroll
    for (int w = 0; w < WW; w++) xr[w] = xp[w];
    float2* out = g_xf + (size_t)row * WF;
    for (int k = 0; k < WF; k++) {
        float re = 0.f, im = 0.f;
#pragma unroll
        for (int w = 0; w < WW; w++) {
            int t = (w*k) & 31;
            re += xr[w]*tc[t];
            im -= xr[w]*ts[t];
        }
        out[k] = make_float2(re, im);
    }
}

// ---------------- stage 1: complex scan over L ----------------
__global__ void k_scan() {
    int i = blockIdx.x * blockDim.x + threadIdx.x;     // (b,c,h,k)
    if (i >= BB*CC*HH*WF) return;
    int k = i % WF;
    int h = (i / WF) % HH;
    int c = (i / (WF*HH)) % CC;
    int b =  i / (WF*HH*CC);
    size_t xfb = ((((size_t)b*CC + c)*LL)*HH + h)*WF + k;
    const size_t xstr = (size_t)HH*WF;
    size_t ab = ((size_t)b*LL*CC + c)*WF + k;
    const size_t astr = (size_t)CC*WF;
    float2 s = make_float2(0.f, 0.f);
    for (int l = 0; l < LL; l++) {
        float2 a = g_A[ab + (size_t)l*astr];
        float2 u = g_xf[xfb + (size_t)l*xstr];
        float re = a.x*s.x - a.y*s.y + u.x;
        float im = a.x*s.y + a.y*s.x + u.y;
        s = make_float2(re, im);
        g_xf[xfb + (size_t)l*xstr] = s;
    }
}

// ---------------- stage 1: irfft -> xt channels-last ----------------
__global__ void k_irfft() {
    __shared__ float tc[32], ts[32];
    if (threadIdx.x < 32) {
        float a = TWO_PI_32 * (float)threadIdx.x;
        tc[threadIdx.x] = cosf(a);
        ts[threadIdx.x] = sinf(a);
    }
    __syncthreads();
    int i = blockIdx.x * blockDim.x + threadIdx.x;     // (b,l,h,c)
    if (i >= BB*LL*HH*CC) return;
    int c = i & 127;
    int h = (i >> 7) & 31;
    int l = (i >> 12) & 31;
    int b =  i >> 17;
    const float2* st = g_xf + ((((size_t)b*CC + c)*LL + l)*HH + h)*WF;
    float2 S[WF];
#pragma unroll
    for (int k = 0; k < WF; k++) S[k] = st[k];
    int bn = b*LL + l;
    float* out = g_xt + ((size_t)bn*NP + h*WW)*CC + c;
    for (int w = 0; w < WW; w++) {
        float v = S[0].x + ((w & 1) ? -S[16].x : S[16].x);
#pragma unroll
        for (int k = 1; k < 16; k++) {
            int t = (w*k) & 31;
            v += 2.f*(S[k].x*tc[t] - S[k].y*ts[t]);
        }
        out[(size_t)w*CC] = v * INV32;
    }
}

// ---------------- LayerNorm over C ----------------
__global__ void k_ln(const float* __restrict__ g, const float* __restrict__ b) {
    int lane = threadIdx.x & 31, wid = threadIdx.x >> 5;
    int r = blockIdx.x*8 + wid;
    float4 v = ((const float4*)(g_xt + (size_t)r*CC))[lane];
    float s = v.x + v.y + v.z + v.w;
#pragma unroll
    for (int o = 16; o; o >>= 1) s += __shfl_xor_sync(0xffffffffu, s, o);
    float mu = s * (1.f/128.f);
    float dx = v.x-mu, dy = v.y-mu, dz = v.z-mu, dw = v.w-mu;
    float q = dx*dx + dy*dy + dz*dz + dw*dw;
#pragma unroll
    for (int o = 16; o; o >>= 1) q += __shfl_xor_sync(0xffffffffu, q, o);
    float rstd = rsqrtf(q*(1.f/128.f) + 1e-5f);
    float4 g4 = ((const float4*)g)[lane];
    float4 b4 = ((const float4*)b)[lane];
    float4 o4;
    o4.x = dx*rstd*g4.x + b4.x;
    o4.y = dy*rstd*g4.y + b4.y;
    o4.z = dz*rstd*g4.z + b4.z;
    o4.w = dw*rstd*g4.w + b4.w;
    ((float4*)(g_xn + (size_t)r*CC))[lane] = o4;
}

// ---------------- tf32 tensor-core GEMM: C[M,N] (=/+=) A[M,K]*B[N,K]^T (+bias) ----
__global__ void k_gemm_tc(const float* __restrict__ A, const float* __restrict__ B,
                          const float* __restrict__ bias, float* __restrict__ C,
                          int M, int N, int K, int accum) {
    __shared__ unsigned As[64*36];
    __shared__ unsigned Bs[64*36];
    int bm = blockIdx.y << 6, bn = blockIdx.x << 6;
    int warp = threadIdx.x >> 5, lane = threadIdx.x & 31;
    int lr = lane >> 2, lc = lane & 3;
    float acc[8][4];
#pragma unroll
    for (int nf = 0; nf < 8; nf++)
#pragma unroll
        for (int j = 0; j < 4; j++) acc[nf][j] = 0.f;

    for (int k0 = 0; k0 < K; k0 += 32) {
        __syncthreads();
#pragma unroll
        for (int i = 0; i < 4; i++) {
            int slot = threadIdx.x + i*128;     // 512 slots = 64 rows x 8 segs
            int m = slot >> 3, seg = (slot & 7) << 2;
            float4 a4 = *(const float4*)(A + (size_t)(bm+m)*K + k0 + seg);
            uint4 au = make_uint4(f2tf32(a4.x), f2tf32(a4.y), f2tf32(a4.z), f2tf32(a4.w));
            *(uint4*)&As[m*36 + seg] = au;
            float4 b4 = *(const float4*)(B + (size_t)(bn+m)*K + k0 + seg);
            uint4 bu = make_uint4(f2tf32(b4.x), f2tf32(b4.y), f2tf32(b4.z), f2tf32(b4.w));
            *(uint4*)&Bs[m*36 + seg] = bu;
        }
        __syncthreads();
#pragma unroll
        for (int ks = 0; ks < 4; ks++) {
            unsigned a[4];
            int am = warp*16;
            a[0] = As[(am+lr  )*36 + ks*8 + lc];
            a[1] = As[(am+lr+8)*36 + ks*8 + lc];
            a[2] = As[(am+lr  )*36 + ks*8 + lc + 4];
            a[3] = As[(am+lr+8)*36 + ks*8 + lc + 4];
#pragma unroll
            for (int nf = 0; nf < 8; nf++) {
                unsigned b[2];
                b[0] = Bs[(nf*8+lr)*36 + ks*8 + lc];
                b[1] = Bs[(nf*8+lr)*36 + ks*8 + lc + 4];
                mma_tf32(acc[nf], a, b);
            }
        }
    }
#pragma unroll
    for (int nf = 0; nf < 8; nf++) {
        int col = bn + nf*8 + lc*2;
        float b0 = bias ? bias[col] : 0.f;
        float b1 = bias ? bias[col+1] : 0.f;
        int row = bm + warp*16 + lr;
        float2* p = (float2*)(C + (size_t)row*N + col);
        float2 v = make_float2(acc[nf][0]+b0, acc[nf][1]+b1);
        if (accum) { float2 o = *p; v.x += o.x; v.y += o.y; }
        *p = v;
        row += 8;
        p = (float2*)(C + (size_t)row*N + col);
        v = make_float2(acc[nf][2]+b0, acc[nf][3]+b1);
        if (accum) { float2 o = *p; v.x += o.x; v.y += o.y; }
        *p = v;
    }
}

// ---------------- fp32 SIMT GEMM (cancellation-sensitive mix GEMM) ------
__global__ void k_gemm(const float* __restrict__ A, const float* __restrict__ B,
                       const float* __restrict__ bias, float* __restrict__ C,
                       int M, int N, int K, int accum) {
    __shared__ float As[16][72];
    __shared__ float Bs[16][72];
    int bm = blockIdx.y << 6, bn = blockIdx.x << 6;
    int tid = threadIdx.x;
    int tx = tid & 15, ty = tid >> 4;
    int lm = tid >> 2, lk = (tid & 3) << 2;
    float acc[4][4];
#pragma unroll
    for (int i = 0; i < 4; i++)
#pragma unroll
        for (int j = 0; j < 4; j++) acc[i][j] = 0.f;

    for (int k0 = 0; k0 < K; k0 += 16) {
        float4 a4 = *(const float4*)(A + (size_t)(bm+lm)*K + k0 + lk);
        float4 b4 = *(const float4*)(B + (size_t)(bn+lm)*K + k0 + lk);
        As[lk+0][lm] = a4.x; As[lk+1][lm] = a4.y; As[lk+2][lm] = a4.z; As[lk+3][lm] = a4.w;
        Bs[lk+0][lm] = b4.x; Bs[lk+1][lm] = b4.y; Bs[lk+2][lm] = b4.z; Bs[lk+3][lm] = b4.w;
        __syncthreads();
#pragma unroll
        for (int k = 0; k < 16; k++) {
            float4 av = *(const float4*)&As[k][ty << 2];
            float4 bv = *(const float4*)&Bs[k][tx << 2];
            acc[0][0] += av.x*bv.x; acc[0][1] += av.x*bv.y; acc[0][2] += av.x*bv.z; acc[0][3] += av.x*bv.w;
            acc[1][0] += av.y*bv.x; acc[1][1] += av.y*bv.y; acc[1][2] += av.y*bv.z; acc[1][3] += av.y*bv.w;
            acc[2][0] += av.z*bv.x; acc[2][1] += av.z*bv.y; acc[2][2] += av.z*bv.z; acc[2][3] += av.z*bv.w;
            acc[3][0] += av.w*bv.x; acc[3][1] += av.w*bv.y; acc[3][2] += av.w*bv.z; acc[3][3] += av.w*bv.w;
        }
        __syncthreads();
    }
#pragma unroll
    for (int i = 0; i < 4; i++) {
        int row = bm + (ty << 2) + i;
#pragma unroll
        for (int j = 0; j < 4; j++) {
            int col = bn + (tx << 2) + j;
            float v = acc[i][j];
            if (bias) v += bias[col];
            size_t ci = (size_t)row*N + col;
            if (accum) v += C[ci];
            C[ci] = v;
        }
    }
}

// ---------------- flash attention: tf32 QK mma + fp16 PV mma --------------------
__global__ void k_fattn() {
    __shared__ unsigned Ksu[64][20];        // K chunk, tf32 bits, padded
    __shared__ __half   Vt[16][72];         // V chunk transposed [d][key], padded
    int blk = blockIdx.x;                   // qt + 16*(head + 8*bn)
    int qt = blk & 15, head = (blk >> 4) & 7, bn = blk >> 7;
    int warp = threadIdx.x >> 5, lane = threadIdx.x & 31;
    int lr = lane >> 2, lc = lane & 3;
    int q0 = qt*64 + warp*16;
    const float* qbase = g_qkv + (size_t)bn*NP*384 + head*16;

    // Q fragments, scaled by hd^-0.5 = 0.25
    unsigned Qa[2][4];
#pragma unroll
    for (int kf = 0; kf < 2; kf++) {
        int col = kf*8 + lc;
        Qa[kf][0] = f2tf32(0.25f * qbase[(size_t)(q0+lr  )*384 + col]);
        Qa[kf][1] = f2tf32(0.25f * qbase[(size_t)(q0+lr+8)*384 + col]);
        Qa[kf][2] = f2tf32(0.25f * qbase[(size_t)(q0+lr  )*384 + col+4]);
        Qa[kf][3] = f2tf32(0.25f * qbase[(size_t)(q0+lr+8)*384 + col+4]);
    }

    float m0 = -1e30f, m1 = -1e30f, l0 = 0.f, l1 = 0.f;
    float Oa[2][4];
#pragma unroll
    for (int dn = 0; dn < 2; dn++)
#pragma unroll
        for (int j = 0; j < 4; j++) Oa[dn][j] = 0.f;

    for (int c0 = 0; c0 < NP; c0 += 64) {
        __syncthreads();
#pragma unroll
        for (int i = 0; i < 2; i++) {
            int slot = threadIdx.x + i*128;           // 256 slots = 64 keys x 4 segs
            int key = slot >> 2, seg = (slot & 3) << 2;
            const float* kp = qbase + (size_t)(c0 + key)*384 + 128 + seg;
            float4 kv = *(const float4*)kp;
            Ksu[key][seg+0] = f2tf32(kv.x);
            Ksu[key][seg+1] = f2tf32(kv.y);
            Ksu[key][seg+2] = f2tf32(kv.z);
            Ksu[key][seg+3] = f2tf32(kv.w);
            float4 vv = *(const float4*)(kp + 128);
            Vt[seg+0][key] = __float2half(vv.x);
            Vt[seg+1][key] = __float2half(vv.y);
            Vt[seg+2][key] = __float2half(vv.z);
            Vt[seg+3][key] = __float2half(vv.w);
        }
        __syncthreads();

        // S = Q K^T
        float S[8][4];
#pragma unroll
        for (int nf = 0; nf < 8; nf++) {
#pragma unroll
            for (int j = 0; j < 4; j++) S[nf][j] = 0.f;
#pragma unroll
            for (int kf = 0; kf < 2; kf++) {
                unsigned b[2];
                b[0] = Ksu[nf*8 + lr][kf*8 + lc];
                b[1] = Ksu[nf*8 + lr][kf*8 + lc + 4];
                mma_tf32(S[nf], Qa[kf], b);
            }
        }

        // online softmax
        float mx0 = -1e30f, mx1 = -1e30f;
#pragma unroll
        for (int nf = 0; nf < 8; nf++) {
            mx0 = fmaxf(mx0, fmaxf(S[nf][0], S[nf][1]));
            mx1 = fmaxf(mx1, fmaxf(S[nf][2], S[nf][3]));
        }
#pragma unroll
        for (int o = 1; o <= 2; o <<= 1) {
            mx0 = fmaxf(mx0, __shfl_xor_sync(0xffffffffu, mx0, o));
            mx1 = fmaxf(mx1, __shfl_xor_sync(0xffffffffu, mx1, o));
        }
        float nm0 = fmaxf(m0, mx0), nm1 = fmaxf(m1, mx1);
        float sc0 = expc(m0 - nm0), sc1 = expc(m1 - nm1);
        float ps0 = 0.f, ps1 = 0.f;
#pragma unroll
        for (int nf = 0; nf < 8; nf++) {
            S[nf][0] = expc(S[nf][0] - nm0);
            S[nf][1] = expc(S[nf][1] - nm0);
            S[nf][2] = expc(S[nf][2] - nm1);
            S[nf][3] = expc(S[nf][3] - nm1);
            ps0 += S[nf][0] + S[nf][1];
            ps1 += S[nf][2] + S[nf][3];
        }
        l0 = l0*sc0 + ps0;
        l1 = l1*sc1 + ps1;
#pragma unroll
        for (int dn = 0; dn < 2; dn++) {
            Oa[dn][0] *= sc0; Oa[dn][1] *= sc0;
            Oa[dn][2] *= sc1; Oa[dn][3] *= sc1;
        }
        m0 = nm0; m1 = nm1;

        // P (fp16) @ V
#pragma unroll
        for (int j = 0; j < 4; j++) {
            unsigned a[4];
            a[0] = packh2(S[2*j  ][0], S[2*j  ][1]);
            a[1] = packh2(S[2*j  ][2], S[2*j  ][3]);
            a[2] = packh2(S[2*j+1][0], S[2*j+1][1]);
            a[3] = packh2(S[2*j+1][2], S[2*j+1][3]);
#pragma unroll
            for (int dn = 0; dn < 2; dn++) {
                unsigned b[2];
                b[0] = *(const unsigned*)&Vt[dn*8 + lr][j*16 + lc*2];
                b[1] = *(const unsigned*)&Vt[dn*8 + lr][j*16 + lc*2 + 8];
                mma_f16(Oa[dn], a, b);
            }
        }
    }

#pragma unroll
    for (int o = 1; o <= 2; o <<= 1) {
        l0 += __shfl_xor_sync(0xffffffffu, l0, o);
        l1 += __shfl_xor_sync(0xffffffffu, l1, o);
    }
    float inv0 = 1.f / l0, inv1 = 1.f / l1;
    float* ob = g_ao + (size_t)bn*NP*CC + head*16;
#pragma unroll
    for (int dn = 0; dn < 2; dn++) {
        int col = dn*8 + lc*2;
        *(float2*)(ob + (size_t)(q0+lr  )*CC + col) = make_float2(Oa[dn][0]*inv0, Oa[dn][1]*inv0);
        *(float2*)(ob + (size_t)(q0+lr+8)*CC + col) = make_float2(Oa[dn][2]*inv1, Oa[dn][3]*inv1);
    }
}

// ---------------- GroupNorm stats (optionally gated input) ----------------
__global__ void k_gnstats(const float* __restrict__ X, const float* __restrict__ gate,
                          float2* __restrict__ stats) {
    __shared__ float sh[256], sh2[256];
    int bn = blockIdx.x >> 2, g = blockIdx.x & 3;
    float s = 0.f, q = 0.f;
    const float* base = X + (size_t)bn*NP*CC + g*32;
    for (int e = threadIdx.x; e < 32768; e += 256) {
        int n = e >> 5, cc = e & 31;
        float v = base[(size_t)n*CC + cc];
        if (gate) v *= gate[bn*NP + n];
        s += v; q += v*v;
    }
    sh[threadIdx.x] = s; sh2[threadIdx.x] = q;
    __syncthreads();
    for (int o = 128; o; o >>= 1) {
        if (threadIdx.x < o) { sh[threadIdx.x] += sh[threadIdx.x+o]; sh2[threadIdx.x] += sh2[threadIdx.x+o]; }
        __syncthreads();
    }
    if (threadIdx.x == 0) {
        float mu = sh[0] * (1.f/32768.f);
        float var = sh2[0] * (1.f/32768.f) - mu*mu;
        stats[blockIdx.x] = make_float2(mu, rsqrtf(var + 1e-5f));
    }
}

__global__ void k_gnapply(const float* __restrict__ g, const float* __restrict__ b) {
    int i = blockIdx.x * blockDim.x + threadIdx.x;
    if (i >= BNN*NP*CC) return;
    int c = i & 127;
    int bn = i >> 17;
    float2 st = g_st1[bn*4 + (c >> 5)];
    g_y2n[i] = (g_xt[i] - st.x)*st.y*g[c] + b[c];
}

__global__ void k_pool() {
    int i = blockIdx.x * blockDim.x + threadIdx.x;     // (bn,pc,c)
    if (i >= BNN*NPC*CC) return;
    int c = i & 127;
    int pc = (i >> 7) & 255;
    int bn = i >> 15;
    int hp = pc >> 4, wp = pc & 15;
    size_t base = ((size_t)bn*NP + hp*64 + wp*2)*CC + c;
    g_gp[i] = 0.25f*(g_y2n[base] + g_y2n[base + CC] + g_y2n[base + 32*CC] + g_y2n[base + 33*CC]);
}

__global__ void k_gate(const float* __restrict__ w_psi, const float* __restrict__ b_psi) {
    int lane = threadIdx.x & 31, wid = threadIdx.x >> 5;
    int p = blockIdx.x*8 + wid;                        // 65536 pixels
    int bn = p >> 10, n = p & 1023;
    int h = n >> 5, w = n & 31;
    int pc = (h >> 1)*16 + (w >> 1);
    float4 gv = ((const float4*)(g_gg + ((size_t)bn*NPC + pc)*CC))[lane];
    float4 lv = ((const float4*)(g_l  + (size_t)p*CC))[lane];
    float4 wp = ((const float4*)w_psi)[lane];
    float s = fmaxf(gv.x+lv.x, 0.f)*wp.x + fmaxf(gv.y+lv.y, 0.f)*wp.y
            + fmaxf(gv.z+lv.z, 0.f)*wp.z + fmaxf(gv.w+lv.w, 0.f)*wp.w;
#pragma unroll
    for (int o = 16; o; o >>= 1) s += __shfl_xor_sync(0xffffffffu, s, o);
    if (lane == 0) g_gate[p] = 1.f/(1.f + expf(-(s + b_psi[0])));
}

__global__ void k_y3(const float* __restrict__ g, const float* __restrict__ b) {
    int i = blockIdx.x * blockDim.x + threadIdx.x;     // (bn,c,n)
    if (i >= BNN*CC*NP) return;
    int n = i & 1023;
    int c = (i >> 10) & 127;
    int bn = i >> 17;
    float v = g_y2n[((size_t)bn*NP + n)*CC + c] * g_gate[bn*NP + n];
    float2 st = g_st2[bn*4 + (c >> 5)];
    g_y3[i] = (v - st.x)*st.y*g[c] + b[c];
}

// ---------------- spectral: partial rfft along W ----------------
__global__ void k_sa() {
    __shared__ float tc[32], ts[32];
    if (threadIdx.x < 32) {
        float a = TWO_PI_32 * (float)threadIdx.x;
        tc[threadIdx.x] = cosf(a);
        ts[threadIdx.x] = sinf(a);
    }
    __syncthreads();
    int row = blockIdx.x * blockDim.x + threadIdx.x;   // (bn,c,h)
    if (row >= BNN*CC*HH) return;
    const float* yp = g_y3 + (size_t)row * WW;
    float xr[WW];
#pragma unroll
    for (int w = 0; w < WW; w++) xr[w] = yp[w];
    float2* out = g_Xw + (size_t)row * MW;
    for (int kw = 0; kw < MW; kw++) {
        float re = 0.f, im = 0.f;
#pragma unroll
        for (int w = 0; w < WW; w++) {
            int t = (w*kw) & 31;
            re += xr[w]*tc[t];
            im -= xr[w]*ts[t];
        }
        out[kw] = make_float2(re, im);
    }
}

// partial DFT along H (modes 0..11) -> z rows for mix GEMM
__global__ void k_sb() {
    __shared__ float2 Xs[HH*MW];
    __shared__ float tc[32], ts[32];
    if (threadIdx.x < 32) {
        float a = TWO_PI_32 * (float)threadIdx.x;
        tc[threadIdx.x] = cosf(a);
        ts[threadIdx.x] = sinf(a);
    }
    int bc = blockIdx.x;                               // (bn,c)
    int bn = bc >> 7, c = bc & 127;
    const float2* src = g_Xw + (size_t)bc * HH * MW;
    for (int e = threadIdx.x; e < HH*MW; e += 192) Xs[e] = src[e];
    __syncthreads();
    if (threadIdx.x < 144) {
        int kh = threadIdx.x / 12, kw = threadIdx.x % 12;
        float re = 0.f, im = 0.f;
#pragma unroll
        for (int h = 0; h < HH; h++) {
            int t = (kh*h) & 31;
            float2 v = Xs[h*MW + kw];
            re += v.x*tc[t] + v.y*ts[t];
            im += v.y*tc[t] - v.x*ts[t];
        }
        size_t rowz = (size_t)(bn*144 + threadIdx.x) * 256;
        g_zin[rowz + c]       = re * INV32;
        g_zin[rowz + 128 + c] = im * INV32;
    }
    __syncthreads();
}

// inverse DFT along H of delta modes
__global__ void k_sd() {
    __shared__ float2 D[144];
    __shared__ float tc[32], ts[32];
    if (threadIdx.x < 32) {
        float a = TWO_PI_32 * (float)threadIdx.x;
        tc[threadIdx.x] = cosf(a);
        ts[threadIdx.x] = sinf(a);
    }
    int bc = blockIdx.x;                               // (bn,c)
    int bn = bc >> 7, c = bc & 127;
    if (threadIdx.x < 144) {
        size_t rowz = (size_t)(bn*144 + threadIdx.x) * 256;
        D[threadIdx.x] = make_float2(g_zout[rowz + c]       - g_zin[rowz + c],
                                     g_zout[rowz + 128 + c] - g_zin[rowz + 128 + c]);
    }
    __syncthreads();
    int h = threadIdx.x / 12, kw = threadIdx.x % 12;   // 384 threads
    float re = 0.f, im = 0.f;
#pragma unroll
    for (int kh = 0; kh < MH; kh++) {
        int t = (kh*h) & 31;
        float2 d = D[kh*12 + kw];
        re += d.x*tc[t] - d.y*ts[t];
        im += d.x*ts[t] + d.y*tc[t];
    }
    g_tH[(size_t)bc*HH*MW + threadIdx.x] = make_float2(re*INV_SQRT32, im*INV_SQRT32);
}

// final c2r along W of delta + out = 2*y3 + ys, output transpose
__global__ void k_se(float* __restrict__ out) {
    __shared__ float tc[32], ts[32];
    if (threadIdx.x < 32) {
        float a = TWO_PI_32 * (float)threadIdx.x;
        tc[threadIdx.x] = cosf(a);
        ts[threadIdx.x] = sinf(a);
    }
    __syncthreads();
    int row = blockIdx.x * blockDim.x + threadIdx.x;   // (bn,c,h)
    if (row >= BNN*CC*HH) return;
    int h = row & 31;
    int c = (row >> 5) & 127;
    int bn = row >> 12;
    float2 T[MW];
    const float2* tp = g_tH + (size_t)row * MW;
#pragma unroll
    for (int kw = 0; kw < MW; kw++) T[kw] = tp[kw];
    const float* yp = g_y3 + (size_t)row * WW;
    int b = bn >> 5, l = bn & 31;
    float* op = out + (((((size_t)b*CC + c)*LL + l)*HH + h)) * WW;
    for (int w = 0; w < WW; w++) {
        float ys = T[0].x;
#pragma unroll
        for (int kw = 1; kw < MW; kw++) {
            int t = (kw*w) & 31;
            ys += 2.f*(T[kw].x*tc[t] - T[kw].y*ts[t]);
        }
        op[w] = 2.f*yp[w] + ys*INV_SQRT32;
    }
}

// ---------------- launch ----------------
static float* symaddr_f(const void* sym) { void* p = 0; cudaGetSymbolAddress(&p, sym); return (float*)p; }

extern "C" void kernel_launch(void* const* d_in, const int* in_sizes, int n_in,
                              void* d_out, int out_size) {
    const float* x      = (const float*)d_in[0];
    const float* dt     = (const float*)d_in[1];
    const float* nu     = (const float*)d_in[2];
    const float* theta  = (const float*)d_in[3];
    const float* ln_g   = (const float*)d_in[4];
    const float* ln_b   = (const float*)d_in[5];
    const float* w_qkv  = (const float*)d_in[6];
    const float* w_proj = (const float*)d_in[7];
    const float* b_proj = (const float*)d_in[8];
    const float* gn_g   = (const float*)d_in[9];
    const float* gn_b   = (const float*)d_in[10];
    const float* w_g    = (const float*)d_in[11];
    const float* w_l    = (const float*)d_in[12];
    const float* w_psi  = (const float*)d_in[13];
    const float* b_psi  = (const float*)d_in[14];
    const float* gate_g = (const float*)d_in[15];
    const float* gate_b = (const float*)d_in[16];
    const float* mix_w  = (const float*)d_in[17];
    const float* mix_b  = (const float*)d_in[18];
    float* out = (float*)d_out;

    float* p_xt  = symaddr_f(g_xt);
    float* p_xn  = symaddr_f(g_xn);
    float* p_qkv = symaddr_f(g_qkv);
    float* p_ao  = symaddr_f(g_ao);
    float* p_y2n = symaddr_f(g_y2n);
    float* p_gp  = symaddr_f(g_gp);
    float* p_gg  = symaddr_f(g_gg);
    float* p_l   = symaddr_f(g_l);
    float* p_zin = symaddr_f(g_zin);
    float* p_zout= symaddr_f(g_zout);
    float2* p_st1 = (float2*)symaddr_f(g_st1);
    float2* p_st2 = (float2*)symaddr_f(g_st2);
    float* p_gate = symaddr_f(g_gate);

    // stage 1
    k_precompA<<<(BB*LL*CC*WF + 255)/256, 256>>>(dt, nu, theta);
    k_rfft<<<(BB*CC*LL*HH + 127)/128, 128>>>(x);
    k_scan<<<(BB*CC*HH*WF + 255)/256, 256>>>();
    k_irfft<<<(BB*LL*HH*CC)/256, 256>>>();
    // stage 2: LN + attention + proj residual
    k_ln<<<(BNN*NP)/8, 256>>>(ln_g, ln_b);
    k_gemm_tc<<<dim3(384/64, (BNN*NP)/64), 128>>>(p_xn, w_qkv, (const float*)0, p_qkv, BNN*NP, 384, CC, 0);
    k_fattn<<<BNN*8*16, 128>>>();
    k_gemm_tc<<<dim3(CC/64, (BNN*NP)/64), 128>>>(p_ao, w_proj, b_proj, p_xt, BNN*NP, CC, CC, 1);
    // stage 3: GN1, gating, GN2
    k_gnstats<<<BNN*4, 256>>>(p_xt, (const float*)0, p_st1);
    k_gnapply<<<(BNN*NP*CC)/256, 256>>>(gn_g, gn_b);
    k_pool<<<(BNN*NPC*CC)/256, 256>>>();
    k_gemm_tc<<<dim3(CC/64, (BNN*NPC)/64), 128>>>(p_gp, w_g, (const float*)0, p_gg, BNN*NPC, CC, CC, 0);
    k_gemm_tc<<<dim3(CC/64, (BNN*NP)/64), 128>>>(p_y2n, w_l, (const float*)0, p_l, BNN*NP, CC, CC, 0);
    k_gate<<<(BNN*NP)/8, 256>>>(w_psi, b_psi);
    k_gnstats<<<BNN*4, 256>>>(p_y2n, p_gate, p_st2);
    k_y3<<<(BNN*CC*NP)/256, 256>>>(gate_g, gate_b);
    // stage 4: spectral delta (mix GEMM stays fp32 SIMT: zout-zin cancellation)
    k_sa<<<(BNN*CC*HH)/256, 256>>>();
    k_sb<<<BNN*CC, 192>>>();
    k_gemm<<<dim3(256/64, (BNN*144)/64), 256>>>(p_zin, mix_w, mix_b, p_zout, BNN*144, 256, 256, 0);
    k_sd<<<BNN*CC, 384>>>();
    k_se<<<(BNN*CC*HH)/256, 256>>>(out);
}

// round 5
// speedup vs baseline: 2.4224x; 1.1083x over previous
#include <cuda_runtime.h>
#include <cuda_fp16.h>
#include <math.h>

// ---------------- shapes ----------------
#define BB 2
#define CC 128
#define LL 32
#define HH 32
#define WW 32
#define WF 17          // W/2+1
#define BNN 64         // B*L
#define NP 1024        // H*W
#define NPC 256        // pooled pixels (16*16)
#define MH 12
#define MW 12

#define TWO_PI_32 0.19634954084936207f   // 2*pi/32
#define INV32 0.03125f
#define INV_SQRT32 0.17677669529663687f
#define QK_SCALE 0.36067376022224085f    // 0.25 * log2(e)

// ---------------- device scratch ----------------
__device__ float2 g_xf[BB*CC*LL*HH*WF];
__device__ float2 g_A [BB*LL*CC*WF];
__device__ float  g_xt [BNN*NP*CC];
__device__ float  g_xn [BNN*NP*CC];
__device__ float  g_qkv[BNN*NP*384];
__device__ float  g_ao [BNN*NP*CC];
__device__ float  g_y2n[BNN*NP*CC];
__device__ float  g_gp [BNN*NPC*CC];
__device__ float  g_gg [BNN*NPC*CC];
__device__ float  g_l  [BNN*NP*CC];
__device__ float  g_gate[BNN*NP];
__device__ float  g_y3 [BNN*CC*NP];
__device__ float2 g_Xw [BNN*CC*HH*MW];
__device__ float  g_zin [BNN*144*256];
__device__ float  g_zout[BNN*144*256];
__device__ float2 g_tH [BNN*CC*HH*MW];
__device__ float2 g_st1[BNN*4];
__device__ float2 g_st2[BNN*4];

// ---------------- mma helpers ----------------
__device__ __forceinline__ unsigned f2tf32(float f) {
    unsigned r; asm("cvt.rna.tf32.f32 %0, %1;" : "=r"(r) : "f"(f)); return r;
}
__device__ __forceinline__ void mma_tf32(float* c, const unsigned* a, const unsigned* b) {
    asm("mma.sync.aligned.m16n8k8.row.col.f32.tf32.tf32.f32 "
        "{%0,%1,%2,%3}, {%4,%5,%6,%7}, {%8,%9}, {%0,%1,%2,%3};"
        : "+f"(c[0]), "+f"(c[1]), "+f"(c[2]), "+f"(c[3])
        : "r"(a[0]), "r"(a[1]), "r"(a[2]), "r"(a[3]), "r"(b[0]), "r"(b[1]));
}
__device__ __forceinline__ void mma_f16(float* c, const unsigned* a, const unsigned* b) {
    asm("mma.sync.aligned.m16n8k16.row.col.f32.f16.f16.f32 "
        "{%0,%1,%2,%3}, {%4,%5,%6,%7}, {%8,%9}, {%0,%1,%2,%3};"
        : "+f"(c[0]), "+f"(c[1]), "+f"(c[2]), "+f"(c[3])
        : "r"(a[0]), "r"(a[1]), "r"(a[2]), "r"(a[3]), "r"(b[0]), "r"(b[1]));
}
__device__ __forceinline__ unsigned packh2(float a, float b) {
    __half2 h = __floats2half2_rn(a, b);
    return *(unsigned*)&h;
}
__device__ __forceinline__ float ex2a(float x) {       // 2^x, overflow-clamped
    float r; asm("ex2.approx.f32 %0, %1;" : "=f"(r) : "f"(fminf(x, 80.f))); return r;
}

// ---------------- stage 1: A precompute ----------------
__global__ void k_precompA(const float* __restrict__ dt, const float* __restrict__ nu,
                           const float* __restrict__ th) {
    int i = blockIdx.x * blockDim.x + threadIdx.x;
    if (i >= BB*LL*CC*WF) return;
    int k = i % WF;
    int c = (i / WF) % CC;
    int l = (i / (WF*CC)) % LL;
    int b =  i / (WF*CC*LL);
    float d  = dt[b*LL + l];
    float e  = expf(-nu[c*WF + k] * d);
    float si, co;
    sincosf(th[c*WF + k] * d, &si, &co);
    g_A[i] = make_float2(e*co, e*si);
}

// ---------------- stage 1: rfft along W ----------------
__global__ void k_rfft(const float* __restrict__ x) {
    __shared__ float tc[32], ts[32];
    if (threadIdx.x < 32) {
        float a = TWO_PI_32 * (float)threadIdx.x;
        tc[threadIdx.x] = cosf(a);
        ts[threadIdx.x] = sinf(a);
    }
    __syncthreads();
    int row = blockIdx.x * blockDim.x + threadIdx.x;   // (b,c,l,h)
    if (row >= BB*CC*LL*HH) return;
    const float* xp = x + (size_t)row * WW;
    float xr[WW];
#pragma unroll
    for (int w = 0; w < WW; w++) xr[w] = xp[w];
    float2* out = g_xf + (size_t)row * WF;
    for (int k = 0; k < WF; k++) {
        float re = 0.f, im = 0.f;
#pragma unroll
        for (int w = 0; w < WW; w++) {
            int t = (w*k) & 31;
            re += xr[w]*tc[t];
            im -= xr[w]*ts[t];
        }
        out[k] = make_float2(re, im);
    }
}

// ---------------- stage 1: complex scan over L ----------------
__global__ void k_scan() {
    int i = blockIdx.x * blockDim.x + threadIdx.x;     // (b,c,h,k)
    if (i >= BB*CC*HH*WF) return;
    int k = i % WF;
    int h = (i / WF) % HH;
    int c = (i / (WF*HH)) % CC;
    int b =  i / (WF*HH*CC);
    size_t xfb = ((((size_t)b*CC + c)*LL)*HH + h)*WF + k;
    const size_t xstr = (size_t)HH*WF;
    size_t ab = ((size_t)b*LL*CC + c)*WF + k;
    const size_t astr = (size_t)CC*WF;
    float2 s = make_float2(0.f, 0.f);
    for (int l = 0; l < LL; l++) {
        float2 a = g_A[ab + (size_t)l*astr];
        float2 u = g_xf[xfb + (size_t)l*xstr];
        float re = a.x*s.x - a.y*s.y + u.x;
        float im = a.x*s.y + a.y*s.x + u.y;
        s = make_float2(re, im);
        g_xf[xfb + (size_t)l*xstr] = s;
    }
}

// ---------------- stage 1: irfft -> xt channels-last ----------------
__global__ void k_irfft() {
    __shared__ float tc[32], ts[32];
    if (threadIdx.x < 32) {
        float a = TWO_PI_32 * (float)threadIdx.x;
        tc[threadIdx.x] = cosf(a);
        ts[threadIdx.x] = sinf(a);
    }
    __syncthreads();
    int i = blockIdx.x * blockDim.x + threadIdx.x;     // (b,l,h,c)
    if (i >= BB*LL*HH*CC) return;
    int c = i & 127;
    int h = (i >> 7) & 31;
    int l = (i >> 12) & 31;
    int b =  i >> 17;
    const float2* st = g_xf + ((((size_t)b*CC + c)*LL + l)*HH + h)*WF;
    float2 S[WF];
#pragma unroll
    for (int k = 0; k < WF; k++) S[k] = st[k];
    int bn = b*LL + l;
    float* out = g_xt + ((size_t)bn*NP + h*WW)*CC + c;
    for (int w = 0; w < WW; w++) {
        float v = S[0].x + ((w & 1) ? -S[16].x : S[16].x);
#pragma unroll
        for (int k = 1; k < 16; k++) {
            int t = (w*k) & 31;
            v += 2.f*(S[k].x*tc[t] - S[k].y*ts[t]);
        }
        out[(size_t)w*CC] = v * INV32;
    }
}

// ---------------- LayerNorm over C ----------------
__global__ void k_ln(const float* __restrict__ g, const float* __restrict__ b) {
    int lane = threadIdx.x & 31, wid = threadIdx.x >> 5;
    int r = blockIdx.x*8 + wid;
    float4 v = ((const float4*)(g_xt + (size_t)r*CC))[lane];
    float s = v.x + v.y + v.z + v.w;
#pragma unroll
    for (int o = 16; o; o >>= 1) s += __shfl_xor_sync(0xffffffffu, s, o);
    float mu = s * (1.f/128.f);
    float dx = v.x-mu, dy = v.y-mu, dz = v.z-mu, dw = v.w-mu;
    float q = dx*dx + dy*dy + dz*dz + dw*dw;
#pragma unroll
    for (int o = 16; o; o >>= 1) q += __shfl_xor_sync(0xffffffffu, q, o);
    float rstd = rsqrtf(q*(1.f/128.f) + 1e-5f);
    float4 g4 = ((const float4*)g)[lane];
    float4 b4 = ((const float4*)b)[lane];
    float4 o4;
    o4.x = dx*rstd*g4.x + b4.x;
    o4.y = dy*rstd*g4.y + b4.y;
    o4.z = dz*rstd*g4.z + b4.z;
    o4.w = dw*rstd*g4.w + b4.w;
    ((float4*)(g_xn + (size_t)r*CC))[lane] = o4;
}

// ---------------- tf32 tensor-core GEMM: C[M,N] (=/+=) A[M,K]*(B - subI*I)[N,K]^T (+bias) ----
__global__ void k_gemm_tc(const float* __restrict__ A, const float* __restrict__ B,
                          const float* __restrict__ bias, float* __restrict__ C,
                          int M, int N, int K, int accum, int subI) {
    __shared__ unsigned As[64*36];
    __shared__ unsigned Bs[64*36];
    int bm = blockIdx.y << 6, bn = blockIdx.x << 6;
    int warp = threadIdx.x >> 5, lane = threadIdx.x & 31;
    int lr = lane >> 2, lc = lane & 3;
    float acc[8][4];
#pragma unroll
    for (int nf = 0; nf < 8; nf++)
#pragma unroll
        for (int j = 0; j < 4; j++) acc[nf][j] = 0.f;

    for (int k0 = 0; k0 < K; k0 += 32) {
        __syncthreads();
#pragma unroll
        for (int i = 0; i < 4; i++) {
            int slot = threadIdx.x + i*128;     // 512 slots = 64 rows x 8 segs
            int m = slot >> 3, seg = (slot & 7) << 2;
            float4 a4 = *(const float4*)(A + (size_t)(bm+m)*K + k0 + seg);
            uint4 au = make_uint4(f2tf32(a4.x), f2tf32(a4.y), f2tf32(a4.z), f2tf32(a4.w));
            *(uint4*)&As[m*36 + seg] = au;
            float4 b4 = *(const float4*)(B + (size_t)(bn+m)*K + k0 + seg);
            if (subI) {
                int row = bn + m, col = k0 + seg;
                if (row == col    ) b4.x -= 1.f;
                if (row == col + 1) b4.y -= 1.f;
                if (row == col + 2) b4.z -= 1.f;
                if (row == col + 3) b4.w -= 1.f;
            }
            uint4 bu = make_uint4(f2tf32(b4.x), f2tf32(b4.y), f2tf32(b4.z), f2tf32(b4.w));
            *(uint4*)&Bs[m*36 + seg] = bu;
        }
        __syncthreads();
#pragma unroll
        for (int ks = 0; ks < 4; ks++) {
            unsigned a[4];
            int am = warp*16;
            a[0] = As[(am+lr  )*36 + ks*8 + lc];
            a[1] = As[(am+lr+8)*36 + ks*8 + lc];
            a[2] = As[(am+lr  )*36 + ks*8 + lc + 4];
            a[3] = As[(am+lr+8)*36 + ks*8 + lc + 4];
#pragma unroll
            for (int nf = 0; nf < 8; nf++) {
                unsigned b[2];
                b[0] = Bs[(nf*8+lr)*36 + ks*8 + lc];
                b[1] = Bs[(nf*8+lr)*36 + ks*8 + lc + 4];
                mma_tf32(acc[nf], a, b);
            }
        }
    }
#pragma unroll
    for (int nf = 0; nf < 8; nf++) {
        int col = bn + nf*8 + lc*2;
        float b0 = bias ? bias[col] : 0.f;
        float b1 = bias ? bias[col+1] : 0.f;
        int row = bm + warp*16 + lr;
        float2* p = (float2*)(C + (size_t)row*N + col);
        float2 v = make_float2(acc[nf][0]+b0, acc[nf][1]+b1);
        if (accum) { float2 o = *p; v.x += o.x; v.y += o.y; }
        *p = v;
        row += 8;
        p = (float2*)(C + (size_t)row*N + col);
        v = make_float2(acc[nf][2]+b0, acc[nf][3]+b1);
        if (accum) { float2 o = *p; v.x += o.x; v.y += o.y; }
        *p = v;
    }
}

// ---------------- flash attention: tf32 QK + fp16 PV, no-max softmax ------------
// Logits are provably tiny (|s| < ~1), so fixed-zero max is safe; exp2 with
// log2(e) folded into Q scale makes softmax exactly e-based.
__global__ void k_fattn() {
    __shared__ unsigned Ksu[64][20];        // K chunk, tf32 bits, padded
    __shared__ __half   Vt[16][72];         // V chunk transposed [d][key], padded
    int blk = blockIdx.x;                   // qt + 16*(head + 8*bn)
    int qt = blk & 15, head = (blk >> 4) & 7, bn = blk >> 7;
    int warp = threadIdx.x >> 5, lane = threadIdx.x & 31;
    int lr = lane >> 2, lc = lane & 3;
    int q0 = qt*64 + warp*16;
    const float* qbase = g_qkv + (size_t)bn*NP*384 + head*16;

    unsigned Qa[2][4];
#pragma unroll
    for (int kf = 0; kf < 2; kf++) {
        int col = kf*8 + lc;
        Qa[kf][0] = f2tf32(QK_SCALE * qbase[(size_t)(q0+lr  )*384 + col]);
        Qa[kf][1] = f2tf32(QK_SCALE * qbase[(size_t)(q0+lr+8)*384 + col]);
        Qa[kf][2] = f2tf32(QK_SCALE * qbase[(size_t)(q0+lr  )*384 + col+4]);
        Qa[kf][3] = f2tf32(QK_SCALE * qbase[(size_t)(q0+lr+8)*384 + col+4]);
    }

    float l0 = 0.f, l1 = 0.f;
    float Oa[2][4];
#pragma unroll
    for (int dn = 0; dn < 2; dn++)
#pragma unroll
        for (int j = 0; j < 4; j++) Oa[dn][j] = 0.f;

    for (int c0 = 0; c0 < NP; c0 += 64) {
        __syncthreads();
#pragma unroll
        for (int i = 0; i < 2; i++) {
            int slot = threadIdx.x + i*128;           // 256 slots = 64 keys x 4 segs
            int key = slot >> 2, seg = (slot & 3) << 2;
            const float* kp = qbase + (size_t)(c0 + key)*384 + 128 + seg;
            float4 kv = *(const float4*)kp;
            Ksu[key][seg+0] = f2tf32(kv.x);
            Ksu[key][seg+1] = f2tf32(kv.y);
            Ksu[key][seg+2] = f2tf32(kv.z);
            Ksu[key][seg+3] = f2tf32(kv.w);
            float4 vv = *(const float4*)(kp + 128);
            Vt[seg+0][key] = __float2half(vv.x);
            Vt[seg+1][key] = __float2half(vv.y);
            Vt[seg+2][key] = __float2half(vv.z);
            Vt[seg+3][key] = __float2half(vv.w);
        }
        __syncthreads();

        // S = Q K^T  (already in log2 domain)
        float S[8][4];
#pragma unroll
        for (int nf = 0; nf < 8; nf++) {
#pragma unroll
            for (int j = 0; j < 4; j++) S[nf][j] = 0.f;
#pragma unroll
            for (int kf = 0; kf < 2; kf++) {
                unsigned b[2];
                b[0] = Ksu[nf*8 + lr][kf*8 + lc];
                b[1] = Ksu[nf*8 + lr][kf*8 + lc + 4];
                mma_tf32(S[nf], Qa[kf], b);
            }
        }

        // p = 2^s, accumulate row sums (no running max needed)
#pragma unroll
        for (int nf = 0; nf < 8; nf++) {
            S[nf][0] = ex2a(S[nf][0]);
            S[nf][1] = ex2a(S[nf][1]);
            S[nf][2] = ex2a(S[nf][2]);
            S[nf][3] = ex2a(S[nf][3]);
            l0 += S[nf][0] + S[nf][1];
            l1 += S[nf][2] + S[nf][3];
        }

        // P (fp16) @ V
#pragma unroll
        for (int j = 0; j < 4; j++) {
            unsigned a[4];
            a[0] = packh2(S[2*j  ][0], S[2*j  ][1]);
            a[1] = packh2(S[2*j  ][2], S[2*j  ][3]);
            a[2] = packh2(S[2*j+1][0], S[2*j+1][1]);
            a[3] = packh2(S[2*j+1][2], S[2*j+1][3]);
#pragma unroll
            for (int dn = 0; dn < 2; dn++) {
                unsigned b[2];
                b[0] = *(const unsigned*)&Vt[dn*8 + lr][j*16 + lc*2];
                b[1] = *(const unsigned*)&Vt[dn*8 + lr][j*16 + lc*2 + 8];
                mma_f16(Oa[dn], a, b);
            }
        }
    }

#pragma unroll
    for (int o = 1; o <= 2; o <<= 1) {
        l0 += __shfl_xor_sync(0xffffffffu, l0, o);
        l1 += __shfl_xor_sync(0xffffffffu, l1, o);
    }
    float inv0 = 1.f / l0, inv1 = 1.f / l1;
    float* ob = g_ao + (size_t)bn*NP*CC + head*16;
#pragma unroll
    for (int dn = 0; dn < 2; dn++) {
        int col = dn*8 + lc*2;
        *(float2*)(ob + (size_t)(q0+lr  )*CC + col) = make_float2(Oa[dn][0]*inv0, Oa[dn][1]*inv0);
        *(float2*)(ob + (size_t)(q0+lr+8)*CC + col) = make_float2(Oa[dn][2]*inv1, Oa[dn][3]*inv1);
    }
}

// ---------------- GroupNorm stats (optionally gated input) ----------------
__global__ void k_gnstats(const float* __restrict__ X, const float* __restrict__ gate,
                          float2* __restrict__ stats) {
    __shared__ float sh[256], sh2[256];
    int bn = blockIdx.x >> 2, g = blockIdx.x & 3;
    float s = 0.f, q = 0.f;
    const float* base = X + (size_t)bn*NP*CC + g*32;
    for (int e = threadIdx.x; e < 32768; e += 256) {
        int n = e >> 5, cc = e & 31;
        float v = base[(size_t)n*CC + cc];
        if (gate) v *= gate[bn*NP + n];
        s += v; q += v*v;
    }
    sh[threadIdx.x] = s; sh2[threadIdx.x] = q;
    __syncthreads();
    for (int o = 128; o; o >>= 1) {
        if (threadIdx.x < o) { sh[threadIdx.x] += sh[threadIdx.x+o]; sh2[threadIdx.x] += sh2[threadIdx.x+o]; }
        __syncthreads();
    }
    if (threadIdx.x == 0) {
        float mu = sh[0] * (1.f/32768.f);
        float var = sh2[0] * (1.f/32768.f) - mu*mu;
        stats[blockIdx.x] = make_float2(mu, rsqrtf(var + 1e-5f));
    }
}

__global__ void k_gnapply(const float* __restrict__ g, const float* __restrict__ b) {
    int i = blockIdx.x * blockDim.x + threadIdx.x;
    if (i >= BNN*NP*CC) return;
    int c = i & 127;
    int bn = i >> 17;
    float2 st = g_st1[bn*4 + (c >> 5)];
    g_y2n[i] = (g_xt[i] - st.x)*st.y*g[c] + b[c];
}

__global__ void k_pool() {
    int i = blockIdx.x * blockDim.x + threadIdx.x;     // (bn,pc,c)
    if (i >= BNN*NPC*CC) return;
    int c = i & 127;
    int pc = (i >> 7) & 255;
    int bn = i >> 15;
    int hp = pc >> 4, wp = pc & 15;
    size_t base = ((size_t)bn*NP + hp*64 + wp*2)*CC + c;
    g_gp[i] = 0.25f*(g_y2n[base] + g_y2n[base + CC] + g_y2n[base + 32*CC] + g_y2n[base + 33*CC]);
}

__global__ void k_gate(const float* __restrict__ w_psi, const float* __restrict__ b_psi) {
    int lane = threadIdx.x & 31, wid = threadIdx.x >> 5;
    int p = blockIdx.x*8 + wid;                        // 65536 pixels
    int bn = p >> 10, n = p & 1023;
    int h = n >> 5, w = n & 31;
    int pc = (h >> 1)*16 + (w >> 1);
    float4 gv = ((const float4*)(g_gg + ((size_t)bn*NPC + pc)*CC))[lane];
    float4 lv = ((const float4*)(g_l  + (size_t)p*CC))[lane];
    float4 wp = ((const float4*)w_psi)[lane];
    float s = fmaxf(gv.x+lv.x, 0.f)*wp.x + fmaxf(gv.y+lv.y, 0.f)*wp.y
            + fmaxf(gv.z+lv.z, 0.f)*wp.z + fmaxf(gv.w+lv.w, 0.f)*wp.w;
#pragma unroll
    for (int o = 16; o; o >>= 1) s += __shfl_xor_sync(0xffffffffu, s, o);
    if (lane == 0) g_gate[p] = 1.f/(1.f + expf(-(s + b_psi[0])));
}

// gated GN2 + transpose to channels-first, coalesced both ways via smem tile
__global__ void k_y3t(const float* __restrict__ g, const float* __restrict__ b) {
    __shared__ float tile[128][33];
    __shared__ float gts[32];
    int bn = blockIdx.x >> 5, h = blockIdx.x & 31;
    if (threadIdx.x < 32) gts[threadIdx.x] = g_gate[bn*NP + h*32 + threadIdx.x];
    __syncthreads();
    const float* src = g_y2n + ((size_t)bn*NP + h*32)*CC;
#pragma unroll
    for (int it = 0; it < 16; it++) {
        int idx = threadIdx.x + it*256;
        int w = idx >> 7, c = idx & 127;
        tile[c][w] = src[(size_t)w*CC + c] * gts[w];
    }
    __syncthreads();
    float* dst = g_y3 + (size_t)bn*CC*NP + h*32;
#pragma unroll
    for (int it = 0; it < 16; it++) {
        int idx = threadIdx.x + it*256;
        int c = idx >> 5, w = idx & 31;
        float2 st = g_st2[bn*4 + (c >> 5)];
        dst[(size_t)c*NP + w] = (tile[c][w] - st.x)*st.y*g[c] + b[c];
    }
}

// ---------------- spectral: partial rfft along W ----------------
__global__ void k_sa() {
    __shared__ float tc[32], ts[32];
    if (threadIdx.x < 32) {
        float a = TWO_PI_32 * (float)threadIdx.x;
        tc[threadIdx.x] = cosf(a);
        ts[threadIdx.x] = sinf(a);
    }
    __syncthreads();
    int row = blockIdx.x * blockDim.x + threadIdx.x;   // (bn,c,h)
    if (row >= BNN*CC*HH) return;
    const float* yp = g_y3 + (size_t)row * WW;
    float xr[WW];
#pragma unroll
    for (int w = 0; w < WW; w++) xr[w] = yp[w];
    float2* out = g_Xw + (size_t)row * MW;
    for (int kw = 0; kw < MW; kw++) {
        float re = 0.f, im = 0.f;
#pragma unroll
        for (int w = 0; w < WW; w++) {
            int t = (w*kw) & 31;
            re += xr[w]*tc[t];
            im -= xr[w]*ts[t];
        }
        out[kw] = make_float2(re, im);
    }
}

// partial DFT along H (modes 0..11) -> z rows for mix GEMM
__global__ void k_sb() {
    __shared__ float2 Xs[HH*MW];
    __shared__ float tc[32], ts[32];
    if (threadIdx.x < 32) {
        float a = TWO_PI_32 * (float)threadIdx.x;
        tc[threadIdx.x] = cosf(a);
        ts[threadIdx.x] = sinf(a);
    }
    int bc = blockIdx.x;                               // (bn,c)
    int bn = bc >> 7, c = bc & 127;
    const float2* src = g_Xw + (size_t)bc * HH * MW;
    for (int e = threadIdx.x; e < HH*MW; e += 192) Xs[e] = src[e];
    __syncthreads();
    if (threadIdx.x < 144) {
        int kh = threadIdx.x / 12, kw = threadIdx.x % 12;
        float re = 0.f, im = 0.f;
#pragma unroll
        for (int h = 0; h < HH; h++) {
            int t = (kh*h) & 31;
            float2 v = Xs[h*MW + kw];
            re += v.x*tc[t] + v.y*ts[t];
            im += v.y*tc[t] - v.x*ts[t];
        }
        size_t rowz = (size_t)(bn*144 + threadIdx.x) * 256;
        g_zin[rowz + c]       = re * INV32;
        g_zin[rowz + 128 + c] = im * INV32;
    }
    __syncthreads();
}

// inverse DFT along H of delta modes (zout IS the delta now)
__global__ void k_sd() {
    __shared__ float2 D[144];
    __shared__ float tc[32], ts[32];
    if (threadIdx.x < 32) {
        float a = TWO_PI_32 * (float)threadIdx.x;
        tc[threadIdx.x] = cosf(a);
        ts[threadIdx.x] = sinf(a);
    }
    int bc = blockIdx.x;                               // (bn,c)
    int bn = bc >> 7, c = bc & 127;
    if (threadIdx.x < 144) {
        size_t rowz = (size_t)(bn*144 + threadIdx.x) * 256;
        D[threadIdx.x] = make_float2(g_zout[rowz + c], g_zout[rowz + 128 + c]);
    }
    __syncthreads();
    int h = threadIdx.x / 12, kw = threadIdx.x % 12;   // 384 threads
    float re = 0.f, im = 0.f;
#pragma unroll
    for (int kh = 0; kh < MH; kh++) {
        int t = (kh*h) & 31;
        float2 d = D[kh*12 + kw];
        re += d.x*tc[t] - d.y*ts[t];
        im += d.x*ts[t] + d.y*tc[t];
    }
    g_tH[(size_t)bc*HH*MW + threadIdx.x] = make_float2(re*INV_SQRT32, im*INV_SQRT32);
}

// final c2r along W of delta + out = 2*y3 + ys, output transpose
__global__ void k_se(float* __restrict__ out) {
    __shared__ float tc[32], ts[32];
    if (threadIdx.x < 32) {
        float a = TWO_PI_32 * (float)threadIdx.x;
        tc[threadIdx.x] = cosf(a);
        ts[threadIdx.x] = sinf(a);
    }
    __syncthreads();
    int row = blockIdx.x * blockDim.x + threadIdx.x;   // (bn,c,h)
    if (row >= BNN*CC*HH) return;
    int h = row & 31;
    int c = (row >> 5) & 127;
    int bn = row >> 12;
    float2 T[MW];
    const float2* tp = g_tH + (size_t)row * MW;
#pragma unroll
    for (int kw = 0; kw < MW; kw++) T[kw] = tp[kw];
    const float* yp = g_y3 + (size_t)row * WW;
    int b = bn >> 5, l = bn & 31;
    float* op = out + (((((size_t)b*CC + c)*LL + l)*HH + h)) * WW;
    for (int w = 0; w < WW; w++) {
        float ys = T[0].x;
#pragma unroll
        for (int kw = 1; kw < MW; kw++) {
            int t = (kw*w) & 31;
            ys += 2.f*(T[kw].x*tc[t] - T[kw].y*ts[t]);
        }
        op[w] = 2.f*yp[w] + ys*INV_SQRT32;
    }
}

// ---------------- launch ----------------
static float* symaddr_f(const void* sym) { void* p = 0; cudaGetSymbolAddress(&p, sym); return (float*)p; }

extern "C" void kernel_launch(void* const* d_in, const int* in_sizes, int n_in,
                              void* d_out, int out_size) {
    const float* x      = (const float*)d_in[0];
    const float* dt     = (const float*)d_in[1];
    const float* nu     = (const float*)d_in[2];
    const float* theta  = (const float*)d_in[3];
    const float* ln_g   = (const float*)d_in[4];
    const float* ln_b   = (const float*)d_in[5];
    const float* w_qkv  = (const float*)d_in[6];
    const float* w_proj = (const float*)d_in[7];
    const float* b_proj = (const float*)d_in[8];
    const float* gn_g   = (const float*)d_in[9];
    const float* gn_b   = (const float*)d_in[10];
    const float* w_g    = (const float*)d_in[11];
    const float* w_l    = (const float*)d_in[12];
    const float* w_psi  = (const float*)d_in[13];
    const float* b_psi  = (const float*)d_in[14];
    const float* gate_g = (const float*)d_in[15];
    const float* gate_b = (const float*)d_in[16];
    const float* mix_w  = (const float*)d_in[17];
    const float* mix_b  = (const float*)d_in[18];
    float* out = (float*)d_out;

    float* p_xt  = symaddr_f(g_xt);
    float* p_xn  = symaddr_f(g_xn);
    float* p_qkv = symaddr_f(g_qkv);
    float* p_ao  = symaddr_f(g_ao);
    float* p_y2n = symaddr_f(g_y2n);
    float* p_gp  = symaddr_f(g_gp);
    float* p_gg  = symaddr_f(g_gg);
    float* p_l   = symaddr_f(g_l);
    float* p_zin = symaddr_f(g_zin);
    float* p_zout= symaddr_f(g_zout);
    float2* p_st1 = (float2*)symaddr_f(g_st1);
    float2* p_st2 = (float2*)symaddr_f(g_st2);
    float* p_gate = symaddr_f(g_gate);

    // stage 1
    k_precompA<<<(BB*LL*CC*WF + 255)/256, 256>>>(dt, nu, theta);
    k_rfft<<<(BB*CC*LL*HH + 127)/128, 128>>>(x);
    k_scan<<<(BB*CC*HH*WF + 255)/256, 256>>>();
    k_irfft<<<(BB*LL*HH*CC)/256, 256>>>();
    // stage 2: LN + attention + proj residual
    k_ln<<<(BNN*NP)/8, 256>>>(ln_g, ln_b);
    k_gemm_tc<<<dim3(384/64, (BNN*NP)/64), 128>>>(p_xn, w_qkv, (const float*)0, p_qkv, BNN*NP, 384, CC, 0, 0);
    k_fattn<<<BNN*8*16, 128>>>();
    k_gemm_tc<<<dim3(CC/64, (BNN*NP)/64), 128>>>(p_ao, w_proj, b_proj, p_xt, BNN*NP, CC, CC, 1, 0);
    // stage 3: GN1, gating, GN2
    k_gnstats<<<BNN*4, 256>>>(p_xt, (const float*)0, p_st1);
    k_gnapply<<<(BNN*NP*CC)/256, 256>>>(gn_g, gn_b);
    k_pool<<<(BNN*NPC*CC)/256, 256>>>();
    k_gemm_tc<<<dim3(CC/64, (BNN*NPC)/64), 128>>>(p_gp, w_g, (const float*)0, p_gg, BNN*NPC, CC, CC, 0, 0);
    k_gemm_tc<<<dim3(CC/64, (BNN*NP)/64), 128>>>(p_y2n, w_l, (const float*)0, p_l, BNN*NP, CC, CC, 0, 0);
    k_gate<<<(BNN*NP)/8, 256>>>(w_psi, b_psi);
    k_gnstats<<<BNN*4, 256>>>(p_y2n, p_gate, p_st2);
    k_y3t<<<BNN*HH, 256>>>(gate_g, gate_b);
    // stage 4: spectral delta; mix GEMM computes delta = z(mix_w - I)^T + mix_b on TC
    k_sa<<<(BNN*CC*HH)/256, 256>>>();
    k_sb<<<BNN*CC, 192>>>();
    k_gemm_tc<<<dim3(256/64, (BNN*144)/64), 128>>>(p_zin, mix_w, mix_b, p_zout, BNN*144, 256, 256, 0, 1);
    k_sd<<<BNN*CC, 384>>>();
    k_se<<<(BNN*CC*HH)/256, 256>>>(out);
}

// round 6
// speedup vs baseline: 2.6697x; 1.1021x over previous
#include <cuda_runtime.h>
#include <cuda_fp16.h>
#include <math.h>

// ---------------- shapes ----------------
#define BB 2
#define CC 128
#define LL 32
#define HH 32
#define WW 32
#define WF 17
#define BNN 64
#define NP 1024
#define NPC 256
#define MH 12
#define MW 12

#define TWO_PI_32 0.19634954084936207f
#define INV32 0.03125f
#define INV_SQRT32 0.17677669529663687f
#define QK_SCALE 0.36067376022224085f    // 0.25 * log2(e)

// ---------------- device scratch ----------------
__device__ float2 g_xf[BB*CC*LL*HH*WF];
__device__ float2 g_A [BB*LL*CC*WF];
__device__ float  g_xt [BNN*NP*CC];
__device__ float  g_xn [BNN*NP*CC];
__device__ __half g_qkvh[BNN*NP*384];
__device__ float  g_ao [BNN*NP*CC];
__device__ float  g_y2n[BNN*NP*CC];
__device__ float  g_gp [BNN*NPC*CC];
__device__ float  g_gg [BNN*NPC*CC];
__device__ float  g_l  [BNN*NP*CC];
__device__ float  g_gate[BNN*NP];
__device__ float  g_y3 [BNN*CC*NP];
__device__ float2 g_Xw [BNN*CC*HH*MW];
__device__ float  g_zin [BNN*144*256];
__device__ float  g_zout[BNN*144*256];
__device__ float2 g_tH [BNN*CC*HH*MW];
__device__ float2 g_st1[BNN*4];
__device__ float2 g_st2[BNN*4];

// ---------------- mma helpers ----------------
__device__ __forceinline__ unsigned f2tf32(float f) {
    unsigned r; asm("cvt.rna.tf32.f32 %0, %1;" : "=r"(r) : "f"(f)); return r;
}
__device__ __forceinline__ void mma_tf32(float* c, const unsigned* a, const unsigned* b) {
    asm("mma.sync.aligned.m16n8k8.row.col.f32.tf32.tf32.f32 "
        "{%0,%1,%2,%3}, {%4,%5,%6,%7}, {%8,%9}, {%0,%1,%2,%3};"
        : "+f"(c[0]), "+f"(c[1]), "+f"(c[2]), "+f"(c[3])
        : "r"(a[0]), "r"(a[1]), "r"(a[2]), "r"(a[3]), "r"(b[0]), "r"(b[1]));
}
__device__ __forceinline__ void mma_f16(float* c, const unsigned* a, const unsigned* b) {
    asm("mma.sync.aligned.m16n8k16.row.col.f32.f16.f16.f32 "
        "{%0,%1,%2,%3}, {%4,%5,%6,%7}, {%8,%9}, {%0,%1,%2,%3};"
        : "+f"(c[0]), "+f"(c[1]), "+f"(c[2]), "+f"(c[3])
        : "r"(a[0]), "r"(a[1]), "r"(a[2]), "r"(a[3]), "r"(b[0]), "r"(b[1]));
}
__device__ __forceinline__ unsigned packh2(float a, float b) {
    __half2 h = __floats2half2_rn(a, b);
    return *(unsigned*)&h;
}
__device__ __forceinline__ float ex2a(float x) {
    float r; asm("ex2.approx.f32 %0, %1;" : "=f"(r) : "f"(fminf(x, 80.f))); return r;
}

// ---------------- stage 1: A precompute ----------------
__global__ void k_precompA(const float* __restrict__ dt, const float* __restrict__ nu,
                           const float* __restrict__ th) {
    int i = blockIdx.x * blockDim.x + threadIdx.x;
    if (i >= BB*LL*CC*WF) return;
    int k = i % WF;
    int c = (i / WF) % CC;
    int l = (i / (WF*CC)) % LL;
    int b =  i / (WF*CC*LL);
    float d  = dt[b*LL + l];
    float e  = expf(-nu[c*WF + k] * d);
    float si, co;
    sincosf(th[c*WF + k] * d, &si, &co);
    g_A[i] = make_float2(e*co, e*si);
}

// ---------------- stage 1: rfft along W ----------------
__global__ void k_rfft(const float* __restrict__ x) {
    __shared__ float tc[32], ts[32];
    if (threadIdx.x < 32) {
        float a = TWO_PI_32 * (float)threadIdx.x;
        tc[threadIdx.x] = cosf(a);
        ts[threadIdx.x] = sinf(a);
    }
    __syncthreads();
    int row = blockIdx.x * blockDim.x + threadIdx.x;   // (b,c,l,h)
    if (row >= BB*CC*LL*HH) return;
    const float* xp = x + (size_t)row * WW;
    float xr[WW];
#pragma unroll
    for (int w = 0; w < WW; w++) xr[w] = xp[w];
    float2* out = g_xf + (size_t)row * WF;
    for (int k = 0; k < WF; k++) {
        float re = 0.f, im = 0.f;
#pragma unroll
        for (int w = 0; w < WW; w++) {
            int t = (w*k) & 31;
            re += xr[w]*tc[t];
            im -= xr[w]*ts[t];
        }
        out[k] = make_float2(re, im);
    }
}

// ---------------- stage 1: complex scan over L ----------------
__global__ void k_scan() {
    int i = blockIdx.x * blockDim.x + threadIdx.x;     // (b,c,h,k)
    if (i >= BB*CC*HH*WF) return;
    int k = i % WF;
    int h = (i / WF) % HH;
    int c = (i / (WF*HH)) % CC;
    int b =  i / (WF*HH*CC);
    size_t xfb = ((((size_t)b*CC + c)*LL)*HH + h)*WF + k;
    const size_t xstr = (size_t)HH*WF;
    size_t ab = ((size_t)b*LL*CC + c)*WF + k;
    const size_t astr = (size_t)CC*WF;
    float2 s = make_float2(0.f, 0.f);
    for (int l = 0; l < LL; l++) {
        float2 a = g_A[ab + (size_t)l*astr];
        float2 u = g_xf[xfb + (size_t)l*xstr];
        float re = a.x*s.x - a.y*s.y + u.x;
        float im = a.x*s.y + a.y*s.x + u.y;
        s = make_float2(re, im);
        g_xf[xfb + (size_t)l*xstr] = s;
    }
}

// ---------------- stage 1: irfft -> xt channels-last (parity split) -------------
__global__ void k_irfft() {
    __shared__ float tc[32], ts[32];
    if (threadIdx.x < 32) {
        float a = TWO_PI_32 * (float)threadIdx.x;
        tc[threadIdx.x] = cosf(a);
        ts[threadIdx.x] = sinf(a);
    }
    __syncthreads();
    int i = blockIdx.x * blockDim.x + threadIdx.x;     // (b,l,h,c)
    if (i >= BB*LL*HH*CC) return;
    int c = i & 127;
    int h = (i >> 7) & 31;
    int l = (i >> 12) & 31;
    int b =  i >> 17;
    const float2* st = g_xf + ((((size_t)b*CC + c)*LL + l)*HH + h)*WF;
    float2 S[WF];
#pragma unroll
    for (int k = 0; k < WF; k++) S[k] = st[k];
    int bn = b*LL + l;
    float* out = g_xt + ((size_t)bn*NP + h*WW)*CC + c;
    // c_k(w+16) = (-1)^k c_k(w): compute even/odd-k partial sums for w<16
    for (int w = 0; w < 16; w++) {
        float se = S[0].x + ((w & 1) ? -S[16].x : S[16].x);
        float so = 0.f;
#pragma unroll
        for (int k = 1; k < 16; k++) {
            int t = (w*k) & 31;
            float term = 2.f*(S[k].x*tc[t] - S[k].y*ts[t]);
            if (k & 1) so += term; else se += term;
        }
        out[(size_t)w*CC]      = (se + so) * INV32;
        out[(size_t)(w+16)*CC] = (se - so) * INV32;
    }
}

// ---------------- LayerNorm over C ----------------
__global__ void k_ln(const float* __restrict__ g, const float* __restrict__ b) {
    int lane = threadIdx.x & 31, wid = threadIdx.x >> 5;
    int r = blockIdx.x*8 + wid;
    float4 v = ((const float4*)(g_xt + (size_t)r*CC))[lane];
    float s = v.x + v.y + v.z + v.w;
#pragma unroll
    for (int o = 16; o; o >>= 1) s += __shfl_xor_sync(0xffffffffu, s, o);
    float mu = s * (1.f/128.f);
    float dx = v.x-mu, dy = v.y-mu, dz = v.z-mu, dw = v.w-mu;
    float q = dx*dx + dy*dy + dz*dz + dw*dw;
#pragma unroll
    for (int o = 16; o; o >>= 1) q += __shfl_xor_sync(0xffffffffu, q, o);
    float rstd = rsqrtf(q*(1.f/128.f) + 1e-5f);
    float4 g4 = ((const float4*)g)[lane];
    float4 b4 = ((const float4*)b)[lane];
    float4 o4;
    o4.x = dx*rstd*g4.x + b4.x;
    o4.y = dy*rstd*g4.y + b4.y;
    o4.z = dz*rstd*g4.z + b4.z;
    o4.w = dw*rstd*g4.w + b4.w;
    ((float4*)(g_xn + (size_t)r*CC))[lane] = o4;
}

// ---------------- tf32 TC GEMM, fp32 out: C = A*(B - subI*I)^T (+bias) ----------
__global__ void k_gemm_tc(const float* __restrict__ A, const float* __restrict__ B,
                          const float* __restrict__ bias, float* __restrict__ C,
                          int M, int N, int K, int accum, int subI) {
    __shared__ unsigned As[64*36];
    __shared__ unsigned Bs[64*36];
    int bm = blockIdx.y << 6, bn = blockIdx.x << 6;
    int warp = threadIdx.x >> 5, lane = threadIdx.x & 31;
    int lr = lane >> 2, lc = lane & 3;
    float acc[8][4];
#pragma unroll
    for (int nf = 0; nf < 8; nf++)
#pragma unroll
        for (int j = 0; j < 4; j++) acc[nf][j] = 0.f;

    for (int k0 = 0; k0 < K; k0 += 32) {
        __syncthreads();
#pragma unroll
        for (int i = 0; i < 4; i++) {
            int slot = threadIdx.x + i*128;
            int m = slot >> 3, seg = (slot & 7) << 2;
            float4 a4 = *(const float4*)(A + (size_t)(bm+m)*K + k0 + seg);
            uint4 au = make_uint4(f2tf32(a4.x), f2tf32(a4.y), f2tf32(a4.z), f2tf32(a4.w));
            *(uint4*)&As[m*36 + seg] = au;
            float4 b4 = *(const float4*)(B + (size_t)(bn+m)*K + k0 + seg);
            if (subI) {
                int row = bn + m, col = k0 + seg;
                if (row == col    ) b4.x -= 1.f;
                if (row == col + 1) b4.y -= 1.f;
                if (row == col + 2) b4.z -= 1.f;
                if (row == col + 3) b4.w -= 1.f;
            }
            uint4 bu = make_uint4(f2tf32(b4.x), f2tf32(b4.y), f2tf32(b4.z), f2tf32(b4.w));
            *(uint4*)&Bs[m*36 + seg] = bu;
        }
        __syncthreads();
#pragma unroll
        for (int ks = 0; ks < 4; ks++) {
            unsigned a[4];
            int am = warp*16;
            a[0] = As[(am+lr  )*36 + ks*8 + lc];
            a[1] = As[(am+lr+8)*36 + ks*8 + lc];
            a[2] = As[(am+lr  )*36 + ks*8 + lc + 4];
            a[3] = As[(am+lr+8)*36 + ks*8 + lc + 4];
#pragma unroll
            for (int nf = 0; nf < 8; nf++) {
                unsigned b[2];
                b[0] = Bs[(nf*8+lr)*36 + ks*8 + lc];
                b[1] = Bs[(nf*8+lr)*36 + ks*8 + lc + 4];
                mma_tf32(acc[nf], a, b);
            }
        }
    }
#pragma unroll
    for (int nf = 0; nf < 8; nf++) {
        int col = bn + nf*8 + lc*2;
        float b0 = bias ? bias[col] : 0.f;
        float b1 = bias ? bias[col+1] : 0.f;
        int row = bm + warp*16 + lr;
        float2* p = (float2*)(C + (size_t)row*N + col);
        float2 v = make_float2(acc[nf][0]+b0, acc[nf][1]+b1);
        if (accum) { float2 o = *p; v.x += o.x; v.y += o.y; }
        *p = v;
        row += 8;
        p = (float2*)(C + (size_t)row*N + col);
        v = make_float2(acc[nf][2]+b0, acc[nf][3]+b1);
        if (accum) { float2 o = *p; v.x += o.x; v.y += o.y; }
        *p = v;
    }
}

// ---------------- tf32 TC GEMM, fp16 out (qkv); cols<128 scaled by QK_SCALE -----
__global__ void k_gemm_tc_h(const float* __restrict__ A, const float* __restrict__ B,
                            __half* __restrict__ C, int M, int N, int K, int qscale) {
    __shared__ unsigned As[64*36];
    __shared__ unsigned Bs[64*36];
    int bm = blockIdx.y << 6, bn = blockIdx.x << 6;
    int warp = threadIdx.x >> 5, lane = threadIdx.x & 31;
    int lr = lane >> 2, lc = lane & 3;
    float acc[8][4];
#pragma unroll
    for (int nf = 0; nf < 8; nf++)
#pragma unroll
        for (int j = 0; j < 4; j++) acc[nf][j] = 0.f;

    for (int k0 = 0; k0 < K; k0 += 32) {
        __syncthreads();
#pragma unroll
        for (int i = 0; i < 4; i++) {
            int slot = threadIdx.x + i*128;
            int m = slot >> 3, seg = (slot & 7) << 2;
            float4 a4 = *(const float4*)(A + (size_t)(bm+m)*K + k0 + seg);
            *(uint4*)&As[m*36 + seg] = make_uint4(f2tf32(a4.x), f2tf32(a4.y), f2tf32(a4.z), f2tf32(a4.w));
            float4 b4 = *(const float4*)(B + (size_t)(bn+m)*K + k0 + seg);
            *(uint4*)&Bs[m*36 + seg] = make_uint4(f2tf32(b4.x), f2tf32(b4.y), f2tf32(b4.z), f2tf32(b4.w));
        }
        __syncthreads();
#pragma unroll
        for (int ks = 0; ks < 4; ks++) {
            unsigned a[4];
            int am = warp*16;
            a[0] = As[(am+lr  )*36 + ks*8 + lc];
            a[1] = As[(am+lr+8)*36 + ks*8 + lc];
            a[2] = As[(am+lr  )*36 + ks*8 + lc + 4];
            a[3] = As[(am+lr+8)*36 + ks*8 + lc + 4];
#pragma unroll
            for (int nf = 0; nf < 8; nf++) {
                unsigned b[2];
                b[0] = Bs[(nf*8+lr)*36 + ks*8 + lc];
                b[1] = Bs[(nf*8+lr)*36 + ks*8 + lc + 4];
                mma_tf32(acc[nf], a, b);
            }
        }
    }
#pragma unroll
    for (int nf = 0; nf < 8; nf++) {
        int col = bn + nf*8 + lc*2;
        float sc = (qscale && col < 128) ? QK_SCALE : 1.f;
        int row = bm + warp*16 + lr;
        *(__half2*)(C + (size_t)row*N + col) = __floats2half2_rn(acc[nf][0]*sc, acc[nf][1]*sc);
        row += 8;
        *(__half2*)(C + (size_t)row*N + col) = __floats2half2_rn(acc[nf][2]*sc, acc[nf][3]*sc);
    }
}

// ---------------- flash attention: all-fp16 mma, 128-query tiles ----------------
__global__ void k_fattn() {
    __shared__ __half Ks[64][24];           // [key][d], padded to 48B rows
    __shared__ __half Vt[16][72];           // [d][key], padded
    int blk = blockIdx.x;                   // qt + 8*(head + 8*bn)
    int qt = blk & 7, head = (blk >> 3) & 7, bn = blk >> 6;
    int warp = threadIdx.x >> 5, lane = threadIdx.x & 31;
    int lr = lane >> 2, lc = lane & 3;
    int q0 = qt*128 + warp*32;
    const __half* qkb = g_qkvh + (size_t)bn*NP*384 + head*16;

    // Q fragments for 2 m-tiles of 16 rows (Q already scaled by QK_SCALE*)
    unsigned Qa[2][4];
#pragma unroll
    for (int mt = 0; mt < 2; mt++) {
        const __half* qp = qkb + (size_t)(q0 + mt*16)*384;
        Qa[mt][0] = *(const unsigned*)(qp + (size_t)(lr  )*384 + 2*lc);
        Qa[mt][1] = *(const unsigned*)(qp + (size_t)(lr+8)*384 + 2*lc);
        Qa[mt][2] = *(const unsigned*)(qp + (size_t)(lr  )*384 + 2*lc + 8);
        Qa[mt][3] = *(const unsigned*)(qp + (size_t)(lr+8)*384 + 2*lc + 8);
    }

    float lsum[2][2] = {{0.f,0.f},{0.f,0.f}};
    float Oa[2][2][4];
#pragma unroll
    for (int mt = 0; mt < 2; mt++)
#pragma unroll
        for (int dn = 0; dn < 2; dn++)
#pragma unroll
            for (int j = 0; j < 4; j++) Oa[mt][dn][j] = 0.f;

    for (int c0 = 0; c0 < NP; c0 += 64) {
        __syncthreads();
        {
            int key = threadIdx.x >> 1, seg = (threadIdx.x & 1) * 8;
            const __half* kp = qkb + (size_t)(c0 + key)*384 + 128 + seg;
            *(uint4*)&Ks[key][seg] = *(const uint4*)kp;
            uint4 vv = *(const uint4*)(kp + 128);
            __half vh[8];
            *(uint4*)vh = vv;
#pragma unroll
            for (int j = 0; j < 8; j++) Vt[seg + j][key] = vh[j];
        }
        __syncthreads();

        // S = Q K^T for 2 m-tiles x 8 n-frags (fp16 mma, k=16 in one step)
        float S[2][8][4];
#pragma unroll
        for (int mt = 0; mt < 2; mt++)
#pragma unroll
            for (int nf = 0; nf < 8; nf++) {
                S[mt][nf][0] = S[mt][nf][1] = S[mt][nf][2] = S[mt][nf][3] = 0.f;
                unsigned b[2];
                b[0] = *(const unsigned*)&Ks[nf*8 + lr][2*lc];
                b[1] = *(const unsigned*)&Ks[nf*8 + lr][2*lc + 8];
                mma_f16(S[mt][nf], Qa[mt], b);
            }

        // p = 2^s, row sums
#pragma unroll
        for (int mt = 0; mt < 2; mt++)
#pragma unroll
            for (int nf = 0; nf < 8; nf++) {
                S[mt][nf][0] = ex2a(S[mt][nf][0]);
                S[mt][nf][1] = ex2a(S[mt][nf][1]);
                S[mt][nf][2] = ex2a(S[mt][nf][2]);
                S[mt][nf][3] = ex2a(S[mt][nf][3]);
                lsum[mt][0] += S[mt][nf][0] + S[mt][nf][1];
                lsum[mt][1] += S[mt][nf][2] + S[mt][nf][3];
            }

        // P @ V
#pragma unroll
        for (int mt = 0; mt < 2; mt++)
#pragma unroll
            for (int j = 0; j < 4; j++) {
                unsigned a[4];
                a[0] = packh2(S[mt][2*j  ][0], S[mt][2*j  ][1]);
                a[1] = packh2(S[mt][2*j  ][2], S[mt][2*j  ][3]);
                a[2] = packh2(S[mt][2*j+1][0], S[mt][2*j+1][1]);
                a[3] = packh2(S[mt][2*j+1][2], S[mt][2*j+1][3]);
#pragma unroll
                for (int dn = 0; dn < 2; dn++) {
                    unsigned b[2];
                    b[0] = *(const unsigned*)&Vt[dn*8 + lr][j*16 + lc*2];
                    b[1] = *(const unsigned*)&Vt[dn*8 + lr][j*16 + lc*2 + 8];
                    mma_f16(Oa[mt][dn], a, b);
                }
            }
    }

#pragma unroll
    for (int mt = 0; mt < 2; mt++)
#pragma unroll
        for (int o = 1; o <= 2; o <<= 1) {
            lsum[mt][0] += __shfl_xor_sync(0xffffffffu, lsum[mt][0], o);
            lsum[mt][1] += __shfl_xor_sync(0xffffffffu, lsum[mt][1], o);
        }
    float* ob = g_ao + (size_t)bn*NP*CC + head*16;
#pragma unroll
    for (int mt = 0; mt < 2; mt++) {
        float inv0 = 1.f / lsum[mt][0], inv1 = 1.f / lsum[mt][1];
        int qr = q0 + mt*16;
#pragma unroll
        for (int dn = 0; dn < 2; dn++) {
            int col = dn*8 + lc*2;
            *(float2*)(ob + (size_t)(qr+lr  )*CC + col) = make_float2(Oa[mt][dn][0]*inv0, Oa[mt][dn][1]*inv0);
            *(float2*)(ob + (size_t)(qr+lr+8)*CC + col) = make_float2(Oa[mt][dn][2]*inv1, Oa[mt][dn][3]*inv1);
        }
    }
}

// ---------------- GroupNorm stats (optionally gated input) ----------------
__global__ void k_gnstats(const float* __restrict__ X, const float* __restrict__ gate,
                          float2* __restrict__ stats) {
    __shared__ float sh[256], sh2[256];
    int bn = blockIdx.x >> 2, g = blockIdx.x & 3;
    float s = 0.f, q = 0.f;
    const float* base = X + (size_t)bn*NP*CC + g*32;
    for (int e = threadIdx.x; e < 32768; e += 256) {
        int n = e >> 5, cc = e & 31;
        float v = base[(size_t)n*CC + cc];
        if (gate) v *= gate[bn*NP + n];
        s += v; q += v*v;
    }
    sh[threadIdx.x] = s; sh2[threadIdx.x] = q;
    __syncthreads();
    for (int o = 128; o; o >>= 1) {
        if (threadIdx.x < o) { sh[threadIdx.x] += sh[threadIdx.x+o]; sh2[threadIdx.x] += sh2[threadIdx.x+o]; }
        __syncthreads();
    }
    if (threadIdx.x == 0) {
        float mu = sh[0] * (1.f/32768.f);
        float var = sh2[0] * (1.f/32768.f) - mu*mu;
        stats[blockIdx.x] = make_float2(mu, rsqrtf(var + 1e-5f));
    }
}

__global__ void k_gnapply(const float* __restrict__ g, const float* __restrict__ b) {
    int i = blockIdx.x * blockDim.x + threadIdx.x;
    if (i >= BNN*NP*CC) return;
    int c = i & 127;
    int bn = i >> 17;
    float2 st = g_st1[bn*4 + (c >> 5)];
    g_y2n[i] = (g_xt[i] - st.x)*st.y*g[c] + b[c];
}

__global__ void k_pool() {
    int i = blockIdx.x * blockDim.x + threadIdx.x;
    if (i >= BNN*NPC*CC) return;
    int c = i & 127;
    int pc = (i >> 7) & 255;
    int bn = i >> 15;
    int hp = pc >> 4, wp = pc & 15;
    size_t base = ((size_t)bn*NP + hp*64 + wp*2)*CC + c;
    g_gp[i] = 0.25f*(g_y2n[base] + g_y2n[base + CC] + g_y2n[base + 32*CC] + g_y2n[base + 33*CC]);
}

__global__ void k_gate(const float* __restrict__ w_psi, const float* __restrict__ b_psi) {
    int lane = threadIdx.x & 31, wid = threadIdx.x >> 5;
    int p = blockIdx.x*8 + wid;
    int bn = p >> 10, n = p & 1023;
    int h = n >> 5, w = n & 31;
    int pc = (h >> 1)*16 + (w >> 1);
    float4 gv = ((const float4*)(g_gg + ((size_t)bn*NPC + pc)*CC))[lane];
    float4 lv = ((const float4*)(g_l  + (size_t)p*CC))[lane];
    float4 wp = ((const float4*)w_psi)[lane];
    float s = fmaxf(gv.x+lv.x, 0.f)*wp.x + fmaxf(gv.y+lv.y, 0.f)*wp.y
            + fmaxf(gv.z+lv.z, 0.f)*wp.z + fmaxf(gv.w+lv.w, 0.f)*wp.w;
#pragma unroll
    for (int o = 16; o; o >>= 1) s += __shfl_xor_sync(0xffffffffu, s, o);
    if (lane == 0) g_gate[p] = 1.f/(1.f + expf(-(s + b_psi[0])));
}

// gated GN2 + transpose to channels-first + partial W-DFT (fused sa)
__global__ void k_y3t(const float* __restrict__ g, const float* __restrict__ b) {
    __shared__ float tile[128][33];
    __shared__ float gts[32];
    __shared__ float tc[32], ts[32];
    int bn = blockIdx.x >> 5, h = blockIdx.x & 31;
    if (threadIdx.x < 32) {
        gts[threadIdx.x] = g_gate[bn*NP + h*32 + threadIdx.x];
        float a = TWO_PI_32 * (float)threadIdx.x;
        tc[threadIdx.x] = cosf(a);
        ts[threadIdx.x] = sinf(a);
    }
    __syncthreads();
    const float* src = g_y2n + ((size_t)bn*NP + h*32)*CC;
#pragma unroll
    for (int it = 0; it < 16; it++) {
        int idx = threadIdx.x + it*256;
        int w = idx >> 7, c = idx & 127;
        tile[c][w] = src[(size_t)w*CC + c] * gts[w];
    }
    __syncthreads();
    float* dst = g_y3 + (size_t)bn*CC*NP + h*32;
#pragma unroll
    for (int it = 0; it < 16; it++) {
        int idx = threadIdx.x + it*256;
        int c = idx >> 5, w = idx & 31;
        float2 st = g_st2[bn*4 + (c >> 5)];
        float v = (tile[c][w] - st.x)*st.y*g[c] + b[c];
        dst[(size_t)c*NP + w] = v;
        tile[c][w] = v;                       // keep normalized value for DFT
    }
    __syncthreads();
    // partial DFT over w: 128 c x 12 modes
    float2* xw = g_Xw + ((size_t)bn*CC)*HH*MW + h*MW;
    for (int e = threadIdx.x; e < 128*12; e += 256) {
        int c = e / 12, kw = e % 12;
        float re = 0.f, im = 0.f;
#pragma unroll
        for (int w = 0; w < WW; w++) {
            int t = (w*kw) & 31;
            float v = tile[c][w];
            re += v*tc[t];
            im -= v*ts[t];
        }
        xw[(size_t)c*HH*MW + kw] = make_float2(re, im);
    }
}

// partial DFT along H -> z rows, coalesced (8 channels per block)
__global__ void k_sb2() {
    __shared__ float2 Xs[8][HH*MW];          // 24KB
    __shared__ float zr[144][8], zi[144][8];
    __shared__ float tc[32], ts[32];
    if (threadIdx.x < 32) {
        float a = TWO_PI_32 * (float)threadIdx.x;
        tc[threadIdx.x] = cosf(a);
        ts[threadIdx.x] = sinf(a);
    }
    int bn = blockIdx.x >> 4, cg = blockIdx.x & 15;   // 16 groups of 8 c
    const float2* src = g_Xw + ((size_t)(bn*CC + cg*8))*HH*MW;
    for (int e = threadIdx.x; e < 8*HH*MW; e += 256) {
        int c = e / (HH*MW), r = e % (HH*MW);
        Xs[c][r] = src[(size_t)c*HH*MW + r];
    }
    __syncthreads();
    for (int e = threadIdx.x; e < 144*8; e += 256) {
        int m = e >> 3, c = e & 7;
        int kh = m / 12, kw = m % 12;
        float re = 0.f, im = 0.f;
#pragma unroll
        for (int h = 0; h < HH; h++) {
            int t = (kh*h) & 31;
            float2 v = Xs[c][h*MW + kw];
            re += v.x*tc[t] + v.y*ts[t];
            im += v.y*tc[t] - v.x*ts[t];
        }
        zr[m][c] = re * INV32;
        zi[m][c] = im * INV32;
    }
    __syncthreads();
    for (int e = threadIdx.x; e < 144*16; e += 256) {
        int m = e >> 4, j = e & 15;
        size_t rowz = (size_t)(bn*144 + m) * 256;
        if (j < 8) g_zin[rowz + cg*8 + j] = zr[m][j];
        else       g_zin[rowz + 128 + cg*8 + (j-8)] = zi[m][j-8];
    }
}

// inverse DFT along H of delta modes, coalesced (32 channels per block)
__global__ void k_sd2() {
    __shared__ float Dr[144][32], Di[144][32];        // 36.9KB
    __shared__ float tc[32], ts[32];
    if (threadIdx.x < 32) {
        float a = TWO_PI_32 * (float)threadIdx.x;
        tc[threadIdx.x] = cosf(a);
        ts[threadIdx.x] = sinf(a);
    }
    int bn = blockIdx.x >> 2, cg = blockIdx.x & 3;    // 4 groups of 32 c
    for (int e = threadIdx.x; e < 144*32; e += 256) {
        int m = e >> 5, c = e & 31;
        size_t rowz = (size_t)(bn*144 + m) * 256;
        Dr[m][c] = g_zout[rowz + cg*32 + c];
        Di[m][c] = g_zout[rowz + 128 + cg*32 + c];
    }
    __syncthreads();
    int c = threadIdx.x & 31, hg = threadIdx.x >> 5;  // 8 h-groups
    float2* dst = g_tH + ((size_t)(bn*CC + cg*32 + c))*HH*MW;
#pragma unroll
    for (int hi = 0; hi < 4; hi++) {
        int h = hg*4 + hi;
#pragma unroll
        for (int kw = 0; kw < 12; kw++) {
            float re = 0.f, im = 0.f;
#pragma unroll
            for (int kh = 0; kh < MH; kh++) {
                int t = (kh*h) & 31;
                float dx = Dr[kh*12 + kw][c], dy = Di[kh*12 + kw][c];
                re += dx*tc[t] - dy*ts[t];
                im += dx*ts[t] + dy*tc[t];
            }
            dst[h*MW + kw] = make_float2(re*INV_SQRT32, im*INV_SQRT32);
        }
    }
}

// final c2r along W of delta + out = 2*y3 + ys (parity split), output transpose
__global__ void k_se(float* __restrict__ out) {
    __shared__ float tc[32], ts[32];
    if (threadIdx.x < 32) {
        float a = TWO_PI_32 * (float)threadIdx.x;
        tc[threadIdx.x] = cosf(a);
        ts[threadIdx.x] = sinf(a);
    }
    __syncthreads();
    int row = blockIdx.x * blockDim.x + threadIdx.x;   // (bn,c,h)
    if (row >= BNN*CC*HH) return;
    int h = row & 31;
    int c = (row >> 5) & 127;
    int bn = row >> 12;
    float2 T[MW];
    const float2* tp = g_tH + (size_t)row * MW;
#pragma unroll
    for (int kw = 0; kw < MW; kw++) T[kw] = tp[kw];
    const float* yp = g_y3 + (size_t)row * WW;
    int b = bn >> 5, l = bn & 31;
    float* op = out + (((((size_t)b*CC + c)*LL + l)*HH + h)) * WW;
    for (int w = 0; w < 16; w++) {
        float se = T[0].x, so = 0.f;
#pragma unroll
        for (int kw = 1; kw < MW; kw++) {
            int t = (kw*w) & 31;
            float term = 2.f*(T[kw].x*tc[t] - T[kw].y*ts[t]);
            if (kw & 1) so += term; else se += term;
        }
        op[w]      = 2.f*yp[w]      + (se + so)*INV_SQRT32;
        op[w + 16] = 2.f*yp[w + 16] + (se - so)*INV_SQRT32;
    }
}

// ---------------- launch ----------------
static float* symaddr_f(const void* sym) { void* p = 0; cudaGetSymbolAddress(&p, sym); return (float*)p; }

extern "C" void kernel_launch(void* const* d_in, const int* in_sizes, int n_in,
                              void* d_out, int out_size) {
    const float* x      = (const float*)d_in[0];
    const float* dt     = (const float*)d_in[1];
    const float* nu     = (const float*)d_in[2];
    const float* theta  = (const float*)d_in[3];
    const float* ln_g   = (const float*)d_in[4];
    const float* ln_b   = (const float*)d_in[5];
    const float* w_qkv  = (const float*)d_in[6];
    const float* w_proj = (const float*)d_in[7];
    const float* b_proj = (const float*)d_in[8];
    const float* gn_g   = (const float*)d_in[9];
    const float* gn_b   = (const float*)d_in[10];
    const float* w_g    = (const float*)d_in[11];
    const float* w_l    = (const float*)d_in[12];
    const float* w_psi  = (const float*)d_in[13];
    const float* b_psi  = (const float*)d_in[14];
    const float* gate_g = (const float*)d_in[15];
    const float* gate_b = (const float*)d_in[16];
    const float* mix_w  = (const float*)d_in[17];
    const float* mix_b  = (const float*)d_in[18];
    float* out = (float*)d_out;

    float* p_xt  = symaddr_f(g_xt);
    float* p_xn  = symaddr_f(g_xn);
    __half* p_qkvh = (__half*)symaddr_f(g_qkvh);
    float* p_ao  = symaddr_f(g_ao);
    float* p_y2n = symaddr_f(g_y2n);
    float* p_gp  = symaddr_f(g_gp);
    float* p_gg  = symaddr_f(g_gg);
    float* p_l   = symaddr_f(g_l);
    float* p_zin = symaddr_f(g_zin);
    float* p_zout= symaddr_f(g_zout);
    float2* p_st1 = (float2*)symaddr_f(g_st1);
    float2* p_st2 = (float2*)symaddr_f(g_st2);
    float* p_gate = symaddr_f(g_gate);

    // stage 1
    k_precompA<<<(BB*LL*CC*WF + 255)/256, 256>>>(dt, nu, theta);
    k_rfft<<<(BB*CC*LL*HH + 127)/128, 128>>>(x);
    k_scan<<<(BB*CC*HH*WF + 255)/256, 256>>>();
    k_irfft<<<(BB*LL*HH*CC)/256, 256>>>();
    // stage 2: LN + attention + proj residual
    k_ln<<<(BNN*NP)/8, 256>>>(ln_g, ln_b);
    k_gemm_tc_h<<<dim3(384/64, (BNN*NP)/64), 128>>>(p_xn, w_qkv, p_qkvh, BNN*NP, 384, CC, 1);
    k_fattn<<<BNN*8*8, 128>>>();
    k_gemm_tc<<<dim3(CC/64, (BNN*NP)/64), 128>>>(p_ao, w_proj, b_proj, p_xt, BNN*NP, CC, CC, 1, 0);
    // stage 3: GN1, gating, GN2
    k_gnstats<<<BNN*4, 256>>>(p_xt, (const float*)0, p_st1);
    k_gnapply<<<(BNN*NP*CC)/256, 256>>>(gn_g, gn_b);
    k_pool<<<(BNN*NPC*CC)/256, 256>>>();
    k_gemm_tc<<<dim3(CC/64, (BNN*NPC)/64), 128>>>(p_gp, w_g, (const float*)0, p_gg, BNN*NPC, CC, CC, 0, 0);
    k_gemm_tc<<<dim3(CC/64, (BNN*NP)/64), 128>>>(p_y2n, w_l, (const float*)0, p_l, BNN*NP, CC, CC, 0, 0);
    k_gate<<<(BNN*NP)/8, 256>>>(w_psi, b_psi);
    k_gnstats<<<BNN*4, 256>>>(p_y2n, p_gate, p_st2);
    k_y3t<<<BNN*HH, 256>>>(gate_g, gate_b);
    // stage 4: spectral delta on TC (delta = z(mix_w - I)^T + mix_b)
    k_sb2<<<BNN*16, 256>>>();
    k_gemm_tc<<<dim3(256/64, (BNN*144)/64), 128>>>(p_zin, mix_w, mix_b, p_zout, BNN*144, 256, 256, 0, 1);
    k_sd2<<<BNN*4, 256>>>();
    k_se<<<(BNN*CC*HH)/256, 256>>>(out);
}

// round 8
// speedup vs baseline: 2.8353x; 1.0620x over previous
#include <cuda_runtime.h>
#include <cuda_fp16.h>
#include <math.h>

// ---------------- shapes ----------------
#define BB 2
#define CC 128
#define LL 32
#define HH 32
#define WW 32
#define WF 17
#define BNN 64
#define NP 1024
#define NPC 256
#define MH 12
#define MW 12

#define TWO_PI_32 0.19634954084936207f
#define INV32 0.03125f
#define INV_SQRT32 0.17677669529663687f
#define QK_SCALE 0.36067376022224085f    // 0.25 * log2(e)

// ---------------- device scratch ----------------
__device__ float2 g_xf[BB*CC*LL*HH*WF];
__device__ float2 g_A [BB*LL*CC*WF];
__device__ float  g_xt [BNN*NP*CC];
__device__ __half g_xnh[BNN*NP*CC];
__device__ __half g_qkvh[BNN*NP*384];
__device__ __half g_aoh[BNN*NP*CC];
__device__ __half g_y2nh[BNN*NP*CC];
__device__ __half g_gph[BNN*NPC*CC];
__device__ __half g_ggh[BNN*NPC*CC];
__device__ __half g_lh [BNN*NP*CC];
__device__ float  g_gate[BNN*NP];
__device__ float  g_y3 [BNN*CC*NP];
__device__ float2 g_Xw [BNN*CC*HH*MW];
__device__ float  g_zin [BNN*144*256];
__device__ float  g_zout[BNN*144*256];
__device__ float2 g_tH [BNN*CC*HH*MW];
__device__ float2 g_st1[BNN*4];
__device__ float2 g_st2[BNN*4];

// ---------------- mma helpers ----------------
__device__ __forceinline__ unsigned f2tf32(float f) {
    unsigned r; asm("cvt.rna.tf32.f32 %0, %1;" : "=r"(r) : "f"(f)); return r;
}
__device__ __forceinline__ void mma_tf32(float* c, const unsigned* a, const unsigned* b) {
    asm("mma.sync.aligned.m16n8k8.row.col.f32.tf32.tf32.f32 "
        "{%0,%1,%2,%3}, {%4,%5,%6,%7}, {%8,%9}, {%0,%1,%2,%3};"
        : "+f"(c[0]), "+f"(c[1]), "+f"(c[2]), "+f"(c[3])
        : "r"(a[0]), "r"(a[1]), "r"(a[2]), "r"(a[3]), "r"(b[0]), "r"(b[1]));
}
__device__ __forceinline__ void mma_f16(float* c, const unsigned* a, const unsigned* b) {
    asm("mma.sync.aligned.m16n8k16.row.col.f32.f16.f16.f32 "
        "{%0,%1,%2,%3}, {%4,%5,%6,%7}, {%8,%9}, {%0,%1,%2,%3};"
        : "+f"(c[0]), "+f"(c[1]), "+f"(c[2]), "+f"(c[3])
        : "r"(a[0]), "r"(a[1]), "r"(a[2]), "r"(a[3]), "r"(b[0]), "r"(b[1]));
}
__device__ __forceinline__ unsigned packh2(float a, float b) {
    __half2 h = __floats2half2_rn(a, b);
    return *(unsigned*)&h;
}
__device__ __forceinline__ float ex2a(float x) {
    float r; asm("ex2.approx.f32 %0, %1;" : "=f"(r) : "f"(fminf(x, 80.f))); return r;
}

// ---------------- stage 1: A precompute ----------------
__global__ void k_precompA(const float* __restrict__ dt, const float* __restrict__ nu,
                           const float* __restrict__ th) {
    int i = blockIdx.x * blockDim.x + threadIdx.x;
    if (i >= BB*LL*CC*WF) return;
    int k = i % WF;
    int c = (i / WF) % CC;
    int l = (i / (WF*CC)) % LL;
    int b =  i / (WF*CC*LL);
    float d  = dt[b*LL + l];
    float e  = expf(-nu[c*WF + k] * d);
    float si, co;
    sincosf(th[c*WF + k] * d, &si, &co);
    g_A[i] = make_float2(e*co, e*si);
}

// ---------------- stage 1: rfft along W ----------------
__global__ void k_rfft(const float* __restrict__ x) {
    __shared__ float tc[32], ts[32];
    if (threadIdx.x < 32) {
        float a = TWO_PI_32 * (float)threadIdx.x;
        tc[threadIdx.x] = cosf(a);
        ts[threadIdx.x] = sinf(a);
    }
    __syncthreads();
    int row = blockIdx.x * blockDim.x + threadIdx.x;   // (b,c,l,h)
    if (row >= BB*CC*LL*HH) return;
    const float* xp = x + (size_t)row * WW;
    float xr[WW];
#pragma unroll
    for (int w = 0; w < WW; w++) xr[w] = xp[w];
    float2* out = g_xf + (size_t)row * WF;
    for (int k = 0; k < WF; k++) {
        float re = 0.f, im = 0.f;
#pragma unroll
        for (int w = 0; w < WW; w++) {
            int t = (w*k) & 31;
            re += xr[w]*tc[t];
            im -= xr[w]*ts[t];
        }
        out[k] = make_float2(re, im);
    }
}

// ---------------- stage 1: complex scan over L ----------------
__global__ void k_scan() {
    int i = blockIdx.x * blockDim.x + threadIdx.x;     // (b,c,h,k)
    if (i >= BB*CC*HH*WF) return;
    int k = i % WF;
    int h = (i / WF) % HH;
    int c = (i / (WF*HH)) % CC;
    int b =  i / (WF*HH*CC);
    size_t xfb = ((((size_t)b*CC + c)*LL)*HH + h)*WF + k;
    const size_t xstr = (size_t)HH*WF;
    size_t ab = ((size_t)b*LL*CC + c)*WF + k;
    const size_t astr = (size_t)CC*WF;
    float2 s = make_float2(0.f, 0.f);
    for (int l = 0; l < LL; l++) {
        float2 a = g_A[ab + (size_t)l*astr];
        float2 u = g_xf[xfb + (size_t)l*xstr];
        float re = a.x*s.x - a.y*s.y + u.x;
        float im = a.x*s.y + a.y*s.x + u.y;
        s = make_float2(re, im);
        g_xf[xfb + (size_t)l*xstr] = s;
    }
}

// ---------------- stage 1: irfft -> xt channels-last (parity split) -------------
__global__ void k_irfft() {
    __shared__ float tc[32], ts[32];
    if (threadIdx.x < 32) {
        float a = TWO_PI_32 * (float)threadIdx.x;
        tc[threadIdx.x] = cosf(a);
        ts[threadIdx.x] = sinf(a);
    }
    __syncthreads();
    int i = blockIdx.x * blockDim.x + threadIdx.x;     // (b,l,h,c)
    if (i >= BB*LL*HH*CC) return;
    int c = i & 127;
    int h = (i >> 7) & 31;
    int l = (i >> 12) & 31;
    int b =  i >> 17;
    const float2* st = g_xf + ((((size_t)b*CC + c)*LL + l)*HH + h)*WF;
    float2 S[WF];
#pragma unroll
    for (int k = 0; k < WF; k++) S[k] = st[k];
    int bn = b*LL + l;
    float* out = g_xt + ((size_t)bn*NP + h*WW)*CC + c;
    for (int w = 0; w < 16; w++) {
        float se = S[0].x + ((w & 1) ? -S[16].x : S[16].x);
        float so = 0.f;
#pragma unroll
        for (int k = 1; k < 16; k++) {
            int t = (w*k) & 31;
            float term = 2.f*(S[k].x*tc[t] - S[k].y*ts[t]);
            if (k & 1) so += term; else se += term;
        }
        out[(size_t)w*CC]      = (se + so) * INV32;
        out[(size_t)(w+16)*CC] = (se - so) * INV32;
    }
}

// ---------------- LayerNorm over C -> fp16 ----------------
__global__ void k_ln(const float* __restrict__ g, const float* __restrict__ b) {
    int lane = threadIdx.x & 31, wid = threadIdx.x >> 5;
    int r = blockIdx.x*8 + wid;
    float4 v = ((const float4*)(g_xt + (size_t)r*CC))[lane];
    float s = v.x + v.y + v.z + v.w;
#pragma unroll
    for (int o = 16; o; o >>= 1) s += __shfl_xor_sync(0xffffffffu, s, o);
    float mu = s * (1.f/128.f);
    float dx = v.x-mu, dy = v.y-mu, dz = v.z-mu, dw = v.w-mu;
    float q = dx*dx + dy*dy + dz*dz + dw*dw;
#pragma unroll
    for (int o = 16; o; o >>= 1) q += __shfl_xor_sync(0xffffffffu, q, o);
    float rstd = rsqrtf(q*(1.f/128.f) + 1e-5f);
    float4 g4 = ((const float4*)g)[lane];
    float4 b4 = ((const float4*)b)[lane];
    __half2* op = (__half2*)(g_xnh + (size_t)r*CC);
    op[lane*2]   = __floats2half2_rn(dx*rstd*g4.x + b4.x, dy*rstd*g4.y + b4.y);
    op[lane*2+1] = __floats2half2_rn(dz*rstd*g4.z + b4.z, dw*rstd*g4.w + b4.w);
}

// ---------------- fp16 TC GEMM: A fp16, B fp32->fp16 on load --------------------
// out: Ch fp16 (optional qscale on cols<128) OR Cf fp32 (+bias, optional accum)
__global__ void k_gemm_h(const __half* __restrict__ A, const float* __restrict__ B,
                         const float* __restrict__ bias, float* __restrict__ Cf,
                         __half* __restrict__ Ch,
                         int M, int N, int K, int accum, int qscale) {
    __shared__ unsigned As[64*20];           // 64 rows x 16 u32 (32 halves), pad 20
    __shared__ unsigned Bs[64*20];
    int bm = blockIdx.y << 6, bn = blockIdx.x << 6;
    int warp = threadIdx.x >> 5, lane = threadIdx.x & 31;
    int lr = lane >> 2, lc = lane & 3;
    float acc[8][4];
#pragma unroll
    for (int nf = 0; nf < 8; nf++)
#pragma unroll
        for (int j = 0; j < 4; j++) acc[nf][j] = 0.f;

    for (int k0 = 0; k0 < K; k0 += 32) {
        __syncthreads();
#pragma unroll
        for (int i = 0; i < 2; i++) {
            int slot = threadIdx.x + i*128;  // 256 slots = 64 rows x 4 uint4
            int m = slot >> 2, seg = (slot & 3) * 4;     // seg in u32 units
            *(uint4*)&As[m*20 + seg] = *(const uint4*)(A + (size_t)(bm+m)*K + k0 + seg*2);
        }
#pragma unroll
        for (int i = 0; i < 4; i++) {
            int slot = threadIdx.x + i*128;  // 512 slots = 64 rows x 8 float4
            int m = slot >> 3, seg = (slot & 7) * 4;     // seg in float units
            float4 b4 = *(const float4*)(B + (size_t)(bn+m)*K + k0 + seg);
            __half2 h0 = __floats2half2_rn(b4.x, b4.y);
            __half2 h1 = __floats2half2_rn(b4.z, b4.w);
            Bs[m*20 + (seg>>1)]     = *(unsigned*)&h0;
            Bs[m*20 + (seg>>1) + 1] = *(unsigned*)&h1;
        }
        __syncthreads();
#pragma unroll
        for (int ks = 0; ks < 2; ks++) {     // k=16 per mma
            unsigned a[4];
            int am = warp*16;
            a[0] = As[(am+lr  )*20 + ks*8 + lc];
            a[1] = As[(am+lr+8)*20 + ks*8 + lc];
            a[2] = As[(am+lr  )*20 + ks*8 + lc + 4];
            a[3] = As[(am+lr+8)*20 + ks*8 + lc + 4];
#pragma unroll
            for (int nf = 0; nf < 8; nf++) {
                unsigned b[2];
                b[0] = Bs[(nf*8+lr)*20 + ks*8 + lc];
                b[1] = Bs[(nf*8+lr)*20 + ks*8 + lc + 4];
                mma_f16(acc[nf], a, b);
            }
        }
    }
#pragma unroll
    for (int nf = 0; nf < 8; nf++) {
        int col = bn + nf*8 + lc*2;
        int row = bm + warp*16 + lr;
        if (Ch) {
            float sc = (qscale && col < 128) ? QK_SCALE : 1.f;
            *(__half2*)(Ch + (size_t)row*N + col)     = __floats2half2_rn(acc[nf][0]*sc, acc[nf][1]*sc);
            *(__half2*)(Ch + (size_t)(row+8)*N + col) = __floats2half2_rn(acc[nf][2]*sc, acc[nf][3]*sc);
        } else {
            float b0 = bias ? bias[col] : 0.f;
            float b1 = bias ? bias[col+1] : 0.f;
            float2* p = (float2*)(Cf + (size_t)row*N + col);
            float2 v = make_float2(acc[nf][0]+b0, acc[nf][1]+b1);
            if (accum) { float2 o = *p; v.x += o.x; v.y += o.y; }
            *p = v;
            p = (float2*)(Cf + (size_t)(row+8)*N + col);
            v = make_float2(acc[nf][2]+b0, acc[nf][3]+b1);
            if (accum) { float2 o = *p; v.x += o.x; v.y += o.y; }
            *p = v;
        }
    }
}

// ---------------- tf32 TC GEMM (mix delta): C = A*(B - subI*I)^T (+bias) --------
__global__ void k_gemm_tc(const float* __restrict__ A, const float* __restrict__ B,
                          const float* __restrict__ bias, float* __restrict__ C,
                          int M, int N, int K, int accum, int subI) {
    __shared__ unsigned As[64*36];
    __shared__ unsigned Bs[64*36];
    int bm = blockIdx.y << 6, bn = blockIdx.x << 6;
    int warp = threadIdx.x >> 5, lane = threadIdx.x & 31;
    int lr = lane >> 2, lc = lane & 3;
    float acc[8][4];
#pragma unroll
    for (int nf = 0; nf < 8; nf++)
#pragma unroll
        for (int j = 0; j < 4; j++) acc[nf][j] = 0.f;

    for (int k0 = 0; k0 < K; k0 += 32) {
        __syncthreads();
#pragma unroll
        for (int i = 0; i < 4; i++) {
            int slot = threadIdx.x + i*128;
            int m = slot >> 3, seg = (slot & 7) << 2;
            float4 a4 = *(const float4*)(A + (size_t)(bm+m)*K + k0 + seg);
            *(uint4*)&As[m*36 + seg] = make_uint4(f2tf32(a4.x), f2tf32(a4.y), f2tf32(a4.z), f2tf32(a4.w));
            float4 b4 = *(const float4*)(B + (size_t)(bn+m)*K + k0 + seg);
            if (subI) {
                int row = bn + m, col = k0 + seg;
                if (row == col    ) b4.x -= 1.f;
                if (row == col + 1) b4.y -= 1.f;
                if (row == col + 2) b4.z -= 1.f;
                if (row == col + 3) b4.w -= 1.f;
            }
            *(uint4*)&Bs[m*36 + seg] = make_uint4(f2tf32(b4.x), f2tf32(b4.y), f2tf32(b4.z), f2tf32(b4.w));
        }
        __syncthreads();
#pragma unroll
        for (int ks = 0; ks < 4; ks++) {
            unsigned a[4];
            int am = warp*16;
            a[0] = As[(am+lr  )*36 + ks*8 + lc];
            a[1] = As[(am+lr+8)*36 + ks*8 + lc];
            a[2] = As[(am+lr  )*36 + ks*8 + lc + 4];
            a[3] = As[(am+lr+8)*36 + ks*8 + lc + 4];
#pragma unroll
            for (int nf = 0; nf < 8; nf++) {
                unsigned b[2];
                b[0] = Bs[(nf*8+lr)*36 + ks*8 + lc];
                b[1] = Bs[(nf*8+lr)*36 + ks*8 + lc + 4];
                mma_tf32(acc[nf], a, b);
            }
        }
    }
#pragma unroll
    for (int nf = 0; nf < 8; nf++) {
        int col = bn + nf*8 + lc*2;
        float b0 = bias ? bias[col] : 0.f;
        float b1 = bias ? bias[col+1] : 0.f;
        int row = bm + warp*16 + lr;
        float2* p = (float2*)(C + (size_t)row*N + col);
        float2 v = make_float2(acc[nf][0]+b0, acc[nf][1]+b1);
        if (accum) { float2 o = *p; v.x += o.x; v.y += o.y; }
        *p = v;
        p = (float2*)(C + (size_t)(row+8)*N + col);
        v = make_float2(acc[nf][2]+b0, acc[nf][3]+b1);
        if (accum) { float2 o = *p; v.x += o.x; v.y += o.y; }
        *p = v;
    }
}

// ---------------- flash attention: all-fp16 mma, 128-query tiles ----------------
__global__ void k_fattn() {
    __shared__ __half Ks[64][24];
    __shared__ __half Vt[16][72];
    int blk = blockIdx.x;                   // qt + 8*(head + 8*bn)
    int qt = blk & 7, head = (blk >> 3) & 7, bn = blk >> 6;
    int warp = threadIdx.x >> 5, lane = threadIdx.x & 31;
    int lr = lane >> 2, lc = lane & 3;
    int q0 = qt*128 + warp*32;
    const __half* qkb = g_qkvh + (size_t)bn*NP*384 + head*16;

    unsigned Qa[2][4];
#pragma unroll
    for (int mt = 0; mt < 2; mt++) {
        const __half* qp = qkb + (size_t)(q0 + mt*16)*384;
        Qa[mt][0] = *(const unsigned*)(qp + (size_t)(lr  )*384 + 2*lc);
        Qa[mt][1] = *(const unsigned*)(qp + (size_t)(lr+8)*384 + 2*lc);
        Qa[mt][2] = *(const unsigned*)(qp + (size_t)(lr  )*384 + 2*lc + 8);
        Qa[mt][3] = *(const unsigned*)(qp + (size_t)(lr+8)*384 + 2*lc + 8);
    }

    float lsum[2][2] = {{0.f,0.f},{0.f,0.f}};
    float Oa[2][2][4];
#pragma unroll
    for (int mt = 0; mt < 2; mt++)
#pragma unroll
        for (int dn = 0; dn < 2; dn++)
#pragma unroll
            for (int j = 0; j < 4; j++) Oa[mt][dn][j] = 0.f;

    for (int c0 = 0; c0 < NP; c0 += 64) {
        __syncthreads();
        {
            int key = threadIdx.x >> 1, seg = (threadIdx.x & 1) * 8;
            const __half* kp = qkb + (size_t)(c0 + key)*384 + 128 + seg;
            *(uint4*)&Ks[key][seg] = *(const uint4*)kp;
            uint4 vv = *(const uint4*)(kp + 128);
            __half vh[8];
            *(uint4*)vh = vv;
#pragma unroll
            for (int j = 0; j < 8; j++) Vt[seg + j][key] = vh[j];
        }
        __syncthreads();

        float S[2][8][4];
#pragma unroll
        for (int mt = 0; mt < 2; mt++)
#pragma unroll
            for (int nf = 0; nf < 8; nf++) {
                S[mt][nf][0] = S[mt][nf][1] = S[mt][nf][2] = S[mt][nf][3] = 0.f;
                unsigned b[2];
                b[0] = *(const unsigned*)&Ks[nf*8 + lr][2*lc];
                b[1] = *(const unsigned*)&Ks[nf*8 + lr][2*lc + 8];
                mma_f16(S[mt][nf], Qa[mt], b);
            }

#pragma unroll
        for (int mt = 0; mt < 2; mt++)
#pragma unroll
            for (int nf = 0; nf < 8; nf++) {
                S[mt][nf][0] = ex2a(S[mt][nf][0]);
                S[mt][nf][1] = ex2a(S[mt][nf][1]);
                S[mt][nf][2] = ex2a(S[mt][nf][2]);
                S[mt][nf][3] = ex2a(S[mt][nf][3]);
                lsum[mt][0] += S[mt][nf][0] + S[mt][nf][1];
                lsum[mt][1] += S[mt][nf][2] + S[mt][nf][3];
            }

#pragma unroll
        for (int mt = 0; mt < 2; mt++)
#pragma unroll
            for (int j = 0; j < 4; j++) {
                unsigned a[4];
                a[0] = packh2(S[mt][2*j  ][0], S[mt][2*j  ][1]);
                a[1] = packh2(S[mt][2*j  ][2], S[mt][2*j  ][3]);
                a[2] = packh2(S[mt][2*j+1][0], S[mt][2*j+1][1]);
                a[3] = packh2(S[mt][2*j+1][2], S[mt][2*j+1][3]);
#pragma unroll
                for (int dn = 0; dn < 2; dn++) {
                    unsigned b[2];
                    b[0] = *(const unsigned*)&Vt[dn*8 + lr][j*16 + lc*2];
                    b[1] = *(const unsigned*)&Vt[dn*8 + lr][j*16 + lc*2 + 8];
                    mma_f16(Oa[mt][dn], a, b);
                }
            }
    }

#pragma unroll
    for (int mt = 0; mt < 2; mt++)
#pragma unroll
        for (int o = 1; o <= 2; o <<= 1) {
            lsum[mt][0] += __shfl_xor_sync(0xffffffffu, lsum[mt][0], o);
            lsum[mt][1] += __shfl_xor_sync(0xffffffffu, lsum[mt][1], o);
        }
    __half* ob = g_aoh + (size_t)bn*NP*CC + head*16;
#pragma unroll
    for (int mt = 0; mt < 2; mt++) {
        float inv0 = 1.f / lsum[mt][0], inv1 = 1.f / lsum[mt][1];
        int qr = q0 + mt*16;
#pragma unroll
        for (int dn = 0; dn < 2; dn++) {
            int col = dn*8 + lc*2;
            *(__half2*)(ob + (size_t)(qr+lr  )*CC + col) = __floats2half2_rn(Oa[mt][dn][0]*inv0, Oa[mt][dn][1]*inv0);
            *(__half2*)(ob + (size_t)(qr+lr+8)*CC + col) = __floats2half2_rn(Oa[mt][dn][2]*inv1, Oa[mt][dn][3]*inv1);
        }
    }
}

// ---------------- GroupNorm stats: fp32 input ----------------
__global__ void k_gnstats(const float* __restrict__ X, float2* __restrict__ stats) {
    __shared__ float sh[256], sh2[256];
    int bn = blockIdx.x >> 2, g = blockIdx.x & 3;
    float s = 0.f, q = 0.f;
    const float* base = X + (size_t)bn*NP*CC + g*32;
    for (int e = threadIdx.x; e < 32768; e += 256) {
        int n = e >> 5, cc = e & 31;
        float v = base[(size_t)n*CC + cc];
        s += v; q += v*v;
    }
    sh[threadIdx.x] = s; sh2[threadIdx.x] = q;
    __syncthreads();
    for (int o = 128; o; o >>= 1) {
        if (threadIdx.x < o) { sh[threadIdx.x] += sh[threadIdx.x+o]; sh2[threadIdx.x] += sh2[threadIdx.x+o]; }
        __syncthreads();
    }
    if (threadIdx.x == 0) {
        float mu = sh[0] * (1.f/32768.f);
        float var = sh2[0] * (1.f/32768.f) - mu*mu;
        stats[blockIdx.x] = make_float2(mu, rsqrtf(var + 1e-5f));
    }
}

// ---------------- GroupNorm stats: fp16 input x gate ----------------
__global__ void k_gnstats_h(const __half* __restrict__ X, const float* __restrict__ gate,
                            float2* __restrict__ stats) {
    __shared__ float sh[256], sh2[256];
    int bn = blockIdx.x >> 2, g = blockIdx.x & 3;
    float s = 0.f, q = 0.f;
    const __half* base = X + (size_t)bn*NP*CC + g*32;
    for (int e = threadIdx.x; e < 32768; e += 256) {
        int n = e >> 5, cc = e & 31;
        float v = __half2float(base[(size_t)n*CC + cc]) * gate[bn*NP + n];
        s += v; q += v*v;
    }
    sh[threadIdx.x] = s; sh2[threadIdx.x] = q;
    __syncthreads();
    for (int o = 128; o; o >>= 1) {
        if (threadIdx.x < o) { sh[threadIdx.x] += sh[threadIdx.x+o]; sh2[threadIdx.x] += sh2[threadIdx.x+o]; }
        __syncthreads();
    }
    if (threadIdx.x == 0) {
        float mu = sh[0] * (1.f/32768.f);
        float var = sh2[0] * (1.f/32768.f) - mu*mu;
        stats[blockIdx.x] = make_float2(mu, rsqrtf(var + 1e-5f));
    }
}

__global__ void k_gnapply(const float* __restrict__ g, const float* __restrict__ b) {
    int i = blockIdx.x * blockDim.x + threadIdx.x;
    if (i >= BNN*NP*CC) return;
    int c = i & 127;
    int bn = i >> 17;
    float2 st = g_st1[bn*4 + (c >> 5)];
    g_y2nh[i] = __float2half((g_xt[i] - st.x)*st.y*g[c] + b[c]);
}

__global__ void k_pool() {
    int i = blockIdx.x * blockDim.x + threadIdx.x;     // half2 units
    if (i >= BNN*NPC*64) return;
    int c2 = i & 63;
    int pc = (i >> 6) & 255;
    int bn = i >> 14;
    int hp = pc >> 4, wp = pc & 15;
    const __half2* base = (const __half2*)g_y2nh + ((size_t)bn*NP + hp*64 + wp*2)*64 + c2;
    float2 a = __half22float2(base[0]);
    float2 b = __half22float2(base[64]);
    float2 c = __half22float2(base[32*64]);
    float2 d = __half22float2(base[33*64]);
    ((__half2*)g_gph)[i] = __floats2half2_rn(0.25f*(a.x+b.x+c.x+d.x), 0.25f*(a.y+b.y+c.y+d.y));
}

__global__ void k_gate(const float* __restrict__ w_psi, const float* __restrict__ b_psi) {
    int lane = threadIdx.x & 31, wid = threadIdx.x >> 5;
    int p = blockIdx.x*8 + wid;
    int bn = p >> 10, n = p & 1023;
    int h = n >> 5, w = n & 31;
    int pc = (h >> 1)*16 + (w >> 1);
    const __half2* gp2 = (const __half2*)(g_ggh + ((size_t)bn*NPC + pc)*CC);
    const __half2* lp2 = (const __half2*)(g_lh + (size_t)p*CC);
    float2 ga = __half22float2(gp2[lane*2]),   gb = __half22float2(gp2[lane*2+1]);
    float2 la = __half22float2(lp2[lane*2]),   lb = __half22float2(lp2[lane*2+1]);
    float4 wp = ((const float4*)w_psi)[lane];
    float s = fmaxf(ga.x+la.x, 0.f)*wp.x + fmaxf(ga.y+la.y, 0.f)*wp.y
            + fmaxf(gb.x+lb.x, 0.f)*wp.z + fmaxf(gb.y+lb.y, 0.f)*wp.w;
#pragma unroll
    for (int o = 16; o; o >>= 1) s += __shfl_xor_sync(0xffffffffu, s, o);
    if (lane == 0) g_gate[p] = 1.f/(1.f + expf(-(s + b_psi[0])));
}

// gated GN2 + transpose to channels-first + partial W-DFT (fused)
__global__ void k_y3t(const float* __restrict__ g, const float* __restrict__ b) {
    __shared__ float tile[128][33];
    __shared__ float gts[32];
    __shared__ float tc[32], ts[32];
    int bn = blockIdx.x >> 5, h = blockIdx.x & 31;
    if (threadIdx.x < 32) {
        gts[threadIdx.x] = g_gate[bn*NP + h*32 + threadIdx.x];
        float a = TWO_PI_32 * (float)threadIdx.x;
        tc[threadIdx.x] = cosf(a);
        ts[threadIdx.x] = sinf(a);
    }
    __syncthreads();
    const __half* src = g_y2nh + ((size_t)bn*NP + h*32)*CC;
#pragma unroll
    for (int it = 0; it < 16; it++) {
        int idx = threadIdx.x + it*256;
        int w = idx >> 7, c = idx & 127;
        tile[c][w] = __half2float(src[(size_t)w*CC + c]) * gts[w];
    }
    __syncthreads();
    float* dst = g_y3 + (size_t)bn*CC*NP + h*32;
#pragma unroll
    for (int it = 0; it < 16; it++) {
        int idx = threadIdx.x + it*256;
        int c = idx >> 5, w = idx & 31;
        float2 st = g_st2[bn*4 + (c >> 5)];
        float v = (tile[c][w] - st.x)*st.y*g[c] + b[c];
        dst[(size_t)c*NP + w] = v;
        tile[c][w] = v;
    }
    __syncthreads();
    float2* xw = g_Xw + ((size_t)bn*CC)*HH*MW + h*MW;
    for (int e = threadIdx.x; e < 128*12; e += 256) {
        int c = e / 12, kw = e % 12;
        float re = 0.f, im = 0.f;
#pragma unroll
        for (int w = 0; w < WW; w++) {
            int t = (w*kw) & 31;
            float v = tile[c][w];
            re += v*tc[t];
            im -= v*ts[t];
        }
        xw[(size_t)c*HH*MW + kw] = make_float2(re, im);
    }
}

// partial DFT along H -> z rows, coalesced (8 channels per block)
__global__ void k_sb2() {
    __shared__ float2 Xs[8][HH*MW];
    __shared__ float zr[144][8], zi[144][8];
    __shared__ float tc[32], ts[32];
    if (threadIdx.x < 32) {
        float a = TWO_PI_32 * (float)threadIdx.x;
        tc[threadIdx.x] = cosf(a);
        ts[threadIdx.x] = sinf(a);
    }
    int bn = blockIdx.x >> 4, cg = blockIdx.x & 15;
    const float2* src = g_Xw + ((size_t)(bn*CC + cg*8))*HH*MW;
    for (int e = threadIdx.x; e < 8*HH*MW; e += 256) {
        int c = e / (HH*MW), r = e % (HH*MW);
        Xs[c][r] = src[(size_t)c*HH*MW + r];
    }
    __syncthreads();
    for (int e = threadIdx.x; e < 144*8; e += 256) {
        int m = e >> 3, c = e & 7;
        int kh = m / 12, kw = m % 12;
        float re = 0.f, im = 0.f;
#pragma unroll
        for (int h = 0; h < HH; h++) {
            int t = (kh*h) & 31;
            float2 v = Xs[c][h*MW + kw];
            re += v.x*tc[t] + v.y*ts[t];
            im += v.y*tc[t] - v.x*ts[t];
        }
        zr[m][c] = re * INV32;
        zi[m][c] = im * INV32;
    }
    __syncthreads();
    for (int e = threadIdx.x; e < 144*16; e += 256) {
        int m = e >> 4, j = e & 15;
        size_t rowz = (size_t)(bn*144 + m) * 256;
        if (j < 8) g_zin[rowz + cg*8 + j] = zr[m][j];
        else       g_zin[rowz + 128 + cg*8 + (j-8)] = zi[m][j-8];
    }
}

// inverse DFT along H of delta modes, coalesced (32 channels per block)
__global__ void k_sd2() {
    __shared__ float Dr[144][32], Di[144][32];
    __shared__ float tc[32], ts[32];
    if (threadIdx.x < 32) {
        float a = TWO_PI_32 * (float)threadIdx.x;
        tc[threadIdx.x] = cosf(a);
        ts[threadIdx.x] = sinf(a);
    }
    int bn = blockIdx.x >> 2, cg = blockIdx.x & 3;
    for (int e = threadIdx.x; e < 144*32; e += 256) {
        int m = e >> 5, c = e & 31;
        size_t rowz = (size_t)(bn*144 + m) * 256;
        Dr[m][c] = g_zout[rowz + cg*32 + c];
        Di[m][c] = g_zout[rowz + 128 + cg*32 + c];
    }
    __syncthreads();
    int c = threadIdx.x & 31, hg = threadIdx.x >> 5;
    float2* dst = g_tH + ((size_t)(bn*CC + cg*32 + c))*HH*MW;
#pragma unroll
    for (int hi = 0; hi < 4; hi++) {
        int h = hg*4 + hi;
#pragma unroll
        for (int kw = 0; kw < 12; kw++) {
            float re = 0.f, im = 0.f;
#pragma unroll
            for (int kh = 0; kh < MH; kh++) {
                int t = (kh*h) & 31;
                float dx = Dr[kh*12 + kw][c], dy = Di[kh*12 + kw][c];
                re += dx*tc[t] - dy*ts[t];
                im += dx*ts[t] + dy*tc[t];
            }
            dst[h*MW + kw] = make_float2(re*INV_SQRT32, im*INV_SQRT32);
        }
    }
}

// final c2r along W of delta + out = 2*y3 + ys (parity split)
__global__ void k_se(float* __restrict__ out) {
    __shared__ float tc[32], ts[32];
    if (threadIdx.x < 32) {
        float a = TWO_PI_32 * (float)threadIdx.x;
        tc[threadIdx.x] = cosf(a);
        ts[threadIdx.x] = sinf(a);
    }
    __syncthreads();
    int row = blockIdx.x * blockDim.x + threadIdx.x;   // (bn,c,h)
    if (row >= BNN*CC*HH) return;
    int h = row & 31;
    int c = (row >> 5) & 127;
    int bn = row >> 12;
    float2 T[MW];
    const float2* tp = g_tH + (size_t)row * MW;
#pragma unroll
    for (int kw = 0; kw < MW; kw++) T[kw] = tp[kw];
    const float* yp = g_y3 + (size_t)row * WW;
    int b = bn >> 5, l = bn & 31;
    float* op = out + (((((size_t)b*CC + c)*LL + l)*HH + h)) * WW;
    for (int w = 0; w < 16; w++) {
        float se = T[0].x, so = 0.f;
#pragma unroll
        for (int kw = 1; kw < MW; kw++) {
            int t = (kw*w) & 31;
            float term = 2.f*(T[kw].x*tc[t] - T[kw].y*ts[t]);
            if (kw & 1) so += term; else se += term;
        }
        op[w]      = 2.f*yp[w]      + (se + so)*INV_SQRT32;
        op[w + 16] = 2.f*yp[w + 16] + (se - so)*INV_SQRT32;
    }
}

// ---------------- launch ----------------
static void* symaddr(const void* sym) { void* p = 0; cudaGetSymbolAddress(&p, sym); return p; }

extern "C" void kernel_launch(void* const* d_in, const int* in_sizes, int n_in,
                              void* d_out, int out_size) {
    const float* x      = (const float*)d_in[0];
    const float* dt     = (const float*)d_in[1];
    const float* nu     = (const float*)d_in[2];
    const float* theta  = (const float*)d_in[3];
    const float* ln_g   = (const float*)d_in[4];
    const float* ln_b   = (const float*)d_in[5];
    const float* w_qkv  = (const float*)d_in[6];
    const float* w_proj = (const float*)d_in[7];
    const float* b_proj = (const float*)d_in[8];
    const float* gn_g   = (const float*)d_in[9];
    const float* gn_b   = (const float*)d_in[10];
    const float* w_g    = (const float*)d_in[11];
    const float* w_l    = (const float*)d_in[12];
    const float* w_psi  = (const float*)d_in[13];
    const float* b_psi  = (const float*)d_in[14];
    const float* gate_g = (const float*)d_in[15];
    const float* gate_b = (const float*)d_in[16];
    const float* mix_w  = (const float*)d_in[17];
    const float* mix_b  = (const float*)d_in[18];
    float* out = (float*)d_out;

    float*  p_xt   = (float*)symaddr(g_xt);
    __half* p_xnh  = (__half*)symaddr(g_xnh);
    __half* p_qkvh = (__half*)symaddr(g_qkvh);
    __half* p_aoh  = (__half*)symaddr(g_aoh);
    __half* p_y2nh = (__half*)symaddr(g_y2nh);
    __half* p_gph  = (__half*)symaddr(g_gph);
    __half* p_ggh  = (__half*)symaddr(g_ggh);
    __half* p_lh   = (__half*)symaddr(g_lh);
    float*  p_zin  = (float*)symaddr(g_zin);
    float*  p_zout = (float*)symaddr(g_zout);
    float2* p_st1  = (float2*)symaddr(g_st1);
    float2* p_st2  = (float2*)symaddr(g_st2);
    float*  p_gate = (float*)symaddr(g_gate);

    // stage 1
    k_precompA<<<(BB*LL*CC*WF + 255)/256, 256>>>(dt, nu, theta);
    k_rfft<<<(BB*CC*LL*HH + 127)/128, 128>>>(x);
    k_scan<<<(BB*CC*HH*WF + 255)/256, 256>>>();
    k_irfft<<<(BB*LL*HH*CC)/256, 256>>>();
    // stage 2: LN + attention + proj residual
    k_ln<<<(BNN*NP)/8, 256>>>(ln_g, ln_b);
    k_gemm_h<<<dim3(384/64, (BNN*NP)/64), 128>>>(p_xnh, w_qkv, (const float*)0, (float*)0, p_qkvh, BNN*NP, 384, CC, 0, 1);
    k_fattn<<<BNN*8*8, 128>>>();
    k_gemm_h<<<dim3(CC/64, (BNN*NP)/64), 128>>>(p_aoh, w_proj, b_proj, p_xt, (__half*)0, BNN*NP, CC, CC, 1, 0);
    // stage 3: GN1, gating, GN2
    k_gnstats<<<BNN*4, 256>>>(p_xt, p_st1);
    k_gnapply<<<(BNN*NP*CC)/256, 256>>>(gn_g, gn_b);
    k_pool<<<(BNN*NPC*64)/256, 256>>>();
    k_gemm_h<<<dim3(CC/64, (BNN*NPC)/64), 128>>>(p_gph, w_g, (const float*)0, (float*)0, p_ggh, BNN*NPC, CC, CC, 0, 0);
    k_gemm_h<<<dim3(CC/64, (BNN*NP)/64), 128>>>(p_y2nh, w_l, (const float*)0, (float*)0, p_lh, BNN*NP, CC, CC, 0, 0);
    k_gate<<<(BNN*NP)/8, 256>>>(w_psi, b_psi);
    k_gnstats_h<<<BNN*4, 256>>>(p_y2nh, p_gate, p_st2);
    k_y3t<<<BNN*HH, 256>>>(gate_g, gate_b);
    // stage 4: spectral delta on TC (delta = z(mix_w - I)^T + mix_b)
    k_sb2<<<BNN*16, 256>>>();
    k_gemm_tc<<<dim3(256/64, (BNN*144)/64), 128>>>(p_zin, mix_w, mix_b, p_zout, BNN*144, 256, 256, 0, 1);
    k_sd2<<<BNN*4, 256>>>();
    k_se<<<(BNN*CC*HH)/256, 256>>>(out);
}

// round 9
// speedup vs baseline: 2.9039x; 1.0242x over previous
#include <cuda_runtime.h>
#include <cuda_fp16.h>
#include <math.h>

// ---------------- shapes ----------------
#define BB 2
#define CC 128
#define LL 32
#define HH 32
#define WW 32
#define WF 17
#define BNN 64
#define NP 1024
#define NPC 256
#define MH 12
#define MW 12

#define TWO_PI_32 0.19634954084936207f
#define INV32 0.03125f
#define INV_SQRT32 0.17677669529663687f
#define QK_SCALE 0.36067376022224085f    // 0.25 * log2(e)

// ---------------- device scratch ----------------
__device__ float2 g_xf[BB*CC*LL*HH*WF];
__device__ float2 g_A [BB*LL*CC*WF];
__device__ float  g_xt [BNN*NP*CC];
__device__ __half g_xnh[BNN*NP*CC];
__device__ __half g_qkvh[BNN*NP*384];
__device__ __half g_aoh[BNN*NP*CC];
__device__ __half g_y2nh[BNN*NP*CC];
__device__ __half g_gph[BNN*NPC*CC];
__device__ __half g_ggh[BNN*NPC*CC];
__device__ __half g_lh [BNN*NP*CC];
__device__ float  g_gate[BNN*NP];
__device__ float  g_y3 [BNN*CC*NP];
__device__ float2 g_Xw [BNN*CC*HH*MW];
__device__ float  g_zin [BNN*144*256];
__device__ float  g_zout[BNN*144*256];
__device__ float2 g_tH [BNN*CC*HH*MW];
__device__ float2 g_st2[BNN*4];
__device__ float  g_sacc[512];           // [bn][group][sum,sumsq]

// ---------------- mma helpers ----------------
__device__ __forceinline__ unsigned f2tf32(float f) {
    unsigned r; asm("cvt.rna.tf32.f32 %0, %1;" : "=r"(r) : "f"(f)); return r;
}
__device__ __forceinline__ void mma_tf32(float* c, const unsigned* a, const unsigned* b) {
    asm("mma.sync.aligned.m16n8k8.row.col.f32.tf32.tf32.f32 "
        "{%0,%1,%2,%3}, {%4,%5,%6,%7}, {%8,%9}, {%0,%1,%2,%3};"
        : "+f"(c[0]), "+f"(c[1]), "+f"(c[2]), "+f"(c[3])
        : "r"(a[0]), "r"(a[1]), "r"(a[2]), "r"(a[3]), "r"(b[0]), "r"(b[1]));
}
__device__ __forceinline__ void mma_f16(float* c, const unsigned* a, const unsigned* b) {
    asm("mma.sync.aligned.m16n8k16.row.col.f32.f16.f16.f32 "
        "{%0,%1,%2,%3}, {%4,%5,%6,%7}, {%8,%9}, {%0,%1,%2,%3};"
        : "+f"(c[0]), "+f"(c[1]), "+f"(c[2]), "+f"(c[3])
        : "r"(a[0]), "r"(a[1]), "r"(a[2]), "r"(a[3]), "r"(b[0]), "r"(b[1]));
}
__device__ __forceinline__ unsigned packh2(float a, float b) {
    __half2 h = __floats2half2_rn(a, b);
    return *(unsigned*)&h;
}
__device__ __forceinline__ float ex2a(float x) {
    float r; asm("ex2.approx.f32 %0, %1;" : "=f"(r) : "f"(fminf(x, 80.f))); return r;
}

// ---------------- stage 1: A precompute (+ zero stats accumulators) -------------
__global__ void k_precompA(const float* __restrict__ dt, const float* __restrict__ nu,
                           const float* __restrict__ th) {
    int i = blockIdx.x * blockDim.x + threadIdx.x;
    if (i < 512) g_sacc[i] = 0.f;
    if (i >= BB*LL*CC*WF) return;
    int k = i % WF;
    int c = (i / WF) % CC;
    int l = (i / (WF*CC)) % LL;
    int b =  i / (WF*CC*LL);
    float d  = dt[b*LL + l];
    float e  = expf(-nu[c*WF + k] * d);
    float si, co;
    sincosf(th[c*WF + k] * d, &si, &co);
    g_A[i] = make_float2(e*co, e*si);
}

// ---------------- stage 1: rfft along W ----------------
__global__ void k_rfft(const float* __restrict__ x) {
    __shared__ float tc[32], ts[32];
    if (threadIdx.x < 32) {
        float a = TWO_PI_32 * (float)threadIdx.x;
        tc[threadIdx.x] = cosf(a);
        ts[threadIdx.x] = sinf(a);
    }
    __syncthreads();
    int row = blockIdx.x * blockDim.x + threadIdx.x;   // (b,c,l,h)
    if (row >= BB*CC*LL*HH) return;
    const float* xp = x + (size_t)row * WW;
    float xr[WW];
#pragma unroll
    for (int w = 0; w < WW; w++) xr[w] = xp[w];
    float2* out = g_xf + (size_t)row * WF;
    for (int k = 0; k < WF; k++) {
        float re = 0.f, im = 0.f;
#pragma unroll
        for (int w = 0; w < WW; w++) {
            int t = (w*k) & 31;
            re += xr[w]*tc[t];
            im -= xr[w]*ts[t];
        }
        out[k] = make_float2(re, im);
    }
}

// ---------------- stage 1: complex scan over L ----------------
__global__ void k_scan() {
    int i = blockIdx.x * blockDim.x + threadIdx.x;     // (b,c,h,k)
    if (i >= BB*CC*HH*WF) return;
    int k = i % WF;
    int h = (i / WF) % HH;
    int c = (i / (WF*HH)) % CC;
    int b =  i / (WF*HH*CC);
    size_t xfb = ((((size_t)b*CC + c)*LL)*HH + h)*WF + k;
    const size_t xstr = (size_t)HH*WF;
    size_t ab = ((size_t)b*LL*CC + c)*WF + k;
    const size_t astr = (size_t)CC*WF;
    float2 s = make_float2(0.f, 0.f);
    for (int l = 0; l < LL; l++) {
        float2 a = g_A[ab + (size_t)l*astr];
        float2 u = g_xf[xfb + (size_t)l*xstr];
        float re = a.x*s.x - a.y*s.y + u.x;
        float im = a.x*s.y + a.y*s.x + u.y;
        s = make_float2(re, im);
        g_xf[xfb + (size_t)l*xstr] = s;
    }
}

// ---------------- stage 1: irfft + LayerNorm fused (block per (bn,h)) -----------
// Staged smem reads (near-coalesced), parity-split DFT, in-block LN over C.
__global__ void k_irfft_ln(const float* __restrict__ g, const float* __restrict__ b) {
    __shared__ float sm[128*35];             // S staging, reused as tile[128][33]
    __shared__ float tc[32], ts[32];
    __shared__ float muv[32], rsv[32];
    int bn = blockIdx.x >> 5, h = blockIdx.x & 31;
    int bb = bn >> 5, l = bn & 31;
    int t = threadIdx.x;
    if (t < 32) {
        float a = TWO_PI_32 * (float)t;
        tc[t] = cosf(a);
        ts[t] = sinf(a);
    }
    const float* gx = (const float*)g_xf;
    for (int idx = t; idx < 128*34; idx += 256) {
        int c = idx / 34, f = idx - c*34;
        size_t base = ((((size_t)bb*CC + c)*LL + l)*HH + h)*(size_t)(WF*2);
        sm[c*35 + f] = gx[base + f];
    }
    __syncthreads();
    int c = t & 127, wh = t >> 7;
    float Sr[16], Si[16];
#pragma unroll
    for (int k = 1; k < 16; k++) {
        Sr[k] = sm[c*35 + 2*k];
        Si[k] = sm[c*35 + 2*k + 1];
    }
    float S0 = sm[c*35], S16r = sm[c*35 + 32];
    float vlo[8], vhi[8];
#pragma unroll
    for (int j = 0; j < 8; j++) {
        int w = wh*8 + j;
        float se = S0 + ((w & 1) ? -S16r : S16r);
        float so = 0.f;
#pragma unroll
        for (int k = 1; k < 16; k++) {
            int tt = (w*k) & 31;
            float term = 2.f*(Sr[k]*tc[tt] - Si[k]*ts[tt]);
            if (k & 1) so += term; else se += term;
        }
        vlo[j] = (se + so) * INV32;
        vhi[j] = (se - so) * INV32;
    }
    float* xto = g_xt + ((size_t)bn*NP + h*32)*CC + c;
#pragma unroll
    for (int j = 0; j < 8; j++) {
        xto[(size_t)(wh*8 + j)*CC]      = vlo[j];
        xto[(size_t)(wh*8 + j + 16)*CC] = vhi[j];
    }
    __syncthreads();                          // done with S staging
#pragma unroll
    for (int j = 0; j < 8; j++) {
        sm[c*33 + wh*8 + j]      = vlo[j];
        sm[c*33 + wh*8 + j + 16] = vhi[j];
    }
    __syncthreads();
    // LN: 8 threads per pixel w
    int w = t >> 3, sub = t & 7;
    float s = 0.f, q = 0.f;
#pragma unroll
    for (int i = 0; i < 16; i++) {
        float v = sm[(sub*16 + i)*33 + w];
        s += v; q += v*v;
    }
#pragma unroll
    for (int o = 1; o <= 4; o <<= 1) {
        s += __shfl_xor_sync(0xffffffffu, s, o);
        q += __shfl_xor_sync(0xffffffffu, q, o);
    }
    if (sub == 0) {
        float mu = s * (1.f/128.f);
        muv[w] = mu;
        rsv[w] = rsqrtf(q*(1.f/128.f) - mu*mu + 1e-5f);
    }
    __syncthreads();
    __half* xo = g_xnh + ((size_t)bn*NP + h*32)*CC;
    for (int idx = t; idx < 4096; idx += 256) {
        int cc = idx & 127, ww = idx >> 7;
        float v = (sm[cc*33 + ww] - muv[ww]) * rsv[ww] * g[cc] + b[cc];
        xo[(size_t)ww*CC + cc] = __float2half(v);
    }
}

// ---------------- fp16 TC GEMM: A fp16, B fp32->fp16 on load --------------------
// out: Ch fp16 (optional qscale cols<128) OR Cf fp32 (+bias, optional accum).
// If sacc != 0 (fp32 path): accumulate per-(bn,group) sum/sumsq of outputs.
__global__ void k_gemm_h(const __half* __restrict__ A, const float* __restrict__ B,
                         const float* __restrict__ bias, float* __restrict__ Cf,
                         __half* __restrict__ Ch, float* sacc,
                         int M, int N, int K, int accum, int qscale) {
    __shared__ unsigned As[64*20];
    __shared__ unsigned Bs[64*20];
    __shared__ float wacc[4][4];
    int bm = blockIdx.y << 6, bn = blockIdx.x << 6;
    int warp = threadIdx.x >> 5, lane = threadIdx.x & 31;
    int lr = lane >> 2, lc = lane & 3;
    float acc[8][4];
#pragma unroll
    for (int nf = 0; nf < 8; nf++)
#pragma unroll
        for (int j = 0; j < 4; j++) acc[nf][j] = 0.f;

    for (int k0 = 0; k0 < K; k0 += 32) {
        __syncthreads();
#pragma unroll
        for (int i = 0; i < 2; i++) {
            int slot = threadIdx.x + i*128;
            int m = slot >> 2, seg = (slot & 3) * 4;
            *(uint4*)&As[m*20 + seg] = *(const uint4*)(A + (size_t)(bm+m)*K + k0 + seg*2);
        }
#pragma unroll
        for (int i = 0; i < 4; i++) {
            int slot = threadIdx.x + i*128;
            int m = slot >> 3, seg = (slot & 7) * 4;
            float4 b4 = *(const float4*)(B + (size_t)(bn+m)*K + k0 + seg);
            __half2 h0 = __floats2half2_rn(b4.x, b4.y);
            __half2 h1 = __floats2half2_rn(b4.z, b4.w);
            Bs[m*20 + (seg>>1)]     = *(unsigned*)&h0;
            Bs[m*20 + (seg>>1) + 1] = *(unsigned*)&h1;
        }
        __syncthreads();
#pragma unroll
        for (int ks = 0; ks < 2; ks++) {
            unsigned a[4];
            int am = warp*16;
            a[0] = As[(am+lr  )*20 + ks*8 + lc];
            a[1] = As[(am+lr+8)*20 + ks*8 + lc];
            a[2] = As[(am+lr  )*20 + ks*8 + lc + 4];
            a[3] = As[(am+lr+8)*20 + ks*8 + lc + 4];
#pragma unroll
            for (int nf = 0; nf < 8; nf++) {
                unsigned b[2];
                b[0] = Bs[(nf*8+lr)*20 + ks*8 + lc];
                b[1] = Bs[(nf*8+lr)*20 + ks*8 + lc + 4];
                mma_f16(acc[nf], a, b);
            }
        }
    }
    float sg0 = 0.f, sq0 = 0.f, sg1 = 0.f, sq1 = 0.f;
#pragma unroll
    for (int nf = 0; nf < 8; nf++) {
        int col = bn + nf*8 + lc*2;
        int row = bm + warp*16 + lr;
        if (Ch) {
            float sc = (qscale && col < 128) ? QK_SCALE : 1.f;
            *(__half2*)(Ch + (size_t)row*N + col)     = __floats2half2_rn(acc[nf][0]*sc, acc[nf][1]*sc);
            *(__half2*)(Ch + (size_t)(row+8)*N + col) = __floats2half2_rn(acc[nf][2]*sc, acc[nf][3]*sc);
        } else {
            float b0 = bias ? bias[col] : 0.f;
            float b1 = bias ? bias[col+1] : 0.f;
            float2* p = (float2*)(Cf + (size_t)row*N + col);
            float2 v = make_float2(acc[nf][0]+b0, acc[nf][1]+b1);
            if (accum) { float2 o = *p; v.x += o.x; v.y += o.y; }
            *p = v;
            float2* p2 = (float2*)(Cf + (size_t)(row+8)*N + col);
            float2 v2 = make_float2(acc[nf][2]+b0, acc[nf][3]+b1);
            if (accum) { float2 o = *p2; v2.x += o.x; v2.y += o.y; }
            *p2 = v2;
            if (sacc) {
                float sv = v.x + v.y + v2.x + v2.y;
                float qv = v.x*v.x + v.y*v.y + v2.x*v2.x + v2.y*v2.y;
                if (nf < 4) { sg0 += sv; sq0 += qv; } else { sg1 += sv; sq1 += qv; }
            }
        }
    }
    if (sacc) {
#pragma unroll
        for (int o = 16; o; o >>= 1) {
            sg0 += __shfl_xor_sync(0xffffffffu, sg0, o);
            sq0 += __shfl_xor_sync(0xffffffffu, sq0, o);
            sg1 += __shfl_xor_sync(0xffffffffu, sg1, o);
            sq1 += __shfl_xor_sync(0xffffffffu, sq1, o);
        }
        if (lane == 0) {
            wacc[warp][0] = sg0; wacc[warp][1] = sq0;
            wacc[warp][2] = sg1; wacc[warp][3] = sq1;
        }
        __syncthreads();
        if (threadIdx.x == 0) {
            float a0 = 0.f, a1 = 0.f, a2 = 0.f, a3 = 0.f;
#pragma unroll
            for (int wi = 0; wi < 4; wi++) {
                a0 += wacc[wi][0]; a1 += wacc[wi][1];
                a2 += wacc[wi][2]; a3 += wacc[wi][3];
            }
            int bni = bm >> 10;
            int gb = bn >> 5;
            atomicAdd(&sacc[bni*8 + (gb  )*2    ], a0);
            atomicAdd(&sacc[bni*8 + (gb  )*2 + 1], a1);
            atomicAdd(&sacc[bni*8 + (gb+1)*2    ], a2);
            atomicAdd(&sacc[bni*8 + (gb+1)*2 + 1], a3);
        }
    }
}

// ---------------- tf32 TC GEMM (mix delta): C = A*(B - subI*I)^T (+bias) --------
__global__ void k_gemm_tc(const float* __restrict__ A, const float* __restrict__ B,
                          const float* __restrict__ bias, float* __restrict__ C,
                          int M, int N, int K, int accum, int subI) {
    __shared__ unsigned As[64*36];
    __shared__ unsigned Bs[64*36];
    int bm = blockIdx.y << 6, bn = blockIdx.x << 6;
    int warp = threadIdx.x >> 5, lane = threadIdx.x & 31;
    int lr = lane >> 2, lc = lane & 3;
    float acc[8][4];
#pragma unroll
    for (int nf = 0; nf < 8; nf++)
#pragma unroll
        for (int j = 0; j < 4; j++) acc[nf][j] = 0.f;

    for (int k0 = 0; k0 < K; k0 += 32) {
        __syncthreads();
#pragma unroll
        for (int i = 0; i < 4; i++) {
            int slot = threadIdx.x + i*128;
            int m = slot >> 3, seg = (slot & 7) << 2;
            float4 a4 = *(const float4*)(A + (size_t)(bm+m)*K + k0 + seg);
            *(uint4*)&As[m*36 + seg] = make_uint4(f2tf32(a4.x), f2tf32(a4.y), f2tf32(a4.z), f2tf32(a4.w));
            float4 b4 = *(const float4*)(B + (size_t)(bn+m)*K + k0 + seg);
            if (subI) {
                int row = bn + m, col = k0 + seg;
                if (row == col    ) b4.x -= 1.f;
                if (row == col + 1) b4.y -= 1.f;
                if (row == col + 2) b4.z -= 1.f;
                if (row == col + 3) b4.w -= 1.f;
            }
            *(uint4*)&Bs[m*36 + seg] = make_uint4(f2tf32(b4.x), f2tf32(b4.y), f2tf32(b4.z), f2tf32(b4.w));
        }
        __syncthreads();
#pragma unroll
        for (int ks = 0; ks < 4; ks++) {
            unsigned a[4];
            int am = warp*16;
            a[0] = As[(am+lr  )*36 + ks*8 + lc];
            a[1] = As[(am+lr+8)*36 + ks*8 + lc];
            a[2] = As[(am+lr  )*36 + ks*8 + lc + 4];
            a[3] = As[(am+lr+8)*36 + ks*8 + lc + 4];
#pragma unroll
            for (int nf = 0; nf < 8; nf++) {
                unsigned b[2];
                b[0] = Bs[(nf*8+lr)*36 + ks*8 + lc];
                b[1] = Bs[(nf*8+lr)*36 + ks*8 + lc + 4];
                mma_tf32(acc[nf], a, b);
            }
        }
    }
#pragma unroll
    for (int nf = 0; nf < 8; nf++) {
        int col = bn + nf*8 + lc*2;
        float b0 = bias ? bias[col] : 0.f;
        float b1 = bias ? bias[col+1] : 0.f;
        int row = bm + warp*16 + lr;
        float2* p = (float2*)(C + (size_t)row*N + col);
        float2 v = make_float2(acc[nf][0]+b0, acc[nf][1]+b1);
        if (accum) { float2 o = *p; v.x += o.x; v.y += o.y; }
        *p = v;
        p = (float2*)(C + (size_t)(row+8)*N + col);
        v = make_float2(acc[nf][2]+b0, acc[nf][3]+b1);
        if (accum) { float2 o = *p; v.x += o.x; v.y += o.y; }
        *p = v;
    }
}

// ---------------- flash attention: all-fp16 mma, 256-query tiles ----------------
__global__ void k_fattn() {
    __shared__ __half Ks[64][24];
    __shared__ __half Vt[16][72];
    int blk = blockIdx.x;                   // qt + 4*(head + 8*bn)
    int qt = blk & 3, head = (blk >> 2) & 7, bn = blk >> 5;
    int warp = threadIdx.x >> 5, lane = threadIdx.x & 31;
    int lr = lane >> 2, lc = lane & 3;
    int q0 = qt*256 + warp*32;
    const __half* qkb = g_qkvh + (size_t)bn*NP*384 + head*16;

    unsigned Qa[2][4];
#pragma unroll
    for (int mt = 0; mt < 2; mt++) {
        const __half* qp = qkb + (size_t)(q0 + mt*16)*384;
        Qa[mt][0] = *(const unsigned*)(qp + (size_t)(lr  )*384 + 2*lc);
        Qa[mt][1] = *(const unsigned*)(qp + (size_t)(lr+8)*384 + 2*lc);
        Qa[mt][2] = *(const unsigned*)(qp + (size_t)(lr  )*384 + 2*lc + 8);
        Qa[mt][3] = *(const unsigned*)(qp + (size_t)(lr+8)*384 + 2*lc + 8);
    }

    float lsum[2][2] = {{0.f,0.f},{0.f,0.f}};
    float Oa[2][2][4];
#pragma unroll
    for (int mt = 0; mt < 2; mt++)
#pragma unroll
        for (int dn = 0; dn < 2; dn++)
#pragma unroll
            for (int j = 0; j < 4; j++) Oa[mt][dn][j] = 0.f;

    for (int c0 = 0; c0 < NP; c0 += 64) {
        __syncthreads();
        {
            int tt = threadIdx.x & 127;
            int key = tt >> 1, seg = (tt & 1) * 8;
            const __half* kp = qkb + (size_t)(c0 + key)*384 + 128 + seg;
            if (threadIdx.x < 128) {
                *(uint4*)&Ks[key][seg] = *(const uint4*)kp;
            } else {
                uint4 vv = *(const uint4*)(kp + 128);
                __half vh[8];
                *(uint4*)vh = vv;
#pragma unroll
                for (int j = 0; j < 8; j++) Vt[seg + j][key] = vh[j];
            }
        }
        __syncthreads();

        float S[2][8][4];
#pragma unroll
        for (int mt = 0; mt < 2; mt++)
#pragma unroll
            for (int nf = 0; nf < 8; nf++) {
                S[mt][nf][0] = S[mt][nf][1] = S[mt][nf][2] = S[mt][nf][3] = 0.f;
                unsigned b[2];
                b[0] = *(const unsigned*)&Ks[nf*8 + lr][2*lc];
                b[1] = *(const unsigned*)&Ks[nf*8 + lr][2*lc + 8];
                mma_f16(S[mt][nf], Qa[mt], b);
            }

#pragma unroll
        for (int mt = 0; mt < 2; mt++)
#pragma unroll
            for (int nf = 0; nf < 8; nf++) {
                S[mt][nf][0] = ex2a(S[mt][nf][0]);
                S[mt][nf][1] = ex2a(S[mt][nf][1]);
                S[mt][nf][2] = ex2a(S[mt][nf][2]);
                S[mt][nf][3] = ex2a(S[mt][nf][3]);
                lsum[mt][0] += S[mt][nf][0] + S[mt][nf][1];
                lsum[mt][1] += S[mt][nf][2] + S[mt][nf][3];
            }

#pragma unroll
        for (int mt = 0; mt < 2; mt++)
#pragma unroll
            for (int j = 0; j < 4; j++) {
                unsigned a[4];
                a[0] = packh2(S[mt][2*j  ][0], S[mt][2*j  ][1]);
                a[1] = packh2(S[mt][2*j  ][2], S[mt][2*j  ][3]);
                a[2] = packh2(S[mt][2*j+1][0], S[mt][2*j+1][1]);
                a[3] = packh2(S[mt][2*j+1][2], S[mt][2*j+1][3]);
#pragma unroll
                for (int dn = 0; dn < 2; dn++) {
                    unsigned b[2];
                    b[0] = *(const unsigned*)&Vt[dn*8 + lr][j*16 + lc*2];
                    b[1] = *(const unsigned*)&Vt[dn*8 + lr][j*16 + lc*2 + 8];
                    mma_f16(Oa[mt][dn], a, b);
                }
            }
    }

#pragma unroll
    for (int mt = 0; mt < 2; mt++)
#pragma unroll
        for (int o = 1; o <= 2; o <<= 1) {
            lsum[mt][0] += __shfl_xor_sync(0xffffffffu, lsum[mt][0], o);
            lsum[mt][1] += __shfl_xor_sync(0xffffffffu, lsum[mt][1], o);
        }
    __half* ob = g_aoh + (size_t)bn*NP*CC + head*16;
#pragma unroll
    for (int mt = 0; mt < 2; mt++) {
        float inv0 = 1.f / lsum[mt][0], inv1 = 1.f / lsum[mt][1];
        int qr = q0 + mt*16;
#pragma unroll
        for (int dn = 0; dn < 2; dn++) {
            int col = dn*8 + lc*2;
            *(__half2*)(ob + (size_t)(qr+lr  )*CC + col) = __floats2half2_rn(Oa[mt][dn][0]*inv0, Oa[mt][dn][1]*inv0);
            *(__half2*)(ob + (size_t)(qr+lr+8)*CC + col) = __floats2half2_rn(Oa[mt][dn][2]*inv1, Oa[mt][dn][3]*inv1);
        }
    }
}

// ---------------- GN1 apply + 2x2 pool fused (stats from g_sacc) ----------------
__global__ void k_gnpool(const float* __restrict__ gg, const float* __restrict__ gb) {
    int bn = blockIdx.x >> 4, hp = blockIdx.x & 15;
    float mu[4], rs[4];
#pragma unroll
    for (int g = 0; g < 4; g++) {
        float s = g_sacc[bn*8 + g*2], q = g_sacc[bn*8 + g*2 + 1];
        float m = s * (1.f/32768.f);
        mu[g] = m;
        rs[g] = rsqrtf(q*(1.f/32768.f) - m*m + 1e-5f);
    }
    for (int idx = threadIdx.x; idx < 2048; idx += 256) {
        int wp = idx >> 7, c = idx & 127;
        int g = c >> 5;
        float ga = gg[c]*rs[g], bb2 = gb[c], m = mu[g];
        size_t a00 = ((size_t)bn*NP + hp*64 + wp*2)*CC + c;
        float y00 = (g_xt[a00]         - m)*ga + bb2;
        float y01 = (g_xt[a00 + CC]    - m)*ga + bb2;
        float y10 = (g_xt[a00 + 32*CC] - m)*ga + bb2;
        float y11 = (g_xt[a00 + 33*CC] - m)*ga + bb2;
        g_y2nh[a00]         = __float2half(y00);
        g_y2nh[a00 + CC]    = __float2half(y01);
        g_y2nh[a00 + 32*CC] = __float2half(y10);
        g_y2nh[a00 + 33*CC] = __float2half(y11);
        g_gph[((size_t)bn*NPC + hp*16 + wp)*CC + c] = __float2half(0.25f*(y00+y01+y10+y11));
    }
}

// ---------------- GroupNorm stats: fp16 input x gate ----------------
__global__ void k_gnstats_h(const __half* __restrict__ X, const float* __restrict__ gate,
                            float2* __restrict__ stats) {
    __shared__ float sh[256], sh2[256];
    int bn = blockIdx.x >> 2, g = blockIdx.x & 3;
    float s = 0.f, q = 0.f;
    const __half* base = X + (size_t)bn*NP*CC + g*32;
    for (int e = threadIdx.x; e < 32768; e += 256) {
        int n = e >> 5, cc = e & 31;
        float v = __half2float(base[(size_t)n*CC + cc]) * gate[bn*NP + n];
        s += v; q += v*v;
    }
    sh[threadIdx.x] = s; sh2[threadIdx.x] = q;
    __syncthreads();
    for (int o = 128; o; o >>= 1) {
        if (threadIdx.x < o) { sh[threadIdx.x] += sh[threadIdx.x+o]; sh2[threadIdx.x] += sh2[threadIdx.x+o]; }
        __syncthreads();
    }
    if (threadIdx.x == 0) {
        float mu = sh[0] * (1.f/32768.f);
        float var = sh2[0] * (1.f/32768.f) - mu*mu;
        stats[blockIdx.x] = make_float2(mu, rsqrtf(var + 1e-5f));
    }
}

__global__ void k_gate(const float* __restrict__ w_psi, const float* __restrict__ b_psi) {
    int lane = threadIdx.x & 31, wid = threadIdx.x >> 5;
    int p = blockIdx.x*8 + wid;
    int bn = p >> 10, n = p & 1023;
    int h = n >> 5, w = n & 31;
    int pc = (h >> 1)*16 + (w >> 1);
    const __half2* gp2 = (const __half2*)(g_ggh + ((size_t)bn*NPC + pc)*CC);
    const __half2* lp2 = (const __half2*)(g_lh + (size_t)p*CC);
    float2 ga = __half22float2(gp2[lane*2]),   gb = __half22float2(gp2[lane*2+1]);
    float2 la = __half22float2(lp2[lane*2]),   lb = __half22float2(lp2[lane*2+1]);
    float4 wp = ((const float4*)w_psi)[lane];
    float s = fmaxf(ga.x+la.x, 0.f)*wp.x + fmaxf(ga.y+la.y, 0.f)*wp.y
            + fmaxf(gb.x+lb.x, 0.f)*wp.z + fmaxf(gb.y+lb.y, 0.f)*wp.w;
#pragma unroll
    for (int o = 16; o; o >>= 1) s += __shfl_xor_sync(0xffffffffu, s, o);
    if (lane == 0) g_gate[p] = 1.f/(1.f + expf(-(s + b_psi[0])));
}

// gated GN2 + transpose to channels-first + partial W-DFT (fused)
__global__ void k_y3t(const float* __restrict__ g, const float* __restrict__ b) {
    __shared__ float tile[128][33];
    __shared__ float gts[32];
    __shared__ float tc[32], ts[32];
    int bn = blockIdx.x >> 5, h = blockIdx.x & 31;
    if (threadIdx.x < 32) {
        gts[threadIdx.x] = g_gate[bn*NP + h*32 + threadIdx.x];
        float a = TWO_PI_32 * (float)threadIdx.x;
        tc[threadIdx.x] = cosf(a);
        ts[threadIdx.x] = sinf(a);
    }
    __syncthreads();
    const __half* src = g_y2nh + ((size_t)bn*NP + h*32)*CC;
#pragma unroll
    for (int it = 0; it < 16; it++) {
        int idx = threadIdx.x + it*256;
        int w = idx >> 7, c = idx & 127;
        tile[c][w] = __half2float(src[(size_t)w*CC + c]) * gts[w];
    }
    __syncthreads();
    float* dst = g_y3 + (size_t)bn*CC*NP + h*32;
#pragma unroll
    for (int it = 0; it < 16; it++) {
        int idx = threadIdx.x + it*256;
        int c = idx >> 5, w = idx & 31;
        float2 st = g_st2[bn*4 + (c >> 5)];
        float v = (tile[c][w] - st.x)*st.y*g[c] + b[c];
        dst[(size_t)c*NP + w] = v;
        tile[c][w] = v;
    }
    __syncthreads();
    float2* xw = g_Xw + ((size_t)bn*CC)*HH*MW + h*MW;
    for (int e = threadIdx.x; e < 128*12; e += 256) {
        int c = e / 12, kw = e % 12;
        float re = 0.f, im = 0.f;
#pragma unroll
        for (int w = 0; w < WW; w++) {
            int t = (w*kw) & 31;
            float v = tile[c][w];
            re += v*tc[t];
            im -= v*ts[t];
        }
        xw[(size_t)c*HH*MW + kw] = make_float2(re, im);
    }
}

// partial DFT along H -> z rows, coalesced (8 channels per block)
__global__ void k_sb2() {
    __shared__ float2 Xs[8][HH*MW];
    __shared__ float zr[144][8], zi[144][8];
    __shared__ float tc[32], ts[32];
    if (threadIdx.x < 32) {
        float a = TWO_PI_32 * (float)threadIdx.x;
        tc[threadIdx.x] = cosf(a);
        ts[threadIdx.x] = sinf(a);
    }
    int bn = blockIdx.x >> 4, cg = blockIdx.x & 15;
    const float2* src = g_Xw + ((size_t)(bn*CC + cg*8))*HH*MW;
    for (int e = threadIdx.x; e < 8*HH*MW; e += 256) {
        int c = e / (HH*MW), r = e % (HH*MW);
        Xs[c][r] = src[(size_t)c*HH*MW + r];
    }
    __syncthreads();
    for (int e = threadIdx.x; e < 144*8; e += 256) {
        int m = e >> 3, c = e & 7;
        int kh = m / 12, kw = m % 12;
        float re = 0.f, im = 0.f;
#pragma unroll
        for (int h = 0; h < HH; h++) {
            int t = (kh*h) & 31;
            float2 v = Xs[c][h*MW + kw];
            re += v.x*tc[t] + v.y*ts[t];
            im += v.y*tc[t] - v.x*ts[t];
        }
        zr[m][c] = re * INV32;
        zi[m][c] = im * INV32;
    }
    __syncthreads();
    for (int e = threadIdx.x; e < 144*16; e += 256) {
        int m = e >> 4, j = e & 15;
        size_t rowz = (size_t)(bn*144 + m) * 256;
        if (j < 8) g_zin[rowz + cg*8 + j] = zr[m][j];
        else       g_zin[rowz + 128 + cg*8 + (j-8)] = zi[m][j-8];
    }
}

// inverse DFT along H of delta modes, coalesced (32 channels per block)
__global__ void k_sd2() {
    __shared__ float Dr[144][32], Di[144][32];
    __shared__ float tc[32], ts[32];
    if (threadIdx.x < 32) {
        float a = TWO_PI_32 * (float)threadIdx.x;
        tc[threadIdx.x] = cosf(a);
        ts[threadIdx.x] = sinf(a);
    }
    int bn = blockIdx.x >> 2, cg = blockIdx.x & 3;
    for (int e = threadIdx.x; e < 144*32; e += 256) {
        int m = e >> 5, c = e & 31;
        size_t rowz = (size_t)(bn*144 + m) * 256;
        Dr[m][c] = g_zout[rowz + cg*32 + c];
        Di[m][c] = g_zout[rowz + 128 + cg*32 + c];
    }
    __syncthreads();
    int c = threadIdx.x & 31, hg = threadIdx.x >> 5;
    float2* dst = g_tH + ((size_t)(bn*CC + cg*32 + c))*HH*MW;
#pragma unroll
    for (int hi = 0; hi < 4; hi++) {
        int h = hg*4 + hi;
#pragma unroll
        for (int kw = 0; kw < 12; kw++) {
            float re = 0.f, im = 0.f;
#pragma unroll
            for (int kh = 0; kh < MH; kh++) {
                int t = (kh*h) & 31;
                float dx = Dr[kh*12 + kw][c], dy = Di[kh*12 + kw][c];
                re += dx*tc[t] - dy*ts[t];
                im += dx*ts[t] + dy*tc[t];
            }
            dst[h*MW + kw] = make_float2(re*INV_SQRT32, im*INV_SQRT32);
        }
    }
}

// final c2r along W of delta + out = 2*y3 + ys (parity split)
__global__ void k_se(float* __restrict__ out) {
    __shared__ float tc[32], ts[32];
    if (threadIdx.x < 32) {
        float a = TWO_PI_32 * (float)threadIdx.x;
        tc[threadIdx.x] = cosf(a);
        ts[threadIdx.x] = sinf(a);
    }
    __syncthreads();
    int row = blockIdx.x * blockDim.x + threadIdx.x;   // (bn,c,h)
    if (row >= BNN*CC*HH) return;
    int h = row & 31;
    int c = (row >> 5) & 127;
    int bn = row >> 12;
    float2 T[MW];
    const float2* tp = g_tH + (size_t)row * MW;
#pragma unroll
    for (int kw = 0; kw < MW; kw++) T[kw] = tp[kw];
    const float* yp = g_y3 + (size_t)row * WW;
    int b = bn >> 5, l = bn & 31;
    float* op = out + (((((size_t)b*CC + c)*LL + l)*HH + h)) * WW;
    for (int w = 0; w < 16; w++) {
        float se = T[0].x, so = 0.f;
#pragma unroll
        for (int kw = 1; kw < MW; kw++) {
            int t = (kw*w) & 31;
            float term = 2.f*(T[kw].x*tc[t] - T[kw].y*ts[t]);
            if (kw & 1) so += term; else se += term;
        }
        op[w]      = 2.f*yp[w]      + (se + so)*INV_SQRT32;
        op[w + 16] = 2.f*yp[w + 16] + (se - so)*INV_SQRT32;
    }
}

// ---------------- launch ----------------
static void* symaddr(const void* sym) { void* p = 0; cudaGetSymbolAddress(&p, sym); return p; }

extern "C" void kernel_launch(void* const* d_in, const int* in_sizes, int n_in,
                              void* d_out, int out_size) {
    const float* x      = (const float*)d_in[0];
    const float* dt     = (const float*)d_in[1];
    const float* nu     = (const float*)d_in[2];
    const float* theta  = (const float*)d_in[3];
    const float* ln_g   = (const float*)d_in[4];
    const float* ln_b   = (const float*)d_in[5];
    const float* w_qkv  = (const float*)d_in[6];
    const float* w_proj = (const float*)d_in[7];
    const float* b_proj = (const float*)d_in[8];
    const float* gn_g   = (const float*)d_in[9];
    const float* gn_b   = (const float*)d_in[10];
    const float* w_g    = (const float*)d_in[11];
    const float* w_l    = (const float*)d_in[12];
    const float* w_psi  = (const float*)d_in[13];
    const float* b_psi  = (const float*)d_in[14];
    const float* gate_g = (const float*)d_in[15];
    const float* gate_b = (const float*)d_in[16];
    const float* mix_w  = (const float*)d_in[17];
    const float* mix_b  = (const float*)d_in[18];
    float* out = (float*)d_out;

    float*  p_xt   = (float*)symaddr(g_xt);
    __half* p_xnh  = (__half*)symaddr(g_xnh);
    __half* p_qkvh = (__half*)symaddr(g_qkvh);
    __half* p_aoh  = (__half*)symaddr(g_aoh);
    __half* p_y2nh = (__half*)symaddr(g_y2nh);
    __half* p_gph  = (__half*)symaddr(g_gph);
    __half* p_ggh  = (__half*)symaddr(g_ggh);
    __half* p_lh   = (__half*)symaddr(g_lh);
    float*  p_zin  = (float*)symaddr(g_zin);
    float*  p_zout = (float*)symaddr(g_zout);
    float2* p_st2  = (float2*)symaddr(g_st2);
    float*  p_gate = (float*)symaddr(g_gate);
    float*  p_sacc = (float*)symaddr(g_sacc);

    // stage 1
    k_precompA<<<(BB*LL*CC*WF + 255)/256, 256>>>(dt, nu, theta);
    k_rfft<<<(BB*CC*LL*HH + 127)/128, 128>>>(x);
    k_scan<<<(BB*CC*HH*WF + 255)/256, 256>>>();
    k_irfft_ln<<<BNN*HH, 256>>>(ln_g, ln_b);
    // stage 2: attention + proj residual (stats fused into proj epilogue)
    k_gemm_h<<<dim3(384/64, (BNN*NP)/64), 128>>>(p_xnh, w_qkv, (const float*)0, (float*)0, p_qkvh, (float*)0, BNN*NP, 384, CC, 0, 1);
    k_fattn<<<BNN*8*4, 256>>>();
    k_gemm_h<<<dim3(CC/64, (BNN*NP)/64), 128>>>(p_aoh, w_proj, b_proj, p_xt, (__half*)0, p_sacc, BNN*NP, CC, CC, 1, 0);
    // stage 3: GN1+pool fused, gating, GN2
    k_gnpool<<<BNN*16, 256>>>(gn_g, gn_b);
    k_gemm_h<<<dim3(CC/64, (BNN*NPC)/64), 128>>>(p_gph, w_g, (const float*)0, (float*)0, p_ggh, (float*)0, BNN*NPC, CC, CC, 0, 0);
    k_gemm_h<<<dim3(CC/64, (BNN*NP)/64), 128>>>(p_y2nh, w_l, (const float*)0, (float*)0, p_lh, (float*)0, BNN*NP, CC, CC, 0, 0);
    k_gate<<<(BNN*NP)/8, 256>>>(w_psi, b_psi);
    k_gnstats_h<<<BNN*4, 256>>>(p_y2nh, p_gate, p_st2);
    k_y3t<<<BNN*HH, 256>>>(gate_g, gate_b);
    // stage 4: spectral delta on TC (delta = z(mix_w - I)^T + mix_b)
    k_sb2<<<BNN*16, 256>>>();
    k_gemm_tc<<<dim3(256/64, (BNN*144)/64), 128>>>(p_zin, mix_w, mix_b, p_zout, BNN*144, 256, 256, 0, 1);
    k_sd2<<<BNN*4, 256>>>();
    k_se<<<(BNN*CC*HH)/256, 256>>>(out);
}

// round 10
// speedup vs baseline: 2.9735x; 1.0240x over previous
#include <cuda_runtime.h>
#include <cuda_fp16.h>
#include <math.h>

// ---------------- shapes ----------------
#define BB 2
#define CC 128
#define LL 32
#define HH 32
#define WW 32
#define WF 17
#define BNN 64
#define NP 1024
#define NPC 256
#define MH 12
#define MW 12

#define TWO_PI_32 0.19634954084936207f
#define INV32 0.03125f
#define INV_SQRT32 0.17677669529663687f
#define QK_SCALE 0.36067376022224085f    // 0.25 * log2(e)

// ---------------- device scratch ----------------
__device__ float2 g_xf[BB*CC*LL*HH*WF];
__device__ float2 g_A [BB*LL*CC*WF];
__device__ float  g_xt [BNN*NP*CC];
__device__ __half g_xnh[BNN*NP*CC];
__device__ __half g_qkvh[BNN*NP*384];
__device__ __half g_aoh[BNN*NP*CC];
__device__ __half g_y2nh[BNN*NP*CC];
__device__ __half g_gph[BNN*NPC*CC];
__device__ __half g_ggh[BNN*NPC*CC];
__device__ __half g_lh [BNN*NP*CC];
__device__ float  g_gate[BNN*NP];
__device__ float  g_y3 [BNN*CC*NP];
__device__ float2 g_Xw [BNN*CC*HH*MW];
__device__ float  g_zin [BNN*144*256];
__device__ float  g_zout[BNN*144*256];
__device__ float2 g_tH [BNN*CC*HH*MW];
__device__ float2 g_st2[BNN*4];
__device__ float  g_sacc[512];           // [bn][group][sum,sumsq]

// ---------------- mma helpers ----------------
__device__ __forceinline__ unsigned f2tf32(float f) {
    unsigned r; asm("cvt.rna.tf32.f32 %0, %1;" : "=r"(r) : "f"(f)); return r;
}
__device__ __forceinline__ void mma_tf32(float* c, const unsigned* a, const unsigned* b) {
    asm("mma.sync.aligned.m16n8k8.row.col.f32.tf32.tf32.f32 "
        "{%0,%1,%2,%3}, {%4,%5,%6,%7}, {%8,%9}, {%0,%1,%2,%3};"
        : "+f"(c[0]), "+f"(c[1]), "+f"(c[2]), "+f"(c[3])
        : "r"(a[0]), "r"(a[1]), "r"(a[2]), "r"(a[3]), "r"(b[0]), "r"(b[1]));
}
__device__ __forceinline__ void mma_f16(float* c, const unsigned* a, const unsigned* b) {
    asm("mma.sync.aligned.m16n8k16.row.col.f32.f16.f16.f32 "
        "{%0,%1,%2,%3}, {%4,%5,%6,%7}, {%8,%9}, {%0,%1,%2,%3};"
        : "+f"(c[0]), "+f"(c[1]), "+f"(c[2]), "+f"(c[3])
        : "r"(a[0]), "r"(a[1]), "r"(a[2]), "r"(a[3]), "r"(b[0]), "r"(b[1]));
}
__device__ __forceinline__ unsigned packh2(float a, float b) {
    __half2 h = __floats2half2_rn(a, b);
    return *(unsigned*)&h;
}
__device__ __forceinline__ float ex2a(float x) {
    float r; asm("ex2.approx.f32 %0, %1;" : "=f"(r) : "f"(fminf(x, 80.f))); return r;
}

// ---------------- stage 1: A precompute (+ zero stats accumulators) -------------
__global__ void k_precompA(const float* __restrict__ dt, const float* __restrict__ nu,
                           const float* __restrict__ th) {
    int i = blockIdx.x * blockDim.x + threadIdx.x;
    if (i < 512) g_sacc[i] = 0.f;
    if (i >= BB*LL*CC*WF) return;
    int k = i % WF;
    int c = (i / WF) % CC;
    int l = (i / (WF*CC)) % LL;
    int b =  i / (WF*CC*LL);
    float d  = dt[b*LL + l];
    float e  = expf(-nu[c*WF + k] * d);
    float si, co;
    sincosf(th[c*WF + k] * d, &si, &co);
    g_A[i] = make_float2(e*co, e*si);
}

// ---------------- stage 1: rfft along W ----------------
__global__ void k_rfft(const float* __restrict__ x) {
    __shared__ float tc[32], ts[32];
    if (threadIdx.x < 32) {
        float a = TWO_PI_32 * (float)threadIdx.x;
        tc[threadIdx.x] = cosf(a);
        ts[threadIdx.x] = sinf(a);
    }
    __syncthreads();
    int row = blockIdx.x * blockDim.x + threadIdx.x;   // (b,c,l,h)
    if (row >= BB*CC*LL*HH) return;
    const float* xp = x + (size_t)row * WW;
    float xr[WW];
#pragma unroll
    for (int w = 0; w < WW; w++) xr[w] = xp[w];
    float2* out = g_xf + (size_t)row * WF;
    for (int k = 0; k < WF; k++) {
        float re = 0.f, im = 0.f;
#pragma unroll
        for (int w = 0; w < WW; w++) {
            int t = (w*k) & 31;
            re += xr[w]*tc[t];
            im -= xr[w]*ts[t];
        }
        out[k] = make_float2(re, im);
    }
}

// ---------------- stage 1: complex scan over L ----------------
__global__ void k_scan() {
    int i = blockIdx.x * blockDim.x + threadIdx.x;     // (b,c,h,k)
    if (i >= BB*CC*HH*WF) return;
    int k = i % WF;
    int h = (i / WF) % HH;
    int c = (i / (WF*HH)) % CC;
    int b =  i / (WF*HH*CC);
    size_t xfb = ((((size_t)b*CC + c)*LL)*HH + h)*WF + k;
    const size_t xstr = (size_t)HH*WF;
    size_t ab = ((size_t)b*LL*CC + c)*WF + k;
    const size_t astr = (size_t)CC*WF;
    float2 s = make_float2(0.f, 0.f);
    for (int l = 0; l < LL; l++) {
        float2 a = g_A[ab + (size_t)l*astr];
        float2 u = g_xf[xfb + (size_t)l*xstr];
        float re = a.x*s.x - a.y*s.y + u.x;
        float im = a.x*s.y + a.y*s.x + u.y;
        s = make_float2(re, im);
        g_xf[xfb + (size_t)l*xstr] = s;
    }
}

// ---------------- stage 1: irfft -> xt channels-last (parity split) -------------
__global__ void k_irfft() {
    __shared__ float tc[32], ts[32];
    if (threadIdx.x < 32) {
        float a = TWO_PI_32 * (float)threadIdx.x;
        tc[threadIdx.x] = cosf(a);
        ts[threadIdx.x] = sinf(a);
    }
    __syncthreads();
    int i = blockIdx.x * blockDim.x + threadIdx.x;     // (b,l,h,c)
    if (i >= BB*LL*HH*CC) return;
    int c = i & 127;
    int h = (i >> 7) & 31;
    int l = (i >> 12) & 31;
    int b =  i >> 17;
    const float2* st = g_xf + ((((size_t)b*CC + c)*LL + l)*HH + h)*WF;
    float2 S[WF];
#pragma unroll
    for (int k = 0; k < WF; k++) S[k] = st[k];
    int bn = b*LL + l;
    float* out = g_xt + ((size_t)bn*NP + h*WW)*CC + c;
    for (int w = 0; w < 16; w++) {
        float se = S[0].x + ((w & 1) ? -S[16].x : S[16].x);
        float so = 0.f;
#pragma unroll
        for (int k = 1; k < 16; k++) {
            int t = (w*k) & 31;
            float term = 2.f*(S[k].x*tc[t] - S[k].y*ts[t]);
            if (k & 1) so += term; else se += term;
        }
        out[(size_t)w*CC]      = (se + so) * INV32;
        out[(size_t)(w+16)*CC] = (se - so) * INV32;
    }
}

// ---------------- LayerNorm over C -> fp16 ----------------
__global__ void k_ln(const float* __restrict__ g, const float* __restrict__ b) {
    int lane = threadIdx.x & 31, wid = threadIdx.x >> 5;
    int r = blockIdx.x*8 + wid;
    float4 v = ((const float4*)(g_xt + (size_t)r*CC))[lane];
    float s = v.x + v.y + v.z + v.w;
#pragma unroll
    for (int o = 16; o; o >>= 1) s += __shfl_xor_sync(0xffffffffu, s, o);
    float mu = s * (1.f/128.f);
    float dx = v.x-mu, dy = v.y-mu, dz = v.z-mu, dw = v.w-mu;
    float q = dx*dx + dy*dy + dz*dz + dw*dw;
#pragma unroll
    for (int o = 16; o; o >>= 1) q += __shfl_xor_sync(0xffffffffu, q, o);
    float rstd = rsqrtf(q*(1.f/128.f) + 1e-5f);
    float4 g4 = ((const float4*)g)[lane];
    float4 b4 = ((const float4*)b)[lane];
    __half2* op = (__half2*)(g_xnh + (size_t)r*CC);
    op[lane*2]   = __floats2half2_rn(dx*rstd*g4.x + b4.x, dy*rstd*g4.y + b4.y);
    op[lane*2+1] = __floats2half2_rn(dz*rstd*g4.z + b4.z, dw*rstd*g4.w + b4.w);
}

// ---------------- fp16 TC GEMM: A fp16, B fp32->fp16 on load --------------------
// out: Ch fp16 (optional qscale cols<128) OR Cf fp32 (+bias, optional accum).
// If sacc != 0 (fp32 path): accumulate per-(bn,group) sum/sumsq of outputs.
__global__ void k_gemm_h(const __half* __restrict__ A, const float* __restrict__ B,
                         const float* __restrict__ bias, float* __restrict__ Cf,
                         __half* __restrict__ Ch, float* sacc,
                         int M, int N, int K, int accum, int qscale) {
    __shared__ unsigned As[64*20];
    __shared__ unsigned Bs[64*20];
    __shared__ float wacc[4][4];
    int bm = blockIdx.y << 6, bn = blockIdx.x << 6;
    int warp = threadIdx.x >> 5, lane = threadIdx.x & 31;
    int lr = lane >> 2, lc = lane & 3;
    float acc[8][4];
#pragma unroll
    for (int nf = 0; nf < 8; nf++)
#pragma unroll
        for (int j = 0; j < 4; j++) acc[nf][j] = 0.f;

    for (int k0 = 0; k0 < K; k0 += 32) {
        __syncthreads();
#pragma unroll
        for (int i = 0; i < 2; i++) {
            int slot = threadIdx.x + i*128;
            int m = slot >> 2, seg = (slot & 3) * 4;
            *(uint4*)&As[m*20 + seg] = *(const uint4*)(A + (size_t)(bm+m)*K + k0 + seg*2);
        }
#pragma unroll
        for (int i = 0; i < 4; i++) {
            int slot = threadIdx.x + i*128;
            int m = slot >> 3, seg = (slot & 7) * 4;
            float4 b4 = *(const float4*)(B + (size_t)(bn+m)*K + k0 + seg);
            __half2 h0 = __floats2half2_rn(b4.x, b4.y);
            __half2 h1 = __floats2half2_rn(b4.z, b4.w);
            Bs[m*20 + (seg>>1)]     = *(unsigned*)&h0;
            Bs[m*20 + (seg>>1) + 1] = *(unsigned*)&h1;
        }
        __syncthreads();
#pragma unroll
        for (int ks = 0; ks < 2; ks++) {
            unsigned a[4];
            int am = warp*16;
            a[0] = As[(am+lr  )*20 + ks*8 + lc];
            a[1] = As[(am+lr+8)*20 + ks*8 + lc];
            a[2] = As[(am+lr  )*20 + ks*8 + lc + 4];
            a[3] = As[(am+lr+8)*20 + ks*8 + lc + 4];
#pragma unroll
            for (int nf = 0; nf < 8; nf++) {
                unsigned b[2];
                b[0] = Bs[(nf*8+lr)*20 + ks*8 + lc];
                b[1] = Bs[(nf*8+lr)*20 + ks*8 + lc + 4];
                mma_f16(acc[nf], a, b);
            }
        }
    }
    float sg0 = 0.f, sq0 = 0.f, sg1 = 0.f, sq1 = 0.f;
#pragma unroll
    for (int nf = 0; nf < 8; nf++) {
        int col = bn + nf*8 + lc*2;
        int row = bm + warp*16 + lr;
        if (Ch) {
            float sc = (qscale && col < 128) ? QK_SCALE : 1.f;
            *(__half2*)(Ch + (size_t)row*N + col)     = __floats2half2_rn(acc[nf][0]*sc, acc[nf][1]*sc);
            *(__half2*)(Ch + (size_t)(row+8)*N + col) = __floats2half2_rn(acc[nf][2]*sc, acc[nf][3]*sc);
        } else {
            float b0 = bias ? bias[col] : 0.f;
            float b1 = bias ? bias[col+1] : 0.f;
            float2* p = (float2*)(Cf + (size_t)row*N + col);
            float2 v = make_float2(acc[nf][0]+b0, acc[nf][1]+b1);
            if (accum) { float2 o = *p; v.x += o.x; v.y += o.y; }
            *p = v;
            float2* p2 = (float2*)(Cf + (size_t)(row+8)*N + col);
            float2 v2 = make_float2(acc[nf][2]+b0, acc[nf][3]+b1);
            if (accum) { float2 o = *p2; v2.x += o.x; v2.y += o.y; }
            *p2 = v2;
            if (sacc) {
                float sv = v.x + v.y + v2.x + v2.y;
                float qv = v.x*v.x + v.y*v.y + v2.x*v2.x + v2.y*v2.y;
                if (nf < 4) { sg0 += sv; sq0 += qv; } else { sg1 += sv; sq1 += qv; }
            }
        }
    }
    if (sacc) {
#pragma unroll
        for (int o = 16; o; o >>= 1) {
            sg0 += __shfl_xor_sync(0xffffffffu, sg0, o);
            sq0 += __shfl_xor_sync(0xffffffffu, sq0, o);
            sg1 += __shfl_xor_sync(0xffffffffu, sg1, o);
            sq1 += __shfl_xor_sync(0xffffffffu, sq1, o);
        }
        if (lane == 0) {
            wacc[warp][0] = sg0; wacc[warp][1] = sq0;
            wacc[warp][2] = sg1; wacc[warp][3] = sq1;
        }
        __syncthreads();
        if (threadIdx.x == 0) {
            float a0 = 0.f, a1 = 0.f, a2 = 0.f, a3 = 0.f;
#pragma unroll
            for (int wi = 0; wi < 4; wi++) {
                a0 += wacc[wi][0]; a1 += wacc[wi][1];
                a2 += wacc[wi][2]; a3 += wacc[wi][3];
            }
            int bni = bm >> 10;
            int gb = bn >> 5;
            atomicAdd(&sacc[bni*8 + (gb  )*2    ], a0);
            atomicAdd(&sacc[bni*8 + (gb  )*2 + 1], a1);
            atomicAdd(&sacc[bni*8 + (gb+1)*2    ], a2);
            atomicAdd(&sacc[bni*8 + (gb+1)*2 + 1], a3);
        }
    }
}

// ---------------- tf32 TC GEMM (mix delta): C = A*(B - subI*I)^T (+bias) --------
__global__ void k_gemm_tc(const float* __restrict__ A, const float* __restrict__ B,
                          const float* __restrict__ bias, float* __restrict__ C,
                          int M, int N, int K, int accum, int subI) {
    __shared__ unsigned As[64*36];
    __shared__ unsigned Bs[64*36];
    int bm = blockIdx.y << 6, bn = blockIdx.x << 6;
    int warp = threadIdx.x >> 5, lane = threadIdx.x & 31;
    int lr = lane >> 2, lc = lane & 3;
    float acc[8][4];
#pragma unroll
    for (int nf = 0; nf < 8; nf++)
#pragma unroll
        for (int j = 0; j < 4; j++) acc[nf][j] = 0.f;

    for (int k0 = 0; k0 < K; k0 += 32) {
        __syncthreads();
#pragma unroll
        for (int i = 0; i < 4; i++) {
            int slot = threadIdx.x + i*128;
            int m = slot >> 3, seg = (slot & 7) << 2;
            float4 a4 = *(const float4*)(A + (size_t)(bm+m)*K + k0 + seg);
            *(uint4*)&As[m*36 + seg] = make_uint4(f2tf32(a4.x), f2tf32(a4.y), f2tf32(a4.z), f2tf32(a4.w));
            float4 b4 = *(const float4*)(B + (size_t)(bn+m)*K + k0 + seg);
            if (subI) {
                int row = bn + m, col = k0 + seg;
                if (row == col    ) b4.x -= 1.f;
                if (row == col + 1) b4.y -= 1.f;
                if (row == col + 2) b4.z -= 1.f;
                if (row == col + 3) b4.w -= 1.f;
            }
            *(uint4*)&Bs[m*36 + seg] = make_uint4(f2tf32(b4.x), f2tf32(b4.y), f2tf32(b4.z), f2tf32(b4.w));
        }
        __syncthreads();
#pragma unroll
        for (int ks = 0; ks < 4; ks++) {
            unsigned a[4];
            int am = warp*16;
            a[0] = As[(am+lr  )*36 + ks*8 + lc];
            a[1] = As[(am+lr+8)*36 + ks*8 + lc];
            a[2] = As[(am+lr  )*36 + ks*8 + lc + 4];
            a[3] = As[(am+lr+8)*36 + ks*8 + lc + 4];
#pragma unroll
            for (int nf = 0; nf < 8; nf++) {
                unsigned b[2];
                b[0] = Bs[(nf*8+lr)*36 + ks*8 + lc];
                b[1] = Bs[(nf*8+lr)*36 + ks*8 + lc + 4];
                mma_tf32(acc[nf], a, b);
            }
        }
    }
#pragma unroll
    for (int nf = 0; nf < 8; nf++) {
        int col = bn + nf*8 + lc*2;
        float b0 = bias ? bias[col] : 0.f;
        float b1 = bias ? bias[col+1] : 0.f;
        int row = bm + warp*16 + lr;
        float2* p = (float2*)(C + (size_t)row*N + col);
        float2 v = make_float2(acc[nf][0]+b0, acc[nf][1]+b1);
        if (accum) { float2 o = *p; v.x += o.x; v.y += o.y; }
        *p = v;
        p = (float2*)(C + (size_t)(row+8)*N + col);
        v = make_float2(acc[nf][2]+b0, acc[nf][3]+b1);
        if (accum) { float2 o = *p; v.x += o.x; v.y += o.y; }
        *p = v;
    }
}

// ---------------- flash attention: all-fp16 mma, 256-query tiles ----------------
__global__ void k_fattn() {
    __shared__ __half Ks[64][24];
    __shared__ __half Vt[16][72];
    int blk = blockIdx.x;                   // qt + 4*(head + 8*bn)
    int qt = blk & 3, head = (blk >> 2) & 7, bn = blk >> 5;
    int warp = threadIdx.x >> 5, lane = threadIdx.x & 31;
    int lr = lane >> 2, lc = lane & 3;
    int q0 = qt*256 + warp*32;
    const __half* qkb = g_qkvh + (size_t)bn*NP*384 + head*16;

    unsigned Qa[2][4];
#pragma unroll
    for (int mt = 0; mt < 2; mt++) {
        const __half* qp = qkb + (size_t)(q0 + mt*16)*384;
        Qa[mt][0] = *(const unsigned*)(qp + (size_t)(lr  )*384 + 2*lc);
        Qa[mt][1] = *(const unsigned*)(qp + (size_t)(lr+8)*384 + 2*lc);
        Qa[mt][2] = *(const unsigned*)(qp + (size_t)(lr  )*384 + 2*lc + 8);
        Qa[mt][3] = *(const unsigned*)(qp + (size_t)(lr+8)*384 + 2*lc + 8);
    }

    float lsum[2][2] = {{0.f,0.f},{0.f,0.f}};
    float Oa[2][2][4];
#pragma unroll
    for (int mt = 0; mt < 2; mt++)
#pragma unroll
        for (int dn = 0; dn < 2; dn++)
#pragma unroll
            for (int j = 0; j < 4; j++) Oa[mt][dn][j] = 0.f;

    for (int c0 = 0; c0 < NP; c0 += 64) {
        __syncthreads();
        {
            int tt = threadIdx.x & 127;
            int key = tt >> 1, seg = (tt & 1) * 8;
            const __half* kp = qkb + (size_t)(c0 + key)*384 + 128 + seg;
            if (threadIdx.x < 128) {
                *(uint4*)&Ks[key][seg] = *(const uint4*)kp;
            } else {
                uint4 vv = *(const uint4*)(kp + 128);
                __half vh[8];
                *(uint4*)vh = vv;
#pragma unroll
                for (int j = 0; j < 8; j++) Vt[seg + j][key] = vh[j];
            }
        }
        __syncthreads();

        float S[2][8][4];
#pragma unroll
        for (int mt = 0; mt < 2; mt++)
#pragma unroll
            for (int nf = 0; nf < 8; nf++) {
                S[mt][nf][0] = S[mt][nf][1] = S[mt][nf][2] = S[mt][nf][3] = 0.f;
                unsigned b[2];
                b[0] = *(const unsigned*)&Ks[nf*8 + lr][2*lc];
                b[1] = *(const unsigned*)&Ks[nf*8 + lr][2*lc + 8];
                mma_f16(S[mt][nf], Qa[mt], b);
            }

#pragma unroll
        for (int mt = 0; mt < 2; mt++)
#pragma unroll
            for (int nf = 0; nf < 8; nf++) {
                S[mt][nf][0] = ex2a(S[mt][nf][0]);
                S[mt][nf][1] = ex2a(S[mt][nf][1]);
                S[mt][nf][2] = ex2a(S[mt][nf][2]);
                S[mt][nf][3] = ex2a(S[mt][nf][3]);
                lsum[mt][0] += S[mt][nf][0] + S[mt][nf][1];
                lsum[mt][1] += S[mt][nf][2] + S[mt][nf][3];
            }

#pragma unroll
        for (int mt = 0; mt < 2; mt++)
#pragma unroll
            for (int j = 0; j < 4; j++) {
                unsigned a[4];
                a[0] = packh2(S[mt][2*j  ][0], S[mt][2*j  ][1]);
                a[1] = packh2(S[mt][2*j  ][2], S[mt][2*j  ][3]);
                a[2] = packh2(S[mt][2*j+1][0], S[mt][2*j+1][1]);
                a[3] = packh2(S[mt][2*j+1][2], S[mt][2*j+1][3]);
#pragma unroll
                for (int dn = 0; dn < 2; dn++) {
                    unsigned b[2];
                    b[0] = *(const unsigned*)&Vt[dn*8 + lr][j*16 + lc*2];
                    b[1] = *(const unsigned*)&Vt[dn*8 + lr][j*16 + lc*2 + 8];
                    mma_f16(Oa[mt][dn], a, b);
                }
            }
    }

#pragma unroll
    for (int mt = 0; mt < 2; mt++)
#pragma unroll
        for (int o = 1; o <= 2; o <<= 1) {
            lsum[mt][0] += __shfl_xor_sync(0xffffffffu, lsum[mt][0], o);
            lsum[mt][1] += __shfl_xor_sync(0xffffffffu, lsum[mt][1], o);
        }
    __half* ob = g_aoh + (size_t)bn*NP*CC + head*16;
#pragma unroll
    for (int mt = 0; mt < 2; mt++) {
        float inv0 = 1.f / lsum[mt][0], inv1 = 1.f / lsum[mt][1];
        int qr = q0 + mt*16;
#pragma unroll
        for (int dn = 0; dn < 2; dn++) {
            int col = dn*8 + lc*2;
            *(__half2*)(ob + (size_t)(qr+lr  )*CC + col) = __floats2half2_rn(Oa[mt][dn][0]*inv0, Oa[mt][dn][1]*inv0);
            *(__half2*)(ob + (size_t)(qr+lr+8)*CC + col) = __floats2half2_rn(Oa[mt][dn][2]*inv1, Oa[mt][dn][3]*inv1);
        }
    }
}

// ---------------- GN1 apply + 2x2 pool fused (stats from g_sacc) ----------------
__global__ void k_gnpool(const float* __restrict__ gg, const float* __restrict__ gb) {
    int bn = blockIdx.x >> 4, hp = blockIdx.x & 15;
    float mu[4], rs[4];
#pragma unroll
    for (int g = 0; g < 4; g++) {
        float s = g_sacc[bn*8 + g*2], q = g_sacc[bn*8 + g*2 + 1];
        float m = s * (1.f/32768.f);
        mu[g] = m;
        rs[g] = rsqrtf(q*(1.f/32768.f) - m*m + 1e-5f);
    }
    for (int idx = threadIdx.x; idx < 2048; idx += 256) {
        int wp = idx >> 7, c = idx & 127;
        int g = c >> 5;
        float ga = gg[c]*rs[g], bb2 = gb[c], m = mu[g];
        size_t a00 = ((size_t)bn*NP + hp*64 + wp*2)*CC + c;
        float y00 = (g_xt[a00]         - m)*ga + bb2;
        float y01 = (g_xt[a00 + CC]    - m)*ga + bb2;
        float y10 = (g_xt[a00 + 32*CC] - m)*ga + bb2;
        float y11 = (g_xt[a00 + 33*CC] - m)*ga + bb2;
        g_y2nh[a00]         = __float2half(y00);
        g_y2nh[a00 + CC]    = __float2half(y01);
        g_y2nh[a00 + 32*CC] = __float2half(y10);
        g_y2nh[a00 + 33*CC] = __float2half(y11);
        g_gph[((size_t)bn*NPC + hp*16 + wp)*CC + c] = __float2half(0.25f*(y00+y01+y10+y11));
    }
}

// ---------------- GroupNorm stats: fp16 input x gate ----------------
__global__ void k_gnstats_h(const __half* __restrict__ X, const float* __restrict__ gate,
                            float2* __restrict__ stats) {
    __shared__ float sh[256], sh2[256];
    int bn = blockIdx.x >> 2, g = blockIdx.x & 3;
    float s = 0.f, q = 0.f;
    const __half* base = X + (size_t)bn*NP*CC + g*32;
    for (int e = threadIdx.x; e < 32768; e += 256) {
        int n = e >> 5, cc = e & 31;
        float v = __half2float(base[(size_t)n*CC + cc]) * gate[bn*NP + n];
        s += v; q += v*v;
    }
    sh[threadIdx.x] = s; sh2[threadIdx.x] = q;
    __syncthreads();
    for (int o = 128; o; o >>= 1) {
        if (threadIdx.x < o) { sh[threadIdx.x] += sh[threadIdx.x+o]; sh2[threadIdx.x] += sh2[threadIdx.x+o]; }
        __syncthreads();
    }
    if (threadIdx.x == 0) {
        float mu = sh[0] * (1.f/32768.f);
        float var = sh2[0] * (1.f/32768.f) - mu*mu;
        stats[blockIdx.x] = make_float2(mu, rsqrtf(var + 1e-5f));
    }
}

__global__ void k_gate(const float* __restrict__ w_psi, const float* __restrict__ b_psi) {
    int lane = threadIdx.x & 31, wid = threadIdx.x >> 5;
    int p = blockIdx.x*8 + wid;
    int bn = p >> 10, n = p & 1023;
    int h = n >> 5, w = n & 31;
    int pc = (h >> 1)*16 + (w >> 1);
    const __half2* gp2 = (const __half2*)(g_ggh + ((size_t)bn*NPC + pc)*CC);
    const __half2* lp2 = (const __half2*)(g_lh + (size_t)p*CC);
    float2 ga = __half22float2(gp2[lane*2]),   gb = __half22float2(gp2[lane*2+1]);
    float2 la = __half22float2(lp2[lane*2]),   lb = __half22float2(lp2[lane*2+1]);
    float4 wp = ((const float4*)w_psi)[lane];
    float s = fmaxf(ga.x+la.x, 0.f)*wp.x + fmaxf(ga.y+la.y, 0.f)*wp.y
            + fmaxf(gb.x+lb.x, 0.f)*wp.z + fmaxf(gb.y+lb.y, 0.f)*wp.w;
#pragma unroll
    for (int o = 16; o; o >>= 1) s += __shfl_xor_sync(0xffffffffu, s, o);
    if (lane == 0) g_gate[p] = 1.f/(1.f + expf(-(s + b_psi[0])));
}

// gated GN2 + transpose to channels-first + partial W-DFT (fused)
__global__ void k_y3t(const float* __restrict__ g, const float* __restrict__ b) {
    __shared__ float tile[128][33];
    __shared__ float gts[32];
    __shared__ float tc[32], ts[32];
    int bn = blockIdx.x >> 5, h = blockIdx.x & 31;
    if (threadIdx.x < 32) {
        gts[threadIdx.x] = g_gate[bn*NP + h*32 + threadIdx.x];
        float a = TWO_PI_32 * (float)threadIdx.x;
        tc[threadIdx.x] = cosf(a);
        ts[threadIdx.x] = sinf(a);
    }
    __syncthreads();
    const __half* src = g_y2nh + ((size_t)bn*NP + h*32)*CC;
#pragma unroll
    for (int it = 0; it < 16; it++) {
        int idx = threadIdx.x + it*256;
        int w = idx >> 7, c = idx & 127;
        tile[c][w] = __half2float(src[(size_t)w*CC + c]) * gts[w];
    }
    __syncthreads();
    float* dst = g_y3 + (size_t)bn*CC*NP + h*32;
#pragma unroll
    for (int it = 0; it < 16; it++) {
        int idx = threadIdx.x + it*256;
        int c = idx >> 5, w = idx & 31;
        float2 st = g_st2[bn*4 + (c >> 5)];
        float v = (tile[c][w] - st.x)*st.y*g[c] + b[c];
        dst[(size_t)c*NP + w] = v;
        tile[c][w] = v;
    }
    __syncthreads();
    float2* xw = g_Xw + ((size_t)bn*CC)*HH*MW + h*MW;
    for (int e = threadIdx.x; e < 128*12; e += 256) {
        int c = e / 12, kw = e % 12;
        float re = 0.f, im = 0.f;
#pragma unroll
        for (int w = 0; w < WW; w++) {
            int t = (w*kw) & 31;
            float v = tile[c][w];
            re += v*tc[t];
            im -= v*ts[t];
        }
        xw[(size_t)c*HH*MW + kw] = make_float2(re, im);
    }
}

// partial DFT along H -> z rows, coalesced (8 channels per block)
__global__ void k_sb2() {
    __shared__ float2 Xs[8][HH*MW];
    __shared__ float zr[144][8], zi[144][8];
    __shared__ float tc[32], ts[32];
    if (threadIdx.x < 32) {
        float a = TWO_PI_32 * (float)threadIdx.x;
        tc[threadIdx.x] = cosf(a);
        ts[threadIdx.x] = sinf(a);
    }
    int bn = blockIdx.x >> 4, cg = blockIdx.x & 15;
    const float2* src = g_Xw + ((size_t)(bn*CC + cg*8))*HH*MW;
    for (int e = threadIdx.x; e < 8*HH*MW; e += 256) {
        int c = e / (HH*MW), r = e % (HH*MW);
        Xs[c][r] = src[(size_t)c*HH*MW + r];
    }
    __syncthreads();
    for (int e = threadIdx.x; e < 144*8; e += 256) {
        int m = e >> 3, c = e & 7;
        int kh = m / 12, kw = m % 12;
        float re = 0.f, im = 0.f;
#pragma unroll
        for (int h = 0; h < HH; h++) {
            int t = (kh*h) & 31;
            float2 v = Xs[c][h*MW + kw];
            re += v.x*tc[t] + v.y*ts[t];
            im += v.y*tc[t] - v.x*ts[t];
        }
        zr[m][c] = re * INV32;
        zi[m][c] = im * INV32;
    }
    __syncthreads();
    for (int e = threadIdx.x; e < 144*16; e += 256) {
        int m = e >> 4, j = e & 15;
        size_t rowz = (size_t)(bn*144 + m) * 256;
        if (j < 8) g_zin[rowz + cg*8 + j] = zr[m][j];
        else       g_zin[rowz + 128 + cg*8 + (j-8)] = zi[m][j-8];
    }
}

// inverse DFT along H of delta modes, coalesced (32 channels per block)
__global__ void k_sd2() {
    __shared__ float Dr[144][32], Di[144][32];
    __shared__ float tc[32], ts[32];
    if (threadIdx.x < 32) {
        float a = TWO_PI_32 * (float)threadIdx.x;
        tc[threadIdx.x] = cosf(a);
        ts[threadIdx.x] = sinf(a);
    }
    int bn = blockIdx.x >> 2, cg = blockIdx.x & 3;
    for (int e = threadIdx.x; e < 144*32; e += 256) {
        int m = e >> 5, c = e & 31;
        size_t rowz = (size_t)(bn*144 + m) * 256;
        Dr[m][c] = g_zout[rowz + cg*32 + c];
        Di[m][c] = g_zout[rowz + 128 + cg*32 + c];
    }
    __syncthreads();
    int c = threadIdx.x & 31, hg = threadIdx.x >> 5;
    float2* dst = g_tH + ((size_t)(bn*CC + cg*32 + c))*HH*MW;
#pragma unroll
    for (int hi = 0; hi < 4; hi++) {
        int h = hg*4 + hi;
#pragma unroll
        for (int kw = 0; kw < 12; kw++) {
            float re = 0.f, im = 0.f;
#pragma unroll
            for (int kh = 0; kh < MH; kh++) {
                int t = (kh*h) & 31;
                float dx = Dr[kh*12 + kw][c], dy = Di[kh*12 + kw][c];
                re += dx*tc[t] - dy*ts[t];
                im += dx*ts[t] + dy*tc[t];
            }
            dst[h*MW + kw] = make_float2(re*INV_SQRT32, im*INV_SQRT32);
        }
    }
}

// final c2r along W of delta + out = 2*y3 + ys (parity split)
__global__ void k_se(float* __restrict__ out) {
    __shared__ float tc[32], ts[32];
    if (threadIdx.x < 32) {
        float a = TWO_PI_32 * (float)threadIdx.x;
        tc[threadIdx.x] = cosf(a);
        ts[threadIdx.x] = sinf(a);
    }
    __syncthreads();
    int row = blockIdx.x * blockDim.x + threadIdx.x;   // (bn,c,h)
    if (row >= BNN*CC*HH) return;
    int h = row & 31;
    int c = (row >> 5) & 127;
    int bn = row >> 12;
    float2 T[MW];
    const float2* tp = g_tH + (size_t)row * MW;
#pragma unroll
    for (int kw = 0; kw < MW; kw++) T[kw] = tp[kw];
    const float* yp = g_y3 + (size_t)row * WW;
    int b = bn >> 5, l = bn & 31;
    float* op = out + (((((size_t)b*CC + c)*LL + l)*HH + h)) * WW;
    for (int w = 0; w < 16; w++) {
        float se = T[0].x, so = 0.f;
#pragma unroll
        for (int kw = 1; kw < MW; kw++) {
            int t = (kw*w) & 31;
            float term = 2.f*(T[kw].x*tc[t] - T[kw].y*ts[t]);
            if (kw & 1) so += term; else se += term;
        }
        op[w]      = 2.f*yp[w]      + (se + so)*INV_SQRT32;
        op[w + 16] = 2.f*yp[w + 16] + (se - so)*INV_SQRT32;
    }
}

// ---------------- launch ----------------
static void* symaddr(const void* sym) { void* p = 0; cudaGetSymbolAddress(&p, sym); return p; }

extern "C" void kernel_launch(void* const* d_in, const int* in_sizes, int n_in,
                              void* d_out, int out_size) {
    const float* x      = (const float*)d_in[0];
    const float* dt     = (const float*)d_in[1];
    const float* nu     = (const float*)d_in[2];
    const float* theta  = (const float*)d_in[3];
    const float* ln_g   = (const float*)d_in[4];
    const float* ln_b   = (const float*)d_in[5];
    const float* w_qkv  = (const float*)d_in[6];
    const float* w_proj = (const float*)d_in[7];
    const float* b_proj = (const float*)d_in[8];
    const float* gn_g   = (const float*)d_in[9];
    const float* gn_b   = (const float*)d_in[10];
    const float* w_g    = (const float*)d_in[11];
    const float* w_l    = (const float*)d_in[12];
    const float* w_psi  = (const float*)d_in[13];
    const float* b_psi  = (const float*)d_in[14];
    const float* gate_g = (const float*)d_in[15];
    const float* gate_b = (const float*)d_in[16];
    const float* mix_w  = (const float*)d_in[17];
    const float* mix_b  = (const float*)d_in[18];
    float* out = (float*)d_out;

    float*  p_xt   = (float*)symaddr(g_xt);
    __half* p_xnh  = (__half*)symaddr(g_xnh);
    __half* p_qkvh = (__half*)symaddr(g_qkvh);
    __half* p_aoh  = (__half*)symaddr(g_aoh);
    __half* p_y2nh = (__half*)symaddr(g_y2nh);
    __half* p_gph  = (__half*)symaddr(g_gph);
    __half* p_ggh  = (__half*)symaddr(g_ggh);
    __half* p_lh   = (__half*)symaddr(g_lh);
    float*  p_zin  = (float*)symaddr(g_zin);
    float*  p_zout = (float*)symaddr(g_zout);
    float2* p_st2  = (float2*)symaddr(g_st2);
    float*  p_gate = (float*)symaddr(g_gate);
    float*  p_sacc = (float*)symaddr(g_sacc);

    // stage 1
    k_precompA<<<(BB*LL*CC*WF + 255)/256, 256>>>(dt, nu, theta);
    k_rfft<<<(BB*CC*LL*HH + 127)/128, 128>>>(x);
    k_scan<<<(BB*CC*HH*WF + 255)/256, 256>>>();
    k_irfft<<<(BB*LL*HH*CC)/256, 256>>>();
    k_ln<<<(BNN*NP)/8, 256>>>(ln_g, ln_b);
    // stage 2: attention + proj residual (stats fused into proj epilogue)
    k_gemm_h<<<dim3(384/64, (BNN*NP)/64), 128>>>(p_xnh, w_qkv, (const float*)0, (float*)0, p_qkvh, (float*)0, BNN*NP, 384, CC, 0, 1);
    k_fattn<<<BNN*8*4, 256>>>();
    k_gemm_h<<<dim3(CC/64, (BNN*NP)/64), 128>>>(p_aoh, w_proj, b_proj, p_xt, (__half*)0, p_sacc, BNN*NP, CC, CC, 1, 0);
    // stage 3: GN1+pool fused, gating, GN2
    k_gnpool<<<BNN*16, 256>>>(gn_g, gn_b);
    k_gemm_h<<<dim3(CC/64, (BNN*NPC)/64), 128>>>(p_gph, w_g, (const float*)0, (float*)0, p_ggh, (float*)0, BNN*NPC, CC, CC, 0, 0);
    k_gemm_h<<<dim3(CC/64, (BNN*NP)/64), 128>>>(p_y2nh, w_l, (const float*)0, (float*)0, p_lh, (float*)0, BNN*NP, CC, CC, 0, 0);
    k_gate<<<(BNN*NP)/8, 256>>>(w_psi, b_psi);
    k_gnstats_h<<<BNN*4, 256>>>(p_y2nh, p_gate, p_st2);
    k_y3t<<<BNN*HH, 256>>>(gate_g, gate_b);
    // stage 4: spectral delta on TC (delta = z(mix_w - I)^T + mix_b)
    k_sb2<<<BNN*16, 256>>>();
    k_gemm_tc<<<dim3(256/64, (BNN*144)/64), 128>>>(p_zin, mix_w, mix_b, p_zout, BNN*144, 256, 256, 0, 1);
    k_sd2<<<BNN*4, 256>>>();
    k_se<<<(BNN*CC*HH)/256, 256>>>(out);
}

// round 11
// speedup vs baseline: 3.0216x; 1.0162x over previous
#include <cuda_runtime.h>
#include <cuda_fp16.h>
#include <math.h>

// ---------------- shapes ----------------
#define BB 2
#define CC 128
#define LL 32
#define HH 32
#define WW 32
#define WF 17
#define BNN 64
#define NP 1024
#define NPC 256
#define MH 12
#define MW 12

#define TWO_PI_32 0.19634954084936207f
#define INV32 0.03125f
#define INV_SQRT32 0.17677669529663687f
#define QK_SCALE 0.36067376022224085f    // 0.25 * log2(e)

// ---------------- device scratch ----------------
__device__ float2 g_xf[BB*CC*LL*HH*WF];
__device__ float2 g_A [BB*LL*CC*WF];
__device__ float  g_xt [BNN*NP*CC];
__device__ __half g_xnh[BNN*NP*CC];
__device__ __half g_qkvh[BNN*NP*384];
__device__ __half g_aoh[BNN*NP*CC];
__device__ __half g_y2nh[BNN*NP*CC];
__device__ __half g_gph[BNN*NPC*CC];
__device__ __half g_ggh[BNN*NPC*CC];
__device__ __half g_lh [BNN*NP*CC];
__device__ float  g_gate[BNN*NP];
__device__ float  g_rs  [BNN*NP*8];      // per-pixel per-group (sum, sumsq)
__device__ float  g_y3 [BNN*CC*NP];
__device__ float2 g_Xw [BNN*CC*HH*MW];
__device__ float  g_zin [BNN*144*256];
__device__ float  g_zout[BNN*144*256];
__device__ float2 g_tH [BNN*CC*HH*MW];
__device__ float  g_sacc[1024];          // [0..511] GN1 (bn,g,{s,q}); [512..1023] GN2

// ---------------- mma helpers ----------------
__device__ __forceinline__ unsigned f2tf32(float f) {
    unsigned r; asm("cvt.rna.tf32.f32 %0, %1;" : "=r"(r) : "f"(f)); return r;
}
__device__ __forceinline__ void mma_tf32(float* c, const unsigned* a, const unsigned* b) {
    asm("mma.sync.aligned.m16n8k8.row.col.f32.tf32.tf32.f32 "
        "{%0,%1,%2,%3}, {%4,%5,%6,%7}, {%8,%9}, {%0,%1,%2,%3};"
        : "+f"(c[0]), "+f"(c[1]), "+f"(c[2]), "+f"(c[3])
        : "r"(a[0]), "r"(a[1]), "r"(a[2]), "r"(a[3]), "r"(b[0]), "r"(b[1]));
}
__device__ __forceinline__ void mma_f16(float* c, const unsigned* a, const unsigned* b) {
    asm("mma.sync.aligned.m16n8k16.row.col.f32.f16.f16.f32 "
        "{%0,%1,%2,%3}, {%4,%5,%6,%7}, {%8,%9}, {%0,%1,%2,%3};"
        : "+f"(c[0]), "+f"(c[1]), "+f"(c[2]), "+f"(c[3])
        : "r"(a[0]), "r"(a[1]), "r"(a[2]), "r"(a[3]), "r"(b[0]), "r"(b[1]));
}
// pack (lo,hi) to f16x2 then 2^x elementwise — one cvt + one MUFU for 2 exps
__device__ __forceinline__ unsigned h2ex2(float lo, float hi) {
    unsigned p;
    asm("{\n\t.reg .b32 t;\n\tcvt.rn.f16x2.f32 t, %2, %1;\n\tex2.approx.f16x2 %0, t;\n\t}"
        : "=r"(p) : "f"(lo), "f"(hi));
    return p;
}

// ---------------- stage 1: A precompute (+ zero stats accumulators) -------------
__global__ void k_precompA(const float* __restrict__ dt, const float* __restrict__ nu,
                           const float* __restrict__ th) {
    int i = blockIdx.x * blockDim.x + threadIdx.x;
    if (i < 1024) g_sacc[i] = 0.f;
    if (i >= BB*LL*CC*WF) return;
    int k = i % WF;
    int c = (i / WF) % CC;
    int l = (i / (WF*CC)) % LL;
    int b =  i / (WF*CC*LL);
    float d  = dt[b*LL + l];
    float e  = expf(-nu[c*WF + k] * d);
    float si, co;
    sincosf(th[c*WF + k] * d, &si, &co);
    g_A[i] = make_float2(e*co, e*si);
}

// ---------------- stage 1: rfft along W ----------------
__global__ void k_rfft(const float* __restrict__ x) {
    __shared__ float tc[32], ts[32];
    if (threadIdx.x < 32) {
        float a = TWO_PI_32 * (float)threadIdx.x;
        tc[threadIdx.x] = cosf(a);
        ts[threadIdx.x] = sinf(a);
    }
    __syncthreads();
    int row = blockIdx.x * blockDim.x + threadIdx.x;   // (b,c,l,h)
    if (row >= BB*CC*LL*HH) return;
    const float* xp = x + (size_t)row * WW;
    float xr[WW];
#pragma unroll
    for (int w = 0; w < WW; w++) xr[w] = xp[w];
    float2* out = g_xf + (size_t)row * WF;
    for (int k = 0; k < WF; k++) {
        float re = 0.f, im = 0.f;
#pragma unroll
        for (int w = 0; w < WW; w++) {
            int t = (w*k) & 31;
            re += xr[w]*tc[t];
            im -= xr[w]*ts[t];
        }
        out[k] = make_float2(re, im);
    }
}

// ---------------- stage 1: complex scan over L ----------------
__global__ void k_scan() {
    int i = blockIdx.x * blockDim.x + threadIdx.x;     // (b,c,h,k)
    if (i >= BB*CC*HH*WF) return;
    int k = i % WF;
    int h = (i / WF) % HH;
    int c = (i / (WF*HH)) % CC;
    int b =  i / (WF*HH*CC);
    size_t xfb = ((((size_t)b*CC + c)*LL)*HH + h)*WF + k;
    const size_t xstr = (size_t)HH*WF;
    size_t ab = ((size_t)b*LL*CC + c)*WF + k;
    const size_t astr = (size_t)CC*WF;
    float2 s = make_float2(0.f, 0.f);
    for (int l = 0; l < LL; l++) {
        float2 a = g_A[ab + (size_t)l*astr];
        float2 u = g_xf[xfb + (size_t)l*xstr];
        float re = a.x*s.x - a.y*s.y + u.x;
        float im = a.x*s.y + a.y*s.x + u.y;
        s = make_float2(re, im);
        g_xf[xfb + (size_t)l*xstr] = s;
    }
}

// ---------------- stage 1: irfft -> xt channels-last (parity split) -------------
__global__ void k_irfft() {
    __shared__ float tc[32], ts[32];
    if (threadIdx.x < 32) {
        float a = TWO_PI_32 * (float)threadIdx.x;
        tc[threadIdx.x] = cosf(a);
        ts[threadIdx.x] = sinf(a);
    }
    __syncthreads();
    int i = blockIdx.x * blockDim.x + threadIdx.x;     // (b,l,h,c)
    if (i >= BB*LL*HH*CC) return;
    int c = i & 127;
    int h = (i >> 7) & 31;
    int l = (i >> 12) & 31;
    int b =  i >> 17;
    const float2* st = g_xf + ((((size_t)b*CC + c)*LL + l)*HH + h)*WF;
    float2 S[WF];
#pragma unroll
    for (int k = 0; k < WF; k++) S[k] = st[k];
    int bn = b*LL + l;
    float* out = g_xt + ((size_t)bn*NP + h*WW)*CC + c;
    for (int w = 0; w < 16; w++) {
        float se = S[0].x + ((w & 1) ? -S[16].x : S[16].x);
        float so = 0.f;
#pragma unroll
        for (int k = 1; k < 16; k++) {
            int t = (w*k) & 31;
            float term = 2.f*(S[k].x*tc[t] - S[k].y*ts[t]);
            if (k & 1) so += term; else se += term;
        }
        out[(size_t)w*CC]      = (se + so) * INV32;
        out[(size_t)(w+16)*CC] = (se - so) * INV32;
    }
}

// ---------------- LayerNorm over C -> fp16 ----------------
__global__ void k_ln(const float* __restrict__ g, const float* __restrict__ b) {
    int lane = threadIdx.x & 31, wid = threadIdx.x >> 5;
    int r = blockIdx.x*8 + wid;
    float4 v = ((const float4*)(g_xt + (size_t)r*CC))[lane];
    float s = v.x + v.y + v.z + v.w;
#pragma unroll
    for (int o = 16; o; o >>= 1) s += __shfl_xor_sync(0xffffffffu, s, o);
    float mu = s * (1.f/128.f);
    float dx = v.x-mu, dy = v.y-mu, dz = v.z-mu, dw = v.w-mu;
    float q = dx*dx + dy*dy + dz*dz + dw*dw;
#pragma unroll
    for (int o = 16; o; o >>= 1) q += __shfl_xor_sync(0xffffffffu, q, o);
    float rstd = rsqrtf(q*(1.f/128.f) + 1e-5f);
    float4 g4 = ((const float4*)g)[lane];
    float4 b4 = ((const float4*)b)[lane];
    __half2* op = (__half2*)(g_xnh + (size_t)r*CC);
    op[lane*2]   = __floats2half2_rn(dx*rstd*g4.x + b4.x, dy*rstd*g4.y + b4.y);
    op[lane*2+1] = __floats2half2_rn(dz*rstd*g4.z + b4.z, dw*rstd*g4.w + b4.w);
}

// ---------------- fp16 TC GEMM: A fp16, B fp32->fp16 on load --------------------
__global__ void k_gemm_h(const __half* __restrict__ A, const float* __restrict__ B,
                         const float* __restrict__ bias, float* __restrict__ Cf,
                         __half* __restrict__ Ch, float* sacc,
                         int M, int N, int K, int accum, int qscale) {
    __shared__ unsigned As[64*20];
    __shared__ unsigned Bs[64*20];
    __shared__ float wacc[4][4];
    int bm = blockIdx.y << 6, bn = blockIdx.x << 6;
    int warp = threadIdx.x >> 5, lane = threadIdx.x & 31;
    int lr = lane >> 2, lc = lane & 3;
    float acc[8][4];
#pragma unroll
    for (int nf = 0; nf < 8; nf++)
#pragma unroll
        for (int j = 0; j < 4; j++) acc[nf][j] = 0.f;

    for (int k0 = 0; k0 < K; k0 += 32) {
        __syncthreads();
#pragma unroll
        for (int i = 0; i < 2; i++) {
            int slot = threadIdx.x + i*128;
            int m = slot >> 2, seg = (slot & 3) * 4;
            *(uint4*)&As[m*20 + seg] = *(const uint4*)(A + (size_t)(bm+m)*K + k0 + seg*2);
        }
#pragma unroll
        for (int i = 0; i < 4; i++) {
            int slot = threadIdx.x + i*128;
            int m = slot >> 3, seg = (slot & 7) * 4;
            float4 b4 = *(const float4*)(B + (size_t)(bn+m)*K + k0 + seg);
            __half2 h0 = __floats2half2_rn(b4.x, b4.y);
            __half2 h1 = __floats2half2_rn(b4.z, b4.w);
            Bs[m*20 + (seg>>1)]     = *(unsigned*)&h0;
            Bs[m*20 + (seg>>1) + 1] = *(unsigned*)&h1;
        }
        __syncthreads();
#pragma unroll
        for (int ks = 0; ks < 2; ks++) {
            unsigned a[4];
            int am = warp*16;
            a[0] = As[(am+lr  )*20 + ks*8 + lc];
            a[1] = As[(am+lr+8)*20 + ks*8 + lc];
            a[2] = As[(am+lr  )*20 + ks*8 + lc + 4];
            a[3] = As[(am+lr+8)*20 + ks*8 + lc + 4];
#pragma unroll
            for (int nf = 0; nf < 8; nf++) {
                unsigned b[2];
                b[0] = Bs[(nf*8+lr)*20 + ks*8 + lc];
                b[1] = Bs[(nf*8+lr)*20 + ks*8 + lc + 4];
                mma_f16(acc[nf], a, b);
            }
        }
    }
    float sg0 = 0.f, sq0 = 0.f, sg1 = 0.f, sq1 = 0.f;
#pragma unroll
    for (int nf = 0; nf < 8; nf++) {
        int col = bn + nf*8 + lc*2;
        int row = bm + warp*16 + lr;
        if (Ch) {
            float sc = (qscale && col < 128) ? QK_SCALE : 1.f;
            *(__half2*)(Ch + (size_t)row*N + col)     = __floats2half2_rn(acc[nf][0]*sc, acc[nf][1]*sc);
            *(__half2*)(Ch + (size_t)(row+8)*N + col) = __floats2half2_rn(acc[nf][2]*sc, acc[nf][3]*sc);
        } else {
            float b0 = bias ? bias[col] : 0.f;
            float b1 = bias ? bias[col+1] : 0.f;
            float2* p = (float2*)(Cf + (size_t)row*N + col);
            float2 v = make_float2(acc[nf][0]+b0, acc[nf][1]+b1);
            if (accum) { float2 o = *p; v.x += o.x; v.y += o.y; }
            *p = v;
            float2* p2 = (float2*)(Cf + (size_t)(row+8)*N + col);
            float2 v2 = make_float2(acc[nf][2]+b0, acc[nf][3]+b1);
            if (accum) { float2 o = *p2; v2.x += o.x; v2.y += o.y; }
            *p2 = v2;
            if (sacc) {
                float sv = v.x + v.y + v2.x + v2.y;
                float qv = v.x*v.x + v.y*v.y + v2.x*v2.x + v2.y*v2.y;
                if (nf < 4) { sg0 += sv; sq0 += qv; } else { sg1 += sv; sq1 += qv; }
            }
        }
    }
    if (sacc) {
#pragma unroll
        for (int o = 16; o; o >>= 1) {
            sg0 += __shfl_xor_sync(0xffffffffu, sg0, o);
            sq0 += __shfl_xor_sync(0xffffffffu, sq0, o);
            sg1 += __shfl_xor_sync(0xffffffffu, sg1, o);
            sq1 += __shfl_xor_sync(0xffffffffu, sq1, o);
        }
        if (lane == 0) {
            wacc[warp][0] = sg0; wacc[warp][1] = sq0;
            wacc[warp][2] = sg1; wacc[warp][3] = sq1;
        }
        __syncthreads();
        if (threadIdx.x == 0) {
            float a0 = 0.f, a1 = 0.f, a2 = 0.f, a3 = 0.f;
#pragma unroll
            for (int wi = 0; wi < 4; wi++) {
                a0 += wacc[wi][0]; a1 += wacc[wi][1];
                a2 += wacc[wi][2]; a3 += wacc[wi][3];
            }
            int bni = bm >> 10;
            int gb = bn >> 5;
            atomicAdd(&sacc[bni*8 + (gb  )*2    ], a0);
            atomicAdd(&sacc[bni*8 + (gb  )*2 + 1], a1);
            atomicAdd(&sacc[bni*8 + (gb+1)*2    ], a2);
            atomicAdd(&sacc[bni*8 + (gb+1)*2 + 1], a3);
        }
    }
}

// ---------------- tf32 TC GEMM (mix delta): C = A*(B - subI*I)^T (+bias) --------
__global__ void k_gemm_tc(const float* __restrict__ A, const float* __restrict__ B,
                          const float* __restrict__ bias, float* __restrict__ C,
                          int M, int N, int K, int accum, int subI) {
    __shared__ unsigned As[64*36];
    __shared__ unsigned Bs[64*36];
    int bm = blockIdx.y << 6, bn = blockIdx.x << 6;
    int warp = threadIdx.x >> 5, lane = threadIdx.x & 31;
    int lr = lane >> 2, lc = lane & 3;
    float acc[8][4];
#pragma unroll
    for (int nf = 0; nf < 8; nf++)
#pragma unroll
        for (int j = 0; j < 4; j++) acc[nf][j] = 0.f;

    for (int k0 = 0; k0 < K; k0 += 32) {
        __syncthreads();
#pragma unroll
        for (int i = 0; i < 4; i++) {
            int slot = threadIdx.x + i*128;
            int m = slot >> 3, seg = (slot & 7) << 2;
            float4 a4 = *(const float4*)(A + (size_t)(bm+m)*K + k0 + seg);
            *(uint4*)&As[m*36 + seg] = make_uint4(f2tf32(a4.x), f2tf32(a4.y), f2tf32(a4.z), f2tf32(a4.w));
            float4 b4 = *(const float4*)(B + (size_t)(bn+m)*K + k0 + seg);
            if (subI) {
                int row = bn + m, col = k0 + seg;
                if (row == col    ) b4.x -= 1.f;
                if (row == col + 1) b4.y -= 1.f;
                if (row == col + 2) b4.z -= 1.f;
                if (row == col + 3) b4.w -= 1.f;
            }
            *(uint4*)&Bs[m*36 + seg] = make_uint4(f2tf32(b4.x), f2tf32(b4.y), f2tf32(b4.z), f2tf32(b4.w));
        }
        __syncthreads();
#pragma unroll
        for (int ks = 0; ks < 4; ks++) {
            unsigned a[4];
            int am = warp*16;
            a[0] = As[(am+lr  )*36 + ks*8 + lc];
            a[1] = As[(am+lr+8)*36 + ks*8 + lc];
            a[2] = As[(am+lr  )*36 + ks*8 + lc + 4];
            a[3] = As[(am+lr+8)*36 + ks*8 + lc + 4];
#pragma unroll
            for (int nf = 0; nf < 8; nf++) {
                unsigned b[2];
                b[0] = Bs[(nf*8+lr)*36 + ks*8 + lc];
                b[1] = Bs[(nf*8+lr)*36 + ks*8 + lc + 4];
                mma_tf32(acc[nf], a, b);
            }
        }
    }
#pragma unroll
    for (int nf = 0; nf < 8; nf++) {
        int col = bn + nf*8 + lc*2;
        float b0 = bias ? bias[col] : 0.f;
        float b1 = bias ? bias[col+1] : 0.f;
        int row = bm + warp*16 + lr;
        float2* p = (float2*)(C + (size_t)row*N + col);
        float2 v = make_float2(acc[nf][0]+b0, acc[nf][1]+b1);
        if (accum) { float2 o = *p; v.x += o.x; v.y += o.y; }
        *p = v;
        p = (float2*)(C + (size_t)(row+8)*N + col);
        v = make_float2(acc[nf][2]+b0, acc[nf][3]+b1);
        if (accum) { float2 o = *p; v.x += o.x; v.y += o.y; }
        *p = v;
    }
}

// ---------------- flash attention: fp16 mma, f16x2 exp, rowsum-via-mma ----------
__global__ void k_fattn() {
    __shared__ __half Ks[64][24];
    __shared__ __half Vt[24][72];           // rows 0-15: V; row 16: ones; 17-23: 0
    int blk = blockIdx.x;                   // qt + 4*(head + 8*bn)
    int qt = blk & 3, head = (blk >> 2) & 7, bn = blk >> 5;
    int warp = threadIdx.x >> 5, lane = threadIdx.x & 31;
    int lr = lane >> 2, lc = lane & 3;
    int q0 = qt*256 + warp*32;
    const __half* qkb = g_qkvh + (size_t)bn*NP*384 + head*16;

    // ones/zero rows for rowsum trick (init once)
    for (int e = threadIdx.x; e < 8*72; e += 256)
        Vt[16 + e/72][e%72] = (e < 72) ? __float2half(1.f) : __float2half(0.f);

    unsigned Qa[2][4];
#pragma unroll
    for (int mt = 0; mt < 2; mt++) {
        const __half* qp = qkb + (size_t)(q0 + mt*16)*384;
        Qa[mt][0] = *(const unsigned*)(qp + (size_t)(lr  )*384 + 2*lc);
        Qa[mt][1] = *(const unsigned*)(qp + (size_t)(lr+8)*384 + 2*lc);
        Qa[mt][2] = *(const unsigned*)(qp + (size_t)(lr  )*384 + 2*lc + 8);
        Qa[mt][3] = *(const unsigned*)(qp + (size_t)(lr+8)*384 + 2*lc + 8);
    }

    float Oa[2][3][4];
#pragma unroll
    for (int mt = 0; mt < 2; mt++)
#pragma unroll
        for (int dn = 0; dn < 3; dn++)
#pragma unroll
            for (int j = 0; j < 4; j++) Oa[mt][dn][j] = 0.f;

    for (int c0 = 0; c0 < NP; c0 += 64) {
        __syncthreads();
        {
            int tt = threadIdx.x & 127;
            int key = tt >> 1, seg = (tt & 1) * 8;
            const __half* kp = qkb + (size_t)(c0 + key)*384 + 128 + seg;
            if (threadIdx.x < 128) {
                *(uint4*)&Ks[key][seg] = *(const uint4*)kp;
            } else {
                uint4 vv = *(const uint4*)(kp + 128);
                __half vh[8];
                *(uint4*)vh = vv;
#pragma unroll
                for (int j = 0; j < 8; j++) Vt[seg + j][key] = vh[j];
            }
        }
        __syncthreads();

        float S[2][8][4];
#pragma unroll
        for (int mt = 0; mt < 2; mt++)
#pragma unroll
            for (int nf = 0; nf < 8; nf++) {
                S[mt][nf][0] = S[mt][nf][1] = S[mt][nf][2] = S[mt][nf][3] = 0.f;
                unsigned b[2];
                b[0] = *(const unsigned*)&Ks[nf*8 + lr][2*lc];
                b[1] = *(const unsigned*)&Ks[nf*8 + lr][2*lc + 8];
                mma_f16(S[mt][nf], Qa[mt], b);
            }

        // P = 2^S directly in fp16 pairs; PV with ones-column for row sums
#pragma unroll
        for (int mt = 0; mt < 2; mt++)
#pragma unroll
            for (int j = 0; j < 4; j++) {
                unsigned a[4];
                a[0] = h2ex2(S[mt][2*j  ][0], S[mt][2*j  ][1]);
                a[1] = h2ex2(S[mt][2*j  ][2], S[mt][2*j  ][3]);
                a[2] = h2ex2(S[mt][2*j+1][0], S[mt][2*j+1][1]);
                a[3] = h2ex2(S[mt][2*j+1][2], S[mt][2*j+1][3]);
#pragma unroll
                for (int dn = 0; dn < 3; dn++) {
                    unsigned b[2];
                    b[0] = *(const unsigned*)&Vt[dn*8 + lr][j*16 + lc*2];
                    b[1] = *(const unsigned*)&Vt[dn*8 + lr][j*16 + lc*2 + 8];
                    mma_f16(Oa[mt][dn], a, b);
                }
            }
    }

    __half* ob = g_aoh + (size_t)bn*NP*CC + head*16;
#pragma unroll
    for (int mt = 0; mt < 2; mt++) {
        // rowsums live in n-col 16 = lc==0 lanes of the third frag
        float rs0 = __shfl_sync(0xffffffffu, Oa[mt][2][0], lane & 28);
        float rs1 = __shfl_sync(0xffffffffu, Oa[mt][2][2], lane & 28);
        float inv0 = 1.f / rs0, inv1 = 1.f / rs1;
        int qr = q0 + mt*16;
#pragma unroll
        for (int dn = 0; dn < 2; dn++) {
            int col = dn*8 + lc*2;
            *(__half2*)(ob + (size_t)(qr+lr  )*CC + col) = __floats2half2_rn(Oa[mt][dn][0]*inv0, Oa[mt][dn][1]*inv0);
            *(__half2*)(ob + (size_t)(qr+lr+8)*CC + col) = __floats2half2_rn(Oa[mt][dn][2]*inv1, Oa[mt][dn][3]*inv1);
        }
    }
}

// ---------------- GN1 apply + 2x2 pool + per-pixel group sums -------------------
__global__ void k_gnpool(const float* __restrict__ gg, const float* __restrict__ gb) {
    int bn = blockIdx.x >> 4, hp = blockIdx.x & 15;
    int lane = threadIdx.x & 31;
    float mu[4], rs[4];
#pragma unroll
    for (int g = 0; g < 4; g++) {
        float s = g_sacc[bn*8 + g*2], q = g_sacc[bn*8 + g*2 + 1];
        float m = s * (1.f/32768.f);
        mu[g] = m;
        rs[g] = rsqrtf(q*(1.f/32768.f) - m*m + 1e-5f);
    }
#pragma unroll
    for (int it = 0; it < 8; it++) {
        int idx = threadIdx.x + it*256;
        int wp = idx >> 7, c = idx & 127;
        int g = c >> 5;
        float ga = gg[c]*rs[g], bb2 = gb[c], m = mu[g];
        size_t a00 = ((size_t)bn*NP + hp*64 + wp*2)*CC + c;
        float y00 = (g_xt[a00]         - m)*ga + bb2;
        float y01 = (g_xt[a00 + CC]    - m)*ga + bb2;
        float y10 = (g_xt[a00 + 32*CC] - m)*ga + bb2;
        float y11 = (g_xt[a00 + 33*CC] - m)*ga + bb2;
        g_y2nh[a00]         = __float2half(y00);
        g_y2nh[a00 + CC]    = __float2half(y01);
        g_y2nh[a00 + 32*CC] = __float2half(y10);
        g_y2nh[a00 + 33*CC] = __float2half(y11);
        g_gph[((size_t)bn*NPC + hp*16 + wp)*CC + c] = __float2half(0.25f*(y00+y01+y10+y11));
        // warp = one channel group: reduce per-pixel sums/sumsqs
        float s00 = y00, s01 = y01, s10 = y10, s11 = y11;
        float q00 = y00*y00, q01 = y01*y01, q10 = y10*y10, q11 = y11*y11;
#pragma unroll
        for (int o = 16; o; o >>= 1) {
            s00 += __shfl_xor_sync(0xffffffffu, s00, o);
            q00 += __shfl_xor_sync(0xffffffffu, q00, o);
            s01 += __shfl_xor_sync(0xffffffffu, s01, o);
            q01 += __shfl_xor_sync(0xffffffffu, q01, o);
            s10 += __shfl_xor_sync(0xffffffffu, s10, o);
            q10 += __shfl_xor_sync(0xffffffffu, q10, o);
            s11 += __shfl_xor_sync(0xffffffffu, s11, o);
            q11 += __shfl_xor_sync(0xffffffffu, q11, o);
        }
        if (lane < 8) {
            float v = (lane==0)?s00:(lane==1)?q00:(lane==2)?s01:(lane==3)?q01
                    : (lane==4)?s10:(lane==5)?q10:(lane==6)?s11:q11;
            int pi = lane >> 1;
            int p = hp*64 + wp*2 + (pi & 1) + ((pi >> 1) ? 32 : 0);
            g_rs[((size_t)bn*NP + p)*8 + g*2 + (lane & 1)] = v;
        }
    }
}

// ---------------- gate + fused gated-GN2 stats ----------------
__global__ void k_gate(const float* __restrict__ w_psi, const float* __restrict__ b_psi) {
    __shared__ float arr[8][8];
    int lane = threadIdx.x & 31, wid = threadIdx.x >> 5;
    int p = blockIdx.x*8 + wid;
    int bn = p >> 10, n = p & 1023;
    int h = n >> 5, w = n & 31;
    int pc = (h >> 1)*16 + (w >> 1);
    const __half2* gp2 = (const __half2*)(g_ggh + ((size_t)bn*NPC + pc)*CC);
    const __half2* lp2 = (const __half2*)(g_lh + (size_t)p*CC);
    float2 ga = __half22float2(gp2[lane*2]),   gb = __half22float2(gp2[lane*2+1]);
    float2 la = __half22float2(lp2[lane*2]),   lb = __half22float2(lp2[lane*2+1]);
    float4 wp = ((const float4*)w_psi)[lane];
    float s = fmaxf(ga.x+la.x, 0.f)*wp.x + fmaxf(ga.y+la.y, 0.f)*wp.y
            + fmaxf(gb.x+lb.x, 0.f)*wp.z + fmaxf(gb.y+lb.y, 0.f)*wp.w;
#pragma unroll
    for (int o = 16; o; o >>= 1) s += __shfl_xor_sync(0xffffffffu, s, o);
    float gt = 1.f/(1.f + expf(-(s + b_psi[0])));
    if (lane == 0) g_gate[p] = gt;
    if (lane < 8) {
        float rv = g_rs[(size_t)p*8 + lane];
        arr[wid][lane] = (lane & 1) ? gt*gt*rv : gt*rv;
    }
    __syncthreads();
    if (threadIdx.x < 8) {
        float a = 0.f;
#pragma unroll
        for (int wi = 0; wi < 8; wi++) a += arr[wi][threadIdx.x];
        atomicAdd(&g_sacc[512 + bn*8 + threadIdx.x], a);
    }
}

// gated GN2 + transpose to channels-first + partial W-DFT (stats from g_sacc)
__global__ void k_y3t(const float* __restrict__ g, const float* __restrict__ b) {
    __shared__ float tile[128][33];
    __shared__ float gts[32];
    __shared__ float tc[32], ts[32];
    __shared__ float mu2[4], rs2[4];
    int bn = blockIdx.x >> 5, h = blockIdx.x & 31;
    if (threadIdx.x < 32) {
        gts[threadIdx.x] = g_gate[bn*NP + h*32 + threadIdx.x];
        float a = TWO_PI_32 * (float)threadIdx.x;
        tc[threadIdx.x] = cosf(a);
        ts[threadIdx.x] = sinf(a);
    }
    if (threadIdx.x < 4) {
        float s = g_sacc[512 + bn*8 + threadIdx.x*2];
        float q = g_sacc[512 + bn*8 + threadIdx.x*2 + 1];
        float m = s * (1.f/32768.f);
        mu2[threadIdx.x] = m;
        rs2[threadIdx.x] = rsqrtf(q*(1.f/32768.f) - m*m + 1e-5f);
    }
    __syncthreads();
    const __half* src = g_y2nh + ((size_t)bn*NP + h*32)*CC;
#pragma unroll
    for (int it = 0; it < 16; it++) {
        int idx = threadIdx.x + it*256;
        int w = idx >> 7, c = idx & 127;
        tile[c][w] = __half2float(src[(size_t)w*CC + c]) * gts[w];
    }
    __syncthreads();
    float* dst = g_y3 + (size_t)bn*CC*NP + h*32;
#pragma unroll
    for (int it = 0; it < 16; it++) {
        int idx = threadIdx.x + it*256;
        int c = idx >> 5, w = idx & 31;
        int gi = c >> 5;
        float v = (tile[c][w] - mu2[gi])*rs2[gi]*g[c] + b[c];
        dst[(size_t)c*NP + w] = v;
        tile[c][w] = v;
    }
    __syncthreads();
    float2* xw = g_Xw + ((size_t)bn*CC)*HH*MW + h*MW;
    for (int e = threadIdx.x; e < 128*12; e += 256) {
        int c = e / 12, kw = e % 12;
        float re = 0.f, im = 0.f;
#pragma unroll
        for (int w = 0; w < WW; w++) {
            int t = (w*kw) & 31;
            float v = tile[c][w];
            re += v*tc[t];
            im -= v*ts[t];
        }
        xw[(size_t)c*HH*MW + kw] = make_float2(re, im);
    }
}

// partial DFT along H -> z rows, coalesced (8 channels per block)
__global__ void k_sb2() {
    __shared__ float2 Xs[8][HH*MW];
    __shared__ float zr[144][8], zi[144][8];
    __shared__ float tc[32], ts[32];
    if (threadIdx.x < 32) {
        float a = TWO_PI_32 * (float)threadIdx.x;
        tc[threadIdx.x] = cosf(a);
        ts[threadIdx.x] = sinf(a);
    }
    int bn = blockIdx.x >> 4, cg = blockIdx.x & 15;
    const float2* src = g_Xw + ((size_t)(bn*CC + cg*8))*HH*MW;
    for (int e = threadIdx.x; e < 8*HH*MW; e += 256) {
        int c = e / (HH*MW), r = e % (HH*MW);
        Xs[c][r] = src[(size_t)c*HH*MW + r];
    }
    __syncthreads();
    for (int e = threadIdx.x; e < 144*8; e += 256) {
        int m = e >> 3, c = e & 7;
        int kh = m / 12, kw = m % 12;
        float re = 0.f, im = 0.f;
#pragma unroll
        for (int h = 0; h < HH; h++) {
            int t = (kh*h) & 31;
            float2 v = Xs[c][h*MW + kw];
            re += v.x*tc[t] + v.y*ts[t];
            im += v.y*tc[t] - v.x*ts[t];
        }
        zr[m][c] = re * INV32;
        zi[m][c] = im * INV32;
    }
    __syncthreads();
    for (int e = threadIdx.x; e < 144*16; e += 256) {
        int m = e >> 4, j = e & 15;
        size_t rowz = (size_t)(bn*144 + m) * 256;
        if (j < 8) g_zin[rowz + cg*8 + j] = zr[m][j];
        else       g_zin[rowz + 128 + cg*8 + (j-8)] = zi[m][j-8];
    }
}

// inverse DFT along H of delta modes, coalesced (32 channels per block)
__global__ void k_sd2() {
    __shared__ float Dr[144][32], Di[144][32];
    __shared__ float tc[32], ts[32];
    if (threadIdx.x < 32) {
        float a = TWO_PI_32 * (float)threadIdx.x;
        tc[threadIdx.x] = cosf(a);
        ts[threadIdx.x] = sinf(a);
    }
    int bn = blockIdx.x >> 2, cg = blockIdx.x & 3;
    for (int e = threadIdx.x; e < 144*32; e += 256) {
        int m = e >> 5, c = e & 31;
        size_t rowz = (size_t)(bn*144 + m) * 256;
        Dr[m][c] = g_zout[rowz + cg*32 + c];
        Di[m][c] = g_zout[rowz + 128 + cg*32 + c];
    }
    __syncthreads();
    int c = threadIdx.x & 31, hg = threadIdx.x >> 5;
    float2* dst = g_tH + ((size_t)(bn*CC + cg*32 + c))*HH*MW;
#pragma unroll
    for (int hi = 0; hi < 4; hi++) {
        int h = hg*4 + hi;
#pragma unroll
        for (int kw = 0; kw < 12; kw++) {
            float re = 0.f, im = 0.f;
#pragma unroll
            for (int kh = 0; kh < MH; kh++) {
                int t = (kh*h) & 31;
                float dx = Dr[kh*12 + kw][c], dy = Di[kh*12 + kw][c];
                re += dx*tc[t] - dy*ts[t];
                im += dx*ts[t] + dy*tc[t];
            }
            dst[h*MW + kw] = make_float2(re*INV_SQRT32, im*INV_SQRT32);
        }
    }
}

// final c2r along W of delta + out = 2*y3 + ys (parity split)
__global__ void k_se(float* __restrict__ out) {
    __shared__ float tc[32], ts[32];
    if (threadIdx.x < 32) {
        float a = TWO_PI_32 * (float)threadIdx.x;
        tc[threadIdx.x] = cosf(a);
        ts[threadIdx.x] = sinf(a);
    }
    __syncthreads();
    int row = blockIdx.x * blockDim.x + threadIdx.x;   // (bn,c,h)
    if (row >= BNN*CC*HH) return;
    int h = row & 31;
    int c = (row >> 5) & 127;
    int bn = row >> 12;
    float2 T[MW];
    const float2* tp = g_tH + (size_t)row * MW;
#pragma unroll
    for (int kw = 0; kw < MW; kw++) T[kw] = tp[kw];
    const float* yp = g_y3 + (size_t)row * WW;
    int b = bn >> 5, l = bn & 31;
    float* op = out + (((((size_t)b*CC + c)*LL + l)*HH + h)) * WW;
    for (int w = 0; w < 16; w++) {
        float se = T[0].x, so = 0.f;
#pragma unroll
        for (int kw = 1; kw < MW; kw++) {
            int t = (kw*w) & 31;
            float term = 2.f*(T[kw].x*tc[t] - T[kw].y*ts[t]);
            if (kw & 1) so += term; else se += term;
        }
        op[w]      = 2.f*yp[w]      + (se + so)*INV_SQRT32;
        op[w + 16] = 2.f*yp[w + 16] + (se - so)*INV_SQRT32;
    }
}

// ---------------- launch ----------------
static void* symaddr(const void* sym) { void* p = 0; cudaGetSymbolAddress(&p, sym); return p; }

extern "C" void kernel_launch(void* const* d_in, const int* in_sizes, int n_in,
                              void* d_out, int out_size) {
    const float* x      = (const float*)d_in[0];
    const float* dt     = (const float*)d_in[1];
    const float* nu     = (const float*)d_in[2];
    const float* theta  = (const float*)d_in[3];
    const float* ln_g   = (const float*)d_in[4];
    const float* ln_b   = (const float*)d_in[5];
    const float* w_qkv  = (const float*)d_in[6];
    const float* w_proj = (const float*)d_in[7];
    const float* b_proj = (const float*)d_in[8];
    const float* gn_g   = (const float*)d_in[9];
    const float* gn_b   = (const float*)d_in[10];
    const float* w_g    = (const float*)d_in[11];
    const float* w_l    = (const float*)d_in[12];
    const float* w_psi  = (const float*)d_in[13];
    const float* b_psi  = (const float*)d_in[14];
    const float* gate_g = (const float*)d_in[15];
    const float* gate_b = (const float*)d_in[16];
    const float* mix_w  = (const float*)d_in[17];
    const float* mix_b  = (const float*)d_in[18];
    float* out = (float*)d_out;

    float*  p_xt   = (float*)symaddr(g_xt);
    __half* p_xnh  = (__half*)symaddr(g_xnh);
    __half* p_qkvh = (__half*)symaddr(g_qkvh);
    __half* p_aoh  = (__half*)symaddr(g_aoh);
    __half* p_y2nh = (__half*)symaddr(g_y2nh);
    __half* p_gph  = (__half*)symaddr(g_gph);
    __half* p_ggh  = (__half*)symaddr(g_ggh);
    __half* p_lh   = (__half*)symaddr(g_lh);
    float*  p_zin  = (float*)symaddr(g_zin);
    float*  p_zout = (float*)symaddr(g_zout);
    float*  p_sacc = (float*)symaddr(g_sacc);

    // stage 1
    k_precompA<<<(BB*LL*CC*WF + 255)/256, 256>>>(dt, nu, theta);
    k_rfft<<<(BB*CC*LL*HH + 127)/128, 128>>>(x);
    k_scan<<<(BB*CC*HH*WF + 255)/256, 256>>>();
    k_irfft<<<(BB*LL*HH*CC)/256, 256>>>();
    k_ln<<<(BNN*NP)/8, 256>>>(ln_g, ln_b);
    // stage 2: attention + proj residual (GN1 stats fused into proj epilogue)
    k_gemm_h<<<dim3(384/64, (BNN*NP)/64), 128>>>(p_xnh, w_qkv, (const float*)0, (float*)0, p_qkvh, (float*)0, BNN*NP, 384, CC, 0, 1);
    k_fattn<<<BNN*8*4, 256>>>();
    k_gemm_h<<<dim3(CC/64, (BNN*NP)/64), 128>>>(p_aoh, w_proj, b_proj, p_xt, (__half*)0, p_sacc, BNN*NP, CC, CC, 1, 0);
    // stage 3: GN1+pool (+rowsums), gating (+GN2 stats), GN2 apply
    k_gnpool<<<BNN*16, 256>>>(gn_g, gn_b);
    k_gemm_h<<<dim3(CC/64, (BNN*NPC)/64), 128>>>(p_gph, w_g, (const float*)0, (float*)0, p_ggh, (float*)0, BNN*NPC, CC, CC, 0, 0);
    k_gemm_h<<<dim3(CC/64, (BNN*NP)/64), 128>>>(p_y2nh, w_l, (const float*)0, (float*)0, p_lh, (float*)0, BNN*NP, CC, CC, 0, 0);
    k_gate<<<(BNN*NP)/8, 256>>>(w_psi, b_psi);
    k_y3t<<<BNN*HH, 256>>>(gate_g, gate_b);
    // stage 4: spectral delta on TC (delta = z(mix_w - I)^T + mix_b)
    k_sb2<<<BNN*16, 256>>>();
    k_gemm_tc<<<dim3(256/64, (BNN*144)/64), 128>>>(p_zin, mix_w, mix_b, p_zout, BNN*144, 256, 256, 0, 1);
    k_sd2<<<BNN*4, 256>>>();
    k_se<<<(BNN*CC*HH)/256, 256>>>(out);
}

// round 12
// speedup vs baseline: 3.1334x; 1.0370x over previous
#include <cuda_runtime.h>
#include <cuda_fp16.h>
#include <math.h>

// ---------------- shapes ----------------
#define BB 2
#define CC 128
#define LL 32
#define HH 32
#define WW 32
#define WF 17
#define BNN 64
#define NP 1024
#define NPC 256
#define MH 12
#define MW 12

#define TWO_PI_32 0.19634954084936207f
#define INV32 0.03125f
#define INV_SQRT32 0.17677669529663687f
#define QK_SCALE 0.36067376022224085f    // 0.25 * log2(e)

// ---------------- device scratch ----------------
__device__ float2 g_xf[BB*CC*LL*HH*WF];
__device__ float2 g_A [BB*LL*CC*WF];
__device__ float  g_xt [BNN*NP*CC];
__device__ __half g_xnh[BNN*NP*CC];
__device__ __half g_qkvh[BNN*NP*384];
__device__ __half g_aoh[BNN*NP*CC];
__device__ __half g_y2nh[BNN*NP*CC];
__device__ __half g_gph[BNN*NPC*CC];
__device__ __half g_ggh[BNN*NPC*CC];
__device__ __half g_lh [BNN*NP*CC];
__device__ float  g_gate[BNN*NP];
__device__ float  g_rs  [BNN*NP*8];      // per-pixel per-group (sum, sumsq)
__device__ __half g_y3h[BNN*CC*NP];
__device__ float2 g_Xw [BNN*CC*HH*MW];
__device__ float  g_zin [BNN*144*256];
__device__ float  g_zout[BNN*144*256];
__device__ float2 g_tH [BNN*CC*HH*MW];
__device__ float  g_sacc[1024];          // [0..511] GN1 (bn,g,{s,q}); [512..1023] GN2

// ---------------- mma helpers ----------------
__device__ __forceinline__ unsigned f2tf32(float f) {
    unsigned r; asm("cvt.rna.tf32.f32 %0, %1;" : "=r"(r) : "f"(f)); return r;
}
__device__ __forceinline__ void mma_tf32(float* c, const unsigned* a, const unsigned* b) {
    asm("mma.sync.aligned.m16n8k8.row.col.f32.tf32.tf32.f32 "
        "{%0,%1,%2,%3}, {%4,%5,%6,%7}, {%8,%9}, {%0,%1,%2,%3};"
        : "+f"(c[0]), "+f"(c[1]), "+f"(c[2]), "+f"(c[3])
        : "r"(a[0]), "r"(a[1]), "r"(a[2]), "r"(a[3]), "r"(b[0]), "r"(b[1]));
}
__device__ __forceinline__ void mma_f16(float* c, const unsigned* a, const unsigned* b) {
    asm("mma.sync.aligned.m16n8k16.row.col.f32.f16.f16.f32 "
        "{%0,%1,%2,%3}, {%4,%5,%6,%7}, {%8,%9}, {%0,%1,%2,%3};"
        : "+f"(c[0]), "+f"(c[1]), "+f"(c[2]), "+f"(c[3])
        : "r"(a[0]), "r"(a[1]), "r"(a[2]), "r"(a[3]), "r"(b[0]), "r"(b[1]));
}
// pack (lo,hi) to f16x2 then 2^x elementwise — one cvt + one MUFU for 2 exps
__device__ __forceinline__ unsigned h2ex2(float lo, float hi) {
    unsigned p;
    asm("{\n\t.reg .b32 t;\n\tcvt.rn.f16x2.f32 t, %2, %1;\n\tex2.approx.f16x2 %0, t;\n\t}"
        : "=r"(p) : "f"(lo), "f"(hi));
    return p;
}

// ---------------- stage 1: A precompute (+ zero stats accumulators) -------------
__global__ void k_precompA(const float* __restrict__ dt, const float* __restrict__ nu,
                           const float* __restrict__ th) {
    int i = blockIdx.x * blockDim.x + threadIdx.x;
    if (i < 1024) g_sacc[i] = 0.f;
    if (i >= BB*LL*CC*WF) return;
    int k = i % WF;
    int c = (i / WF) % CC;
    int l = (i / (WF*CC)) % LL;
    int b =  i / (WF*CC*LL);
    float d  = dt[b*LL + l];
    float e  = expf(-nu[c*WF + k] * d);
    float si, co;
    sincosf(th[c*WF + k] * d, &si, &co);
    g_A[i] = make_float2(e*co, e*si);
}

// ---------------- stage 1: rfft along W + scan over L fused ---------------------
// block per (b,c,h4): 128 threads = 4 h x 32 l. DFT in regs -> smem; scan in smem.
__global__ void k_rfscan(const float* __restrict__ x) {
    __shared__ float2 S[4][32][WF];          // 17.4KB
    __shared__ float2 As[32][WF];            // 4.4KB
    __shared__ float tc[32], ts[32];
    int bc = blockIdx.x >> 3, h4 = blockIdx.x & 7;
    int b = bc >> 7, c = bc & 127;
    if (threadIdx.x < 32) {
        float a = TWO_PI_32 * (float)threadIdx.x;
        tc[threadIdx.x] = cosf(a);
        ts[threadIdx.x] = sinf(a);
    }
    for (int e = threadIdx.x; e < 32*WF; e += 128) {
        int l = e / WF, k = e % WF;
        As[l][k] = g_A[((size_t)(b*LL + l)*CC + c)*WF + k];
    }
    __syncthreads();
    int l = threadIdx.x & 31, hh = threadIdx.x >> 5;
    int h = h4*4 + hh;
    const float* xp = x + ((size_t)((b*CC + c)*LL + l)*HH + h)*WW;
    float xr[WW];
#pragma unroll
    for (int w = 0; w < WW; w++) xr[w] = xp[w];
    for (int k = 0; k < WF; k++) {
        float re = 0.f, im = 0.f;
#pragma unroll
        for (int w = 0; w < WW; w++) {
            int t = (w*k) & 31;
            re += xr[w]*tc[t];
            im -= xr[w]*ts[t];
        }
        S[hh][l][k] = make_float2(re, im);
    }
    __syncthreads();
    // scan over l: 68 threads (hh,k)
    if (threadIdx.x < 4*WF) {
        int shh = threadIdx.x / WF, sk = threadIdx.x % WF;
        float2 s = make_float2(0.f, 0.f);
        for (int sl = 0; sl < LL; sl++) {
            float2 a = As[sl][sk];
            float2 u = S[shh][sl][sk];
            float re = a.x*s.x - a.y*s.y + u.x;
            float im = a.x*s.y + a.y*s.x + u.y;
            s = make_float2(re, im);
            S[shh][sl][sk] = s;
        }
    }
    __syncthreads();
    // coalesced write to g_xf (b,c,l,h,k)
    for (int e = threadIdx.x; e < 4*32*WF; e += 128) {
        int k = e % WF, rest = e / WF;
        int whh = rest & 3, wl = rest >> 2;
        g_xf[(((size_t)(b*CC + c)*LL + wl)*HH + h4*4 + whh)*WF + k] = S[whh][wl][k];
    }
}

// ---------------- stage 1: irfft -> xt channels-last (parity split) -------------
__global__ void k_irfft() {
    __shared__ float tc[32], ts[32];
    if (threadIdx.x < 32) {
        float a = TWO_PI_32 * (float)threadIdx.x;
        tc[threadIdx.x] = cosf(a);
        ts[threadIdx.x] = sinf(a);
    }
    __syncthreads();
    int i = blockIdx.x * blockDim.x + threadIdx.x;     // (b,l,h,c)
    if (i >= BB*LL*HH*CC) return;
    int c = i & 127;
    int h = (i >> 7) & 31;
    int l = (i >> 12) & 31;
    int b =  i >> 17;
    const float2* st = g_xf + ((((size_t)b*CC + c)*LL + l)*HH + h)*WF;
    float2 S[WF];
#pragma unroll
    for (int k = 0; k < WF; k++) S[k] = st[k];
    int bn = b*LL + l;
    float* out = g_xt + ((size_t)bn*NP + h*WW)*CC + c;
    for (int w = 0; w < 16; w++) {
        float se = S[0].x + ((w & 1) ? -S[16].x : S[16].x);
        float so = 0.f;
#pragma unroll
        for (int k = 1; k < 16; k++) {
            int t = (w*k) & 31;
            float term = 2.f*(S[k].x*tc[t] - S[k].y*ts[t]);
            if (k & 1) so += term; else se += term;
        }
        out[(size_t)w*CC]      = (se + so) * INV32;
        out[(size_t)(w+16)*CC] = (se - so) * INV32;
    }
}

// ---------------- LayerNorm over C -> fp16 ----------------
__global__ void k_ln(const float* __restrict__ g, const float* __restrict__ b) {
    int lane = threadIdx.x & 31, wid = threadIdx.x >> 5;
    int r = blockIdx.x*8 + wid;
    float4 v = ((const float4*)(g_xt + (size_t)r*CC))[lane];
    float s = v.x + v.y + v.z + v.w;
#pragma unroll
    for (int o = 16; o; o >>= 1) s += __shfl_xor_sync(0xffffffffu, s, o);
    float mu = s * (1.f/128.f);
    float dx = v.x-mu, dy = v.y-mu, dz = v.z-mu, dw = v.w-mu;
    float q = dx*dx + dy*dy + dz*dz + dw*dw;
#pragma unroll
    for (int o = 16; o; o >>= 1) q += __shfl_xor_sync(0xffffffffu, q, o);
    float rstd = rsqrtf(q*(1.f/128.f) + 1e-5f);
    float4 g4 = ((const float4*)g)[lane];
    float4 b4 = ((const float4*)b)[lane];
    __half2* op = (__half2*)(g_xnh + (size_t)r*CC);
    op[lane*2]   = __floats2half2_rn(dx*rstd*g4.x + b4.x, dy*rstd*g4.y + b4.y);
    op[lane*2+1] = __floats2half2_rn(dz*rstd*g4.z + b4.z, dw*rstd*g4.w + b4.w);
}

// ---------------- fp16 TC GEMM: A fp16, B fp32->fp16 on load --------------------
__global__ void k_gemm_h(const __half* __restrict__ A, const float* __restrict__ B,
                         const float* __restrict__ bias, float* __restrict__ Cf,
                         __half* __restrict__ Ch, float* sacc,
                         int M, int N, int K, int accum, int qscale) {
    __shared__ unsigned As[64*20];
    __shared__ unsigned Bs[64*20];
    __shared__ float wacc[4][4];
    int bm = blockIdx.y << 6, bn = blockIdx.x << 6;
    int warp = threadIdx.x >> 5, lane = threadIdx.x & 31;
    int lr = lane >> 2, lc = lane & 3;
    float acc[8][4];
#pragma unroll
    for (int nf = 0; nf < 8; nf++)
#pragma unroll
        for (int j = 0; j < 4; j++) acc[nf][j] = 0.f;

    for (int k0 = 0; k0 < K; k0 += 32) {
        __syncthreads();
#pragma unroll
        for (int i = 0; i < 2; i++) {
            int slot = threadIdx.x + i*128;
            int m = slot >> 2, seg = (slot & 3) * 4;
            *(uint4*)&As[m*20 + seg] = *(const uint4*)(A + (size_t)(bm+m)*K + k0 + seg*2);
        }
#pragma unroll
        for (int i = 0; i < 4; i++) {
            int slot = threadIdx.x + i*128;
            int m = slot >> 3, seg = (slot & 7) * 4;
            float4 b4 = *(const float4*)(B + (size_t)(bn+m)*K + k0 + seg);
            __half2 h0 = __floats2half2_rn(b4.x, b4.y);
            __half2 h1 = __floats2half2_rn(b4.z, b4.w);
            Bs[m*20 + (seg>>1)]     = *(unsigned*)&h0;
            Bs[m*20 + (seg>>1) + 1] = *(unsigned*)&h1;
        }
        __syncthreads();
#pragma unroll
        for (int ks = 0; ks < 2; ks++) {
            unsigned a[4];
            int am = warp*16;
            a[0] = As[(am+lr  )*20 + ks*8 + lc];
            a[1] = As[(am+lr+8)*20 + ks*8 + lc];
            a[2] = As[(am+lr  )*20 + ks*8 + lc + 4];
            a[3] = As[(am+lr+8)*20 + ks*8 + lc + 4];
#pragma unroll
            for (int nf = 0; nf < 8; nf++) {
                unsigned b[2];
                b[0] = Bs[(nf*8+lr)*20 + ks*8 + lc];
                b[1] = Bs[(nf*8+lr)*20 + ks*8 + lc + 4];
                mma_f16(acc[nf], a, b);
            }
        }
    }
    float sg0 = 0.f, sq0 = 0.f, sg1 = 0.f, sq1 = 0.f;
#pragma unroll
    for (int nf = 0; nf < 8; nf++) {
        int col = bn + nf*8 + lc*2;
        int row = bm + warp*16 + lr;
        if (Ch) {
            float sc = (qscale && col < 128) ? QK_SCALE : 1.f;
            *(__half2*)(Ch + (size_t)row*N + col)     = __floats2half2_rn(acc[nf][0]*sc, acc[nf][1]*sc);
            *(__half2*)(Ch + (size_t)(row+8)*N + col) = __floats2half2_rn(acc[nf][2]*sc, acc[nf][3]*sc);
        } else {
            float b0 = bias ? bias[col] : 0.f;
            float b1 = bias ? bias[col+1] : 0.f;
            float2* p = (float2*)(Cf + (size_t)row*N + col);
            float2 v = make_float2(acc[nf][0]+b0, acc[nf][1]+b1);
            if (accum) { float2 o = *p; v.x += o.x; v.y += o.y; }
            *p = v;
            float2* p2 = (float2*)(Cf + (size_t)(row+8)*N + col);
            float2 v2 = make_float2(acc[nf][2]+b0, acc[nf][3]+b1);
            if (accum) { float2 o = *p2; v2.x += o.x; v2.y += o.y; }
            *p2 = v2;
            if (sacc) {
                float sv = v.x + v.y + v2.x + v2.y;
                float qv = v.x*v.x + v.y*v.y + v2.x*v2.x + v2.y*v2.y;
                if (nf < 4) { sg0 += sv; sq0 += qv; } else { sg1 += sv; sq1 += qv; }
            }
        }
    }
    if (sacc) {
#pragma unroll
        for (int o = 16; o; o >>= 1) {
            sg0 += __shfl_xor_sync(0xffffffffu, sg0, o);
            sq0 += __shfl_xor_sync(0xffffffffu, sq0, o);
            sg1 += __shfl_xor_sync(0xffffffffu, sg1, o);
            sq1 += __shfl_xor_sync(0xffffffffu, sq1, o);
        }
        if (lane == 0) {
            wacc[warp][0] = sg0; wacc[warp][1] = sq0;
            wacc[warp][2] = sg1; wacc[warp][3] = sq1;
        }
        __syncthreads();
        if (threadIdx.x == 0) {
            float a0 = 0.f, a1 = 0.f, a2 = 0.f, a3 = 0.f;
#pragma unroll
            for (int wi = 0; wi < 4; wi++) {
                a0 += wacc[wi][0]; a1 += wacc[wi][1];
                a2 += wacc[wi][2]; a3 += wacc[wi][3];
            }
            int bni = bm >> 10;
            int gb = bn >> 5;
            atomicAdd(&sacc[bni*8 + (gb  )*2    ], a0);
            atomicAdd(&sacc[bni*8 + (gb  )*2 + 1], a1);
            atomicAdd(&sacc[bni*8 + (gb+1)*2    ], a2);
            atomicAdd(&sacc[bni*8 + (gb+1)*2 + 1], a3);
        }
    }
}

// ---------------- tf32 TC GEMM (mix delta): C = A*(B - subI*I)^T (+bias) --------
__global__ void k_gemm_tc(const float* __restrict__ A, const float* __restrict__ B,
                          const float* __restrict__ bias, float* __restrict__ C,
                          int M, int N, int K, int accum, int subI) {
    __shared__ unsigned As[64*36];
    __shared__ unsigned Bs[64*36];
    int bm = blockIdx.y << 6, bn = blockIdx.x << 6;
    int warp = threadIdx.x >> 5, lane = threadIdx.x & 31;
    int lr = lane >> 2, lc = lane & 3;
    float acc[8][4];
#pragma unroll
    for (int nf = 0; nf < 8; nf++)
#pragma unroll
        for (int j = 0; j < 4; j++) acc[nf][j] = 0.f;

    for (int k0 = 0; k0 < K; k0 += 32) {
        __syncthreads();
#pragma unroll
        for (int i = 0; i < 4; i++) {
            int slot = threadIdx.x + i*128;
            int m = slot >> 3, seg = (slot & 7) << 2;
            float4 a4 = *(const float4*)(A + (size_t)(bm+m)*K + k0 + seg);
            *(uint4*)&As[m*36 + seg] = make_uint4(f2tf32(a4.x), f2tf32(a4.y), f2tf32(a4.z), f2tf32(a4.w));
            float4 b4 = *(const float4*)(B + (size_t)(bn+m)*K + k0 + seg);
            if (subI) {
                int row = bn + m, col = k0 + seg;
                if (row == col    ) b4.x -= 1.f;
                if (row == col + 1) b4.y -= 1.f;
                if (row == col + 2) b4.z -= 1.f;
                if (row == col + 3) b4.w -= 1.f;
            }
            *(uint4*)&Bs[m*36 + seg] = make_uint4(f2tf32(b4.x), f2tf32(b4.y), f2tf32(b4.z), f2tf32(b4.w));
        }
        __syncthreads();
#pragma unroll
        for (int ks = 0; ks < 4; ks++) {
            unsigned a[4];
            int am = warp*16;
            a[0] = As[(am+lr  )*36 + ks*8 + lc];
            a[1] = As[(am+lr+8)*36 + ks*8 + lc];
            a[2] = As[(am+lr  )*36 + ks*8 + lc + 4];
            a[3] = As[(am+lr+8)*36 + ks*8 + lc + 4];
#pragma unroll
            for (int nf = 0; nf < 8; nf++) {
                unsigned b[2];
                b[0] = Bs[(nf*8+lr)*36 + ks*8 + lc];
                b[1] = Bs[(nf*8+lr)*36 + ks*8 + lc + 4];
                mma_tf32(acc[nf], a, b);
            }
        }
    }
#pragma unroll
    for (int nf = 0; nf < 8; nf++) {
        int col = bn + nf*8 + lc*2;
        float b0 = bias ? bias[col] : 0.f;
        float b1 = bias ? bias[col+1] : 0.f;
        int row = bm + warp*16 + lr;
        float2* p = (float2*)(C + (size_t)row*N + col);
        float2 v = make_float2(acc[nf][0]+b0, acc[nf][1]+b1);
        if (accum) { float2 o = *p; v.x += o.x; v.y += o.y; }
        *p = v;
        p = (float2*)(C + (size_t)(row+8)*N + col);
        v = make_float2(acc[nf][2]+b0, acc[nf][3]+b1);
        if (accum) { float2 o = *p; v.x += o.x; v.y += o.y; }
        *p = v;
    }
}

// ---------------- flash attention: fp16 mma, f16x2 exp, rowsum-via-mma ----------
__global__ void k_fattn() {
    __shared__ __half Ks[64][24];
    __shared__ __half Vt[24][72];           // rows 0-15: V; row 16: ones; 17-23: 0
    int blk = blockIdx.x;                   // qt + 4*(head + 8*bn)
    int qt = blk & 3, head = (blk >> 2) & 7, bn = blk >> 5;
    int warp = threadIdx.x >> 5, lane = threadIdx.x & 31;
    int lr = lane >> 2, lc = lane & 3;
    int q0 = qt*256 + warp*32;
    const __half* qkb = g_qkvh + (size_t)bn*NP*384 + head*16;

    for (int e = threadIdx.x; e < 8*72; e += 256)
        Vt[16 + e/72][e%72] = (e < 72) ? __float2half(1.f) : __float2half(0.f);

    unsigned Qa[2][4];
#pragma unroll
    for (int mt = 0; mt < 2; mt++) {
        const __half* qp = qkb + (size_t)(q0 + mt*16)*384;
        Qa[mt][0] = *(const unsigned*)(qp + (size_t)(lr  )*384 + 2*lc);
        Qa[mt][1] = *(const unsigned*)(qp + (size_t)(lr+8)*384 + 2*lc);
        Qa[mt][2] = *(const unsigned*)(qp + (size_t)(lr  )*384 + 2*lc + 8);
        Qa[mt][3] = *(const unsigned*)(qp + (size_t)(lr+8)*384 + 2*lc + 8);
    }

    float Oa[2][3][4];
#pragma unroll
    for (int mt = 0; mt < 2; mt++)
#pragma unroll
        for (int dn = 0; dn < 3; dn++)
#pragma unroll
            for (int j = 0; j < 4; j++) Oa[mt][dn][j] = 0.f;

    for (int c0 = 0; c0 < NP; c0 += 64) {
        __syncthreads();
        {
            int tt = threadIdx.x & 127;
            int key = tt >> 1, seg = (tt & 1) * 8;
            const __half* kp = qkb + (size_t)(c0 + key)*384 + 128 + seg;
            if (threadIdx.x < 128) {
                *(uint4*)&Ks[key][seg] = *(const uint4*)kp;
            } else {
                uint4 vv = *(const uint4*)(kp + 128);
                __half vh[8];
                *(uint4*)vh = vv;
#pragma unroll
                for (int j = 0; j < 8; j++) Vt[seg + j][key] = vh[j];
            }
        }
        __syncthreads();

        float S[2][8][4];
#pragma unroll
        for (int mt = 0; mt < 2; mt++)
#pragma unroll
            for (int nf = 0; nf < 8; nf++) {
                S[mt][nf][0] = S[mt][nf][1] = S[mt][nf][2] = S[mt][nf][3] = 0.f;
                unsigned b[2];
                b[0] = *(const unsigned*)&Ks[nf*8 + lr][2*lc];
                b[1] = *(const unsigned*)&Ks[nf*8 + lr][2*lc + 8];
                mma_f16(S[mt][nf], Qa[mt], b);
            }

#pragma unroll
        for (int mt = 0; mt < 2; mt++)
#pragma unroll
            for (int j = 0; j < 4; j++) {
                unsigned a[4];
                a[0] = h2ex2(S[mt][2*j  ][0], S[mt][2*j  ][1]);
                a[1] = h2ex2(S[mt][2*j  ][2], S[mt][2*j  ][3]);
                a[2] = h2ex2(S[mt][2*j+1][0], S[mt][2*j+1][1]);
                a[3] = h2ex2(S[mt][2*j+1][2], S[mt][2*j+1][3]);
#pragma unroll
                for (int dn = 0; dn < 3; dn++) {
                    unsigned b[2];
                    b[0] = *(const unsigned*)&Vt[dn*8 + lr][j*16 + lc*2];
                    b[1] = *(const unsigned*)&Vt[dn*8 + lr][j*16 + lc*2 + 8];
                    mma_f16(Oa[mt][dn], a, b);
                }
            }
    }

    __half* ob = g_aoh + (size_t)bn*NP*CC + head*16;
#pragma unroll
    for (int mt = 0; mt < 2; mt++) {
        float rs0 = __shfl_sync(0xffffffffu, Oa[mt][2][0], lane & 28);
        float rs1 = __shfl_sync(0xffffffffu, Oa[mt][2][2], lane & 28);
        float inv0 = 1.f / rs0, inv1 = 1.f / rs1;
        int qr = q0 + mt*16;
#pragma unroll
        for (int dn = 0; dn < 2; dn++) {
            int col = dn*8 + lc*2;
            *(__half2*)(ob + (size_t)(qr+lr  )*CC + col) = __floats2half2_rn(Oa[mt][dn][0]*inv0, Oa[mt][dn][1]*inv0);
            *(__half2*)(ob + (size_t)(qr+lr+8)*CC + col) = __floats2half2_rn(Oa[mt][dn][2]*inv1, Oa[mt][dn][3]*inv1);
        }
    }
}

// ---------------- GN1 apply + 2x2 pool + per-pixel group sums -------------------
__global__ void k_gnpool(const float* __restrict__ gg, const float* __restrict__ gb) {
    int bn = blockIdx.x >> 4, hp = blockIdx.x & 15;
    int lane = threadIdx.x & 31;
    float mu[4], rs[4];
#pragma unroll
    for (int g = 0; g < 4; g++) {
        float s = g_sacc[bn*8 + g*2], q = g_sacc[bn*8 + g*2 + 1];
        float m = s * (1.f/32768.f);
        mu[g] = m;
        rs[g] = rsqrtf(q*(1.f/32768.f) - m*m + 1e-5f);
    }
#pragma unroll
    for (int it = 0; it < 8; it++) {
        int idx = threadIdx.x + it*256;
        int wp = idx >> 7, c = idx & 127;
        int g = c >> 5;
        float ga = gg[c]*rs[g], bb2 = gb[c], m = mu[g];
        size_t a00 = ((size_t)bn*NP + hp*64 + wp*2)*CC + c;
        float y00 = (g_xt[a00]         - m)*ga + bb2;
        float y01 = (g_xt[a00 + CC]    - m)*ga + bb2;
        float y10 = (g_xt[a00 + 32*CC] - m)*ga + bb2;
        float y11 = (g_xt[a00 + 33*CC] - m)*ga + bb2;
        g_y2nh[a00]         = __float2half(y00);
        g_y2nh[a00 + CC]    = __float2half(y01);
        g_y2nh[a00 + 32*CC] = __float2half(y10);
        g_y2nh[a00 + 33*CC] = __float2half(y11);
        g_gph[((size_t)bn*NPC + hp*16 + wp)*CC + c] = __float2half(0.25f*(y00+y01+y10+y11));
        float s00 = y00, s01 = y01, s10 = y10, s11 = y11;
        float q00 = y00*y00, q01 = y01*y01, q10 = y10*y10, q11 = y11*y11;
#pragma unroll
        for (int o = 16; o; o >>= 1) {
            s00 += __shfl_xor_sync(0xffffffffu, s00, o);
            q00 += __shfl_xor_sync(0xffffffffu, q00, o);
            s01 += __shfl_xor_sync(0xffffffffu, s01, o);
            q01 += __shfl_xor_sync(0xffffffffu, q01, o);
            s10 += __shfl_xor_sync(0xffffffffu, s10, o);
            q10 += __shfl_xor_sync(0xffffffffu, q10, o);
            s11 += __shfl_xor_sync(0xffffffffu, s11, o);
            q11 += __shfl_xor_sync(0xffffffffu, q11, o);
        }
        if (lane < 8) {
            float v = (lane==0)?s00:(lane==1)?q00:(lane==2)?s01:(lane==3)?q01
                    : (lane==4)?s10:(lane==5)?q10:(lane==6)?s11:q11;
            int pi = lane >> 1;
            int p = hp*64 + wp*2 + (pi & 1) + ((pi >> 1) ? 32 : 0);
            g_rs[((size_t)bn*NP + p)*8 + g*2 + (lane & 1)] = v;
        }
    }
}

// ---------------- gate + fused gated-GN2 stats ----------------
__global__ void k_gate(const float* __restrict__ w_psi, const float* __restrict__ b_psi) {
    __shared__ float arr[8][8];
    int lane = threadIdx.x & 31, wid = threadIdx.x >> 5;
    int p = blockIdx.x*8 + wid;
    int bn = p >> 10, n = p & 1023;
    int h = n >> 5, w = n & 31;
    int pc = (h >> 1)*16 + (w >> 1);
    const __half2* gp2 = (const __half2*)(g_ggh + ((size_t)bn*NPC + pc)*CC);
    const __half2* lp2 = (const __half2*)(g_lh + (size_t)p*CC);
    float2 ga = __half22float2(gp2[lane*2]),   gb = __half22float2(gp2[lane*2+1]);
    float2 la = __half22float2(lp2[lane*2]),   lb = __half22float2(lp2[lane*2+1]);
    float4 wp = ((const float4*)w_psi)[lane];
    float s = fmaxf(ga.x+la.x, 0.f)*wp.x + fmaxf(ga.y+la.y, 0.f)*wp.y
            + fmaxf(gb.x+lb.x, 0.f)*wp.z + fmaxf(gb.y+lb.y, 0.f)*wp.w;
#pragma unroll
    for (int o = 16; o; o >>= 1) s += __shfl_xor_sync(0xffffffffu, s, o);
    float gt = 1.f/(1.f + expf(-(s + b_psi[0])));
    if (lane == 0) g_gate[p] = gt;
    if (lane < 8) {
        float rv = g_rs[(size_t)p*8 + lane];
        arr[wid][lane] = (lane & 1) ? gt*gt*rv : gt*rv;
    }
    __syncthreads();
    if (threadIdx.x < 8) {
        float a = 0.f;
#pragma unroll
        for (int wi = 0; wi < 8; wi++) a += arr[wi][threadIdx.x];
        atomicAdd(&g_sacc[512 + bn*8 + threadIdx.x], a);
    }
}

// gated GN2 + transpose to channels-first (fp16) + partial W-DFT
__global__ void k_y3t(const float* __restrict__ g, const float* __restrict__ b) {
    __shared__ float tile[128][33];
    __shared__ float gts[32];
    __shared__ float tc[32], ts[32];
    __shared__ float mu2[4], rs2[4];
    int bn = blockIdx.x >> 5, h = blockIdx.x & 31;
    if (threadIdx.x < 32) {
        gts[threadIdx.x] = g_gate[bn*NP + h*32 + threadIdx.x];
        float a = TWO_PI_32 * (float)threadIdx.x;
        tc[threadIdx.x] = cosf(a);
        ts[threadIdx.x] = sinf(a);
    }
    if (threadIdx.x < 4) {
        float s = g_sacc[512 + bn*8 + threadIdx.x*2];
        float q = g_sacc[512 + bn*8 + threadIdx.x*2 + 1];
        float m = s * (1.f/32768.f);
        mu2[threadIdx.x] = m;
        rs2[threadIdx.x] = rsqrtf(q*(1.f/32768.f) - m*m + 1e-5f);
    }
    __syncthreads();
    const __half* src = g_y2nh + ((size_t)bn*NP + h*32)*CC;
#pragma unroll
    for (int it = 0; it < 16; it++) {
        int idx = threadIdx.x + it*256;
        int w = idx >> 7, c = idx & 127;
        tile[c][w] = __half2float(src[(size_t)w*CC + c]) * gts[w];
    }
    __syncthreads();
    __half* dst = g_y3h + (size_t)bn*CC*NP + h*32;
#pragma unroll
    for (int it = 0; it < 16; it++) {
        int idx = threadIdx.x + it*256;
        int c = idx >> 5, w = idx & 31;
        int gi = c >> 5;
        float v = (tile[c][w] - mu2[gi])*rs2[gi]*g[c] + b[c];
        dst[(size_t)c*NP + w] = __float2half(v);
        tile[c][w] = v;
    }
    __syncthreads();
    float2* xw = g_Xw + ((size_t)bn*CC)*HH*MW + h*MW;
    for (int e = threadIdx.x; e < 128*12; e += 256) {
        int c = e / 12, kw = e % 12;
        float re = 0.f, im = 0.f;
#pragma unroll
        for (int w = 0; w < WW; w++) {
            int t = (w*kw) & 31;
            float v = tile[c][w];
            re += v*tc[t];
            im -= v*ts[t];
        }
        xw[(size_t)c*HH*MW + kw] = make_float2(re, im);
    }
}

// partial DFT along H -> z rows, coalesced (8 channels per block)
__global__ void k_sb2() {
    __shared__ float2 Xs[8][HH*MW];
    __shared__ float zr[144][8], zi[144][8];
    __shared__ float tc[32], ts[32];
    if (threadIdx.x < 32) {
        float a = TWO_PI_32 * (float)threadIdx.x;
        tc[threadIdx.x] = cosf(a);
        ts[threadIdx.x] = sinf(a);
    }
    int bn = blockIdx.x >> 4, cg = blockIdx.x & 15;
    const float2* src = g_Xw + ((size_t)(bn*CC + cg*8))*HH*MW;
    for (int e = threadIdx.x; e < 8*HH*MW; e += 256) {
        int c = e / (HH*MW), r = e % (HH*MW);
        Xs[c][r] = src[(size_t)c*HH*MW + r];
    }
    __syncthreads();
    for (int e = threadIdx.x; e < 144*8; e += 256) {
        int m = e >> 3, c = e & 7;
        int kh = m / 12, kw = m % 12;
        float re = 0.f, im = 0.f;
#pragma unroll
        for (int h = 0; h < HH; h++) {
            int t = (kh*h) & 31;
            float2 v = Xs[c][h*MW + kw];
            re += v.x*tc[t] + v.y*ts[t];
            im += v.y*tc[t] - v.x*ts[t];
        }
        zr[m][c] = re * INV32;
        zi[m][c] = im * INV32;
    }
    __syncthreads();
    for (int e = threadIdx.x; e < 144*16; e += 256) {
        int m = e >> 4, j = e & 15;
        size_t rowz = (size_t)(bn*144 + m) * 256;
        if (j < 8) g_zin[rowz + cg*8 + j] = zr[m][j];
        else       g_zin[rowz + 128 + cg*8 + (j-8)] = zi[m][j-8];
    }
}

// inverse DFT along H of delta modes, coalesced (32 channels per block)
__global__ void k_sd2() {
    __shared__ float Dr[144][32], Di[144][32];
    __shared__ float tc[32], ts[32];
    if (threadIdx.x < 32) {
        float a = TWO_PI_32 * (float)threadIdx.x;
        tc[threadIdx.x] = cosf(a);
        ts[threadIdx.x] = sinf(a);
    }
    int bn = blockIdx.x >> 2, cg = blockIdx.x & 3;
    for (int e = threadIdx.x; e < 144*32; e += 256) {
        int m = e >> 5, c = e & 31;
        size_t rowz = (size_t)(bn*144 + m) * 256;
        Dr[m][c] = g_zout[rowz + cg*32 + c];
        Di[m][c] = g_zout[rowz + 128 + cg*32 + c];
    }
    __syncthreads();
    int c = threadIdx.x & 31, hg = threadIdx.x >> 5;
    float2* dst = g_tH + ((size_t)(bn*CC + cg*32 + c))*HH*MW;
#pragma unroll
    for (int hi = 0; hi < 4; hi++) {
        int h = hg*4 + hi;
#pragma unroll
        for (int kw = 0; kw < 12; kw++) {
            float re = 0.f, im = 0.f;
#pragma unroll
            for (int kh = 0; kh < MH; kh++) {
                int t = (kh*h) & 31;
                float dx = Dr[kh*12 + kw][c], dy = Di[kh*12 + kw][c];
                re += dx*tc[t] - dy*ts[t];
                im += dx*ts[t] + dy*tc[t];
            }
            dst[h*MW + kw] = make_float2(re*INV_SQRT32, im*INV_SQRT32);
        }
    }
}

// final c2r along W of delta + out = 2*y3 + ys (parity split)
__global__ void k_se(float* __restrict__ out) {
    __shared__ float tc[32], ts[32];
    if (threadIdx.x < 32) {
        float a = TWO_PI_32 * (float)threadIdx.x;
        tc[threadIdx.x] = cosf(a);
        ts[threadIdx.x] = sinf(a);
    }
    __syncthreads();
    int row = blockIdx.x * blockDim.x + threadIdx.x;   // (bn,c,h)
    if (row >= BNN*CC*HH) return;
    int h = row & 31;
    int c = (row >> 5) & 127;
    int bn = row >> 12;
    float2 T[MW];
    const float2* tp = g_tH + (size_t)row * MW;
#pragma unroll
    for (int kw = 0; kw < MW; kw++) T[kw] = tp[kw];
    const __half* yp = g_y3h + (size_t)row * WW;
    int b = bn >> 5, l = bn & 31;
    float* op = out + (((((size_t)b*CC + c)*LL + l)*HH + h)) * WW;
    for (int w = 0; w < 16; w++) {
        float se = T[0].x, so = 0.f;
#pragma unroll
        for (int kw = 1; kw < MW; kw++) {
            int t = (kw*w) & 31;
            float term = 2.f*(T[kw].x*tc[t] - T[kw].y*ts[t]);
            if (kw & 1) so += term; else se += term;
        }
        op[w]      = 2.f*__half2float(yp[w])      + (se + so)*INV_SQRT32;
        op[w + 16] = 2.f*__half2float(yp[w + 16]) + (se - so)*INV_SQRT32;
    }
}

// ---------------- launch ----------------
static void* symaddr(const void* sym) { void* p = 0; cudaGetSymbolAddress(&p, sym); return p; }

extern "C" void kernel_launch(void* const* d_in, const int* in_sizes, int n_in,
                              void* d_out, int out_size) {
    const float* x      = (const float*)d_in[0];
    const float* dt     = (const float*)d_in[1];
    const float* nu     = (const float*)d_in[2];
    const float* theta  = (const float*)d_in[3];
    const float* ln_g   = (const float*)d_in[4];
    const float* ln_b   = (const float*)d_in[5];
    const float* w_qkv  = (const float*)d_in[6];
    const float* w_proj = (const float*)d_in[7];
    const float* b_proj = (const float*)d_in[8];
    const float* gn_g   = (const float*)d_in[9];
    const float* gn_b   = (const float*)d_in[10];
    const float* w_g    = (const float*)d_in[11];
    const float* w_l    = (const float*)d_in[12];
    const float* w_psi  = (const float*)d_in[13];
    const float* b_psi  = (const float*)d_in[14];
    const float* gate_g = (const float*)d_in[15];
    const float* gate_b = (const float*)d_in[16];
    const float* mix_w  = (const float*)d_in[17];
    const float* mix_b  = (const float*)d_in[18];
    float* out = (float*)d_out;

    float*  p_xt   = (float*)symaddr(g_xt);
    __half* p_xnh  = (__half*)symaddr(g_xnh);
    __half* p_qkvh = (__half*)symaddr(g_qkvh);
    __half* p_aoh  = (__half*)symaddr(g_aoh);
    __half* p_y2nh = (__half*)symaddr(g_y2nh);
    __half* p_gph  = (__half*)symaddr(g_gph);
    __half* p_ggh  = (__half*)symaddr(g_ggh);
    __half* p_lh   = (__half*)symaddr(g_lh);
    float*  p_zin  = (float*)symaddr(g_zin);
    float*  p_zout = (float*)symaddr(g_zout);
    float*  p_sacc = (float*)symaddr(g_sacc);

    // stage 1 (rfft+scan fused)
    k_precompA<<<(BB*LL*CC*WF + 255)/256, 256>>>(dt, nu, theta);
    k_rfscan<<<BB*CC*8, 128>>>(x);
    k_irfft<<<(BB*LL*HH*CC)/256, 256>>>();
    k_ln<<<(BNN*NP)/8, 256>>>(ln_g, ln_b);
    // stage 2: attention + proj residual (GN1 stats fused into proj epilogue)
    k_gemm_h<<<dim3(384/64, (BNN*NP)/64), 128>>>(p_xnh, w_qkv, (const float*)0, (float*)0, p_qkvh, (float*)0, BNN*NP, 384, CC, 0, 1);
    k_fattn<<<BNN*8*4, 256>>>();
    k_gemm_h<<<dim3(CC/64, (BNN*NP)/64), 128>>>(p_aoh, w_proj, b_proj, p_xt, (__half*)0, p_sacc, BNN*NP, CC, CC, 1, 0);
    // stage 3: GN1+pool (+rowsums), gating (+GN2 stats), GN2 apply
    k_gnpool<<<BNN*16, 256>>>(gn_g, gn_b);
    k_gemm_h<<<dim3(CC/64, (BNN*NPC)/64), 128>>>(p_gph, w_g, (const float*)0, (float*)0, p_ggh, (float*)0, BNN*NPC, CC, CC, 0, 0);
    k_gemm_h<<<dim3(CC/64, (BNN*NP)/64), 128>>>(p_y2nh, w_l, (const float*)0, (float*)0, p_lh, (float*)0, BNN*NP, CC, CC, 0, 0);
    k_gate<<<(BNN*NP)/8, 256>>>(w_psi, b_psi);
    k_y3t<<<BNN*HH, 256>>>(gate_g, gate_b);
    // stage 4: spectral delta on TC (delta = z(mix_w - I)^T + mix_b)
    k_sb2<<<BNN*16, 256>>>();
    k_gemm_tc<<<dim3(256/64, (BNN*144)/64), 128>>>(p_zin, mix_w, mix_b, p_zout, BNN*144, 256, 256, 0, 1);
    k_sd2<<<BNN*4, 256>>>();
    k_se<<<(BNN*CC*HH)/256, 256>>>(out);
}